// round 5
// baseline (speedup 1.0000x reference)
#include <cuda_runtime.h>
#include <math.h>

// ---------------------------------------------------------------------------
// IEBINS — fixed shapes: B=2, H=120, W=160, HD=128, CD=192, BN=16, 6 iters
// fp32 implicit-GEMM direct convs + fused pointwise/bins kernels.
// ---------------------------------------------------------------------------

#define H_   120
#define W_   160
#define HW   19200
#define NPIX 38400   // B * HW

enum { ACT_NONE = 0, ACT_RELU = 1, ACT_SIG = 2, ACT_TANH = 3 };

// ------------------------- scratch (single static arena) -------------------
// edges : 2*17*HW  =   652,800
// cd    : 2*16*HW  =   614,400
// e1    : 2*128*HW = 4,915,200
// e2    : 2*128*HW = 4,915,200
// hx    : 2*576*HW = 22,118,400   layout per batch: [h 0:128 | d 128:384 | ctx 384:576]
// h     : 2*128*HW
// z,r,q : 2*128*HW each
// logits: 2*16*HW
constexpr long OFF_EDGES = 0;
constexpr long OFF_CD    = 652800;
constexpr long OFF_E1    = 1267200;
constexpr long OFF_E2    = 6182400;
constexpr long OFF_HX    = 11097600;
constexpr long OFF_H     = 33216000;
constexpr long OFF_Z     = 38131200;
constexpr long OFF_R     = 43046400;
constexpr long OFF_Q     = 47961600;
constexpr long OFF_LOG   = 52876800;
constexpr long SCRATCH_TOTAL = 53491200;   // floats (~204 MiB)

__device__ __align__(16) float g_scratch[SCRATCH_TOTAL];

// ------------------------- activation epilogue -----------------------------
template <int ACT>
__device__ __forceinline__ float epi(float v) {
    if (ACT == ACT_RELU) return fmaxf(v, 0.0f);
    if (ACT == ACT_SIG)  return 1.0f / (1.0f + expf(-v));
    if (ACT == ACT_TANH) return tanhf(v);
    return v;
}

// ------------------------- implicit-GEMM conv ------------------------------
// O[b, co, y, x] = act( bias[co] + sum_{ci,ky,kx} W[co,ci,ky,kx] *
//                       I[b, ci, y+ky-PH, x+kx-PW] )
// GEMM view: M = COUT (tile 128), N = NPIX (tile 64), K = CIN*KH*KW (step 16)
// 256 threads, 8x4 register micro-tile per thread.
template <int CIN, int COUT, int KH, int KW, int PH, int PW, int ACT>
__global__ __launch_bounds__(256)
void conv_k(long in_off, int in_bs,
            const float* __restrict__ wgt, const float* __restrict__ bias,
            long out_off, int out_bs)
{
    constexpr int KTOT = CIN * KH * KW;
    static_assert(KTOT % 16 == 0, "K must be a multiple of 16");

    __shared__ __align__(16) float As[16][136];  // [k][m], padded
    __shared__ __align__(16) float Bs[16][72];   // [k][n], padded

    const float* in  = g_scratch + in_off;
    float*       out = g_scratch + out_off;

    const int tid = threadIdx.x;
    const int n0  = blockIdx.x << 6;   // pixel tile base (64)
    const int m0  = blockIdx.y << 7;   // out-channel tile base (128)

    // ---- B (im2col) loader coords: one pixel per thread, 4 k-rows ----
    const int bn   = tid & 63;
    const int krow = tid >> 6;         // 0..3
    const int p    = n0 + bn;          // NPIX % 64 == 0 -> always valid
    const int bb   = p / HW;
    const int hw   = p - bb * HW;
    const int py   = hw / W_;
    const int px   = hw - py * W_;
    const float* inb = in + (long)bb * in_bs;

    // ---- A (weights) loader coords: 2 float4 per thread ----
    const int arow = tid >> 1;                 // 0..127
    const int acol = (tid & 1) << 3;           // 0 or 8
    const bool aok = (m0 + arow) < COUT;
    const float* wrow = wgt + (long)(m0 + arow) * KTOT + acol;

    // ---- micro-tile coords ----
    const int tn = tid & 15;   // 16 col groups of 4 pixels
    const int tm = tid >> 4;   // 16 row groups of 8 channels

    float acc[8][4];
#pragma unroll
    for (int i = 0; i < 8; i++)
#pragma unroll
        for (int j = 0; j < 4; j++) acc[i][j] = 0.0f;

    for (int k0 = 0; k0 < KTOT; k0 += 16) {
        // load A tile (weights) -> transposed into As[k][m]
        float4 a0 = make_float4(0.f, 0.f, 0.f, 0.f), a1 = a0;
        if (aok) {
            a0 = *reinterpret_cast<const float4*>(wrow + k0);
            a1 = *reinterpret_cast<const float4*>(wrow + k0 + 4);
        }
        As[acol + 0][arow] = a0.x; As[acol + 1][arow] = a0.y;
        As[acol + 2][arow] = a0.z; As[acol + 3][arow] = a0.w;
        As[acol + 4][arow] = a1.x; As[acol + 5][arow] = a1.y;
        As[acol + 6][arow] = a1.z; As[acol + 7][arow] = a1.w;

        // load B tile (on-the-fly im2col with zero padding)
#pragma unroll
        for (int i = 0; i < 4; i++) {
            const int kk = krow * 4 + i;
            const int k  = k0 + kk;
            const int ci = k / (KH * KW);
            const int r  = k - ci * (KH * KW);
            const int ky = r / KW;
            const int kx = r - ky * KW;
            const int iy = py + ky - PH;
            const int ix = px + kx - PW;
            float v = 0.0f;
            if ((unsigned)iy < (unsigned)H_ && (unsigned)ix < (unsigned)W_)
                v = __ldg(inb + ci * HW + iy * W_ + ix);
            Bs[kk][bn] = v;
        }
        __syncthreads();

#pragma unroll
        for (int kk = 0; kk < 16; kk++) {
            const float4 av0 = *reinterpret_cast<const float4*>(&As[kk][tm * 8]);
            const float4 av1 = *reinterpret_cast<const float4*>(&As[kk][tm * 8 + 4]);
            const float4 bv  = *reinterpret_cast<const float4*>(&Bs[kk][tn * 4]);
            const float a[8] = {av0.x, av0.y, av0.z, av0.w, av1.x, av1.y, av1.z, av1.w};
            const float bl[4] = {bv.x, bv.y, bv.z, bv.w};
#pragma unroll
            for (int i = 0; i < 8; i++)
#pragma unroll
                for (int j = 0; j < 4; j++)
                    acc[i][j] = fmaf(a[i], bl[j], acc[i][j]);
        }
        __syncthreads();
    }

    // ---- epilogue: bias + activation + float4 store ----
    const int pj  = n0 + (tn << 2);     // 4 consecutive pixels, same batch (HW%4==0)
    const int b2  = pj / HW;
    const int hwj = pj - b2 * HW;
    float* ob = out + (long)b2 * out_bs + hwj;
#pragma unroll
    for (int i = 0; i < 8; i++) {
        const int co = m0 + tm * 8 + i;
        if (co >= COUT) break;
        const float bv = bias[co];
        float4 o;
        o.x = epi<ACT>(acc[i][0] + bv);
        o.y = epi<ACT>(acc[i][1] + bv);
        o.z = epi<ACT>(acc[i][2] + bv);
        o.w = epi<ACT>(acc[i][3] + bv);
        *reinterpret_cast<float4*>(ob + (long)co * HW) = o;
    }
}

// ------------------------- pointwise kernels -------------------------------

// uniform bins: edges j*5 (j=0..16), centers 2.5 + 5*i
__global__ void setup_bins_kernel() {
    const int p = blockIdx.x * blockDim.x + threadIdx.x;
    if (p >= NPIX) return;
    const int b = p / HW, hw = p - b * HW;
    float* ed = g_scratch + OFF_EDGES + (long)b * 17 * HW + hw;
    float* cd = g_scratch + OFF_CD    + (long)b * 16 * HW + hw;
#pragma unroll
    for (int j = 0; j < 17; j++) ed[j * HW] = 5.0f * j;
#pragma unroll
    for (int i = 0; i < 16; i++) cd[i * HW] = 2.5f + 5.0f * i;
}

__global__ void copy_ctx_kernel(const float* __restrict__ ctx) {
    const long i = (long)blockIdx.x * blockDim.x + threadIdx.x;
    const long N = 2L * 192 * HW;
    if (i >= N) return;
    const long b = i / (192L * HW);
    const long rem = i - b * (192L * HW);
    g_scratch[OFF_HX + b * 576L * HW + 384L * HW + rem] = ctx[i];
}

__global__ void copy_h_kernel(const float* __restrict__ h0) {
    const long i = (long)blockIdx.x * blockDim.x + threadIdx.x;
    const long N = 2L * 128 * HW;
    if (i >= N) return;
    const long b = i / (128L * HW);
    const long rem = i - b * (128L * HW);
    const float v = h0[i];
    g_scratch[OFF_H + i] = v;
    g_scratch[OFF_HX + b * 576L * HW + rem] = v;
}

// hx[h-slot] = r * h   (convq then reads [r*h, x])
__global__ void rh_kernel() {
    const long i = (long)blockIdx.x * blockDim.x + threadIdx.x;
    const long b = i / (128L * HW);
    const long rem = i - b * (128L * HW);
    g_scratch[OFF_HX + b * 576L * HW + rem] =
        g_scratch[OFF_R + i] * g_scratch[OFF_H + i];
}

// h = (1-z)*h + z*q ; also refresh hx h-slot
__global__ void gru_update_kernel() {
    const long i = (long)blockIdx.x * blockDim.x + threadIdx.x;
    const long b = i / (128L * HW);
    const long rem = i - b * (128L * HW);
    const float z = g_scratch[OFF_Z + i];
    const float q = g_scratch[OFF_Q + i];
    const float h = g_scratch[OFF_H + i];
    const float hn = (1.0f - z) * h + z * q;
    g_scratch[OFF_H + i] = hn;
    g_scratch[OFF_HX + b * 576L * HW + rem] = hn;
}

// softmax(16) -> depth_r, uncertainty, label/cs, bin update (per pixel)
__global__ void bins_kernel(float* __restrict__ out, int it) {
    const int p = blockIdx.x * blockDim.x + threadIdx.x;
    if (p >= NPIX) return;
    const int b = p / HW, hw = p - b * HW;

    const float* lg = g_scratch + OFF_LOG   + (long)b * 16 * HW + hw;
    float*       cdp = g_scratch + OFF_CD   + (long)b * 16 * HW + hw;
    float*       edp = g_scratch + OFF_EDGES + (long)b * 17 * HW + hw;

    float l[16], cd[16];
    float m = -1e30f;
#pragma unroll
    for (int i = 0; i < 16; i++) { l[i] = lg[i * HW]; m = fmaxf(m, l[i]); }
    float s = 0.0f;
#pragma unroll
    for (int i = 0; i < 16; i++) { l[i] = expf(l[i] - m); s += l[i]; }
    const float inv = 1.0f / s;

    float dr = 0.0f;
#pragma unroll
    for (int i = 0; i < 16; i++) { cd[i] = cdp[i * HW]; dr += l[i] * cd[i]; }
    dr *= inv;

    float var = 0.0f;
#pragma unroll
    for (int i = 0; i < 16; i++) { const float d = cd[i] - dr; var += l[i] * d * d; }
    var *= inv;
    const float unc = sqrtf(var);

    out[(0 * 6 + it) * NPIX + p] = dr;   // pred_depths_r
    out[(2 * 6 + it) * NPIX + p] = unc;  // uncertainty_maps

    // label: count of edges[1..15] <= dr; 0 if dr >= edges[16]
    int cnt = 0;
#pragma unroll
    for (int j = 1; j <= 15; j++) cnt += (dr >= edp[j * HW]) ? 1 : 0;
    const float etop = edp[16 * HW];
    const int label = (dr >= etop) ? 0 : cnt;
    out[(1 * 6 + it) * NPIX + p] = cd[label];  // pred_depths_c

    // update bins: start = max(dr - unc/2, 0), width = unc/16, clip [0,80]
    const float start = fmaxf(dr - 0.5f * unc, 0.0f);
    const float delta = unc * (1.0f / 16.0f);
    float cum = start;
    float eprev = fminf(fmaxf(cum, 0.0f), 80.0f);
    edp[0] = eprev;
#pragma unroll
    for (int i = 1; i <= 16; i++) {
        cum += delta;
        const float e = fminf(fmaxf(cum, 0.0f), 80.0f);
        edp[i * HW] = e;
        cdp[(i - 1) * HW] = 0.5f * (eprev + e);
        eprev = e;
    }
}

// ------------------------- launch ------------------------------------------
extern "C" void kernel_launch(void* const* d_in, const int* in_sizes, int n_in,
                              void* d_out, int out_size)
{
    (void)in_sizes; (void)n_in; (void)out_size;
    const float* context = (const float*)d_in[1];
    const float* gruh    = (const float*)d_in[2];
    const float* e1w = (const float*)d_in[3];  const float* e1b = (const float*)d_in[4];
    const float* e2w = (const float*)d_in[5];  const float* e2b = (const float*)d_in[6];
    const float* e3w = (const float*)d_in[7];  const float* e3b = (const float*)d_in[8];
    const float* e4w = (const float*)d_in[9];  const float* e4b = (const float*)d_in[10];
    const float* z1w = (const float*)d_in[11]; const float* z1b = (const float*)d_in[12];
    const float* r1w = (const float*)d_in[13]; const float* r1b = (const float*)d_in[14];
    const float* q1w = (const float*)d_in[15]; const float* q1b = (const float*)d_in[16];
    const float* z2w = (const float*)d_in[17]; const float* z2b = (const float*)d_in[18];
    const float* r2w = (const float*)d_in[19]; const float* r2b = (const float*)d_in[20];
    const float* q2w = (const float*)d_in[21]; const float* q2b = (const float*)d_in[22];
    const float* p1w = (const float*)d_in[23]; const float* p1b = (const float*)d_in[24];
    const float* p2w = (const float*)d_in[25]; const float* p2b = (const float*)d_in[26];
    float* out = (float*)d_out;

    const dim3 blk(256);
    const int NT = NPIX / 64;  // 600 pixel tiles

    setup_bins_kernel<<<(NPIX + 255) / 256, 256>>>();
    copy_ctx_kernel<<<(2 * 192 * HW) / 256, 256>>>(context);
    copy_h_kernel<<<(2 * 128 * HW) / 256, 256>>>(gruh);

    for (int it = 0; it < 6; ++it) {
        // ProjectionInputDepth encoder (writes d directly into hx x-slot)
        conv_k<16, 128, 7, 7, 3, 3, ACT_RELU><<<dim3(NT, 1), blk>>>(OFF_CD, 16 * HW, e1w, e1b, OFF_E1, 128 * HW);
        conv_k<128, 128, 3, 3, 1, 1, ACT_RELU><<<dim3(NT, 1), blk>>>(OFF_E1, 128 * HW, e2w, e2b, OFF_E2, 128 * HW);
        conv_k<128, 128, 3, 3, 1, 1, ACT_RELU><<<dim3(NT, 1), blk>>>(OFF_E2, 128 * HW, e3w, e3b, OFF_E1, 128 * HW);
        conv_k<128, 256, 3, 3, 1, 1, ACT_RELU><<<dim3(NT, 2), blk>>>(OFF_E1, 128 * HW, e4w, e4b, OFF_HX + 128L * HW, 576 * HW);

        // SepConvGRU horizontal (1,5)
        conv_k<576, 128, 1, 5, 0, 2, ACT_SIG><<<dim3(NT, 1), blk>>>(OFF_HX, 576 * HW, z1w, z1b, OFF_Z, 128 * HW);
        conv_k<576, 128, 1, 5, 0, 2, ACT_SIG><<<dim3(NT, 1), blk>>>(OFF_HX, 576 * HW, r1w, r1b, OFF_R, 128 * HW);
        rh_kernel<<<(2 * 128 * HW) / 256, 256>>>();
        conv_k<576, 128, 1, 5, 0, 2, ACT_TANH><<<dim3(NT, 1), blk>>>(OFF_HX, 576 * HW, q1w, q1b, OFF_Q, 128 * HW);
        gru_update_kernel<<<(2 * 128 * HW) / 256, 256>>>();

        // SepConvGRU vertical (5,1)
        conv_k<576, 128, 5, 1, 2, 0, ACT_SIG><<<dim3(NT, 1), blk>>>(OFF_HX, 576 * HW, z2w, z2b, OFF_Z, 128 * HW);
        conv_k<576, 128, 5, 1, 2, 0, ACT_SIG><<<dim3(NT, 1), blk>>>(OFF_HX, 576 * HW, r2w, r2b, OFF_R, 128 * HW);
        rh_kernel<<<(2 * 128 * HW) / 256, 256>>>();
        conv_k<576, 128, 5, 1, 2, 0, ACT_TANH><<<dim3(NT, 1), blk>>>(OFF_HX, 576 * HW, q2w, q2b, OFF_Q, 128 * HW);
        gru_update_kernel<<<(2 * 128 * HW) / 256, 256>>>();

        // PHead
        conv_k<128, 128, 3, 3, 1, 1, ACT_RELU><<<dim3(NT, 1), blk>>>(OFF_H, 128 * HW, p1w, p1b, OFF_E1, 128 * HW);
        conv_k<128, 16, 3, 3, 1, 1, ACT_NONE><<<dim3(NT, 1), blk>>>(OFF_E1, 128 * HW, p2w, p2b, OFF_LOG, 16 * HW);

        // softmax / depth_r / uncertainty / label / bin update + outputs
        bins_kernel<<<(NPIX + 127) / 128, 128>>>(out, it);
    }
}

// round 6
// speedup vs baseline: 1.0059x; 1.0059x over previous
#include <cuda_runtime.h>
#include <math.h>

// ---------------------------------------------------------------------------
// IEBINS — fixed shapes: B=2, H=120, W=160, HD=128, CD=192, BN=16, 6 iters
// fp32 implicit-GEMM direct convs + fused pointwise/bins kernels.
// ---------------------------------------------------------------------------

#define H_   120
#define W_   160
#define HW   19200
#define NPIX 38400   // B * HW

enum { ACT_NONE = 0, ACT_RELU = 1, ACT_SIG = 2, ACT_TANH = 3 };

// ------------------------- scratch (single static arena) -------------------
// edges : 2*17*HW  =   652,800
// cd    : 2*16*HW  =   614,400
// e1    : 2*128*HW = 4,915,200
// e2    : 2*128*HW = 4,915,200
// hx    : 2*576*HW = 22,118,400   layout per batch: [h 0:128 | d 128:384 | ctx 384:576]
// h     : 2*128*HW
// z,r,q : 2*128*HW each
// logits: 2*16*HW
constexpr long OFF_EDGES = 0;
constexpr long OFF_CD    = 652800;
constexpr long OFF_E1    = 1267200;
constexpr long OFF_E2    = 6182400;
constexpr long OFF_HX    = 11097600;
constexpr long OFF_H     = 33216000;
constexpr long OFF_Z     = 38131200;
constexpr long OFF_R     = 43046400;
constexpr long OFF_Q     = 47961600;
constexpr long OFF_LOG   = 52876800;
constexpr long SCRATCH_TOTAL = 53491200;   // floats (~204 MiB)

__device__ __align__(16) float g_scratch[SCRATCH_TOTAL];

// ------------------------- activation epilogue -----------------------------
template <int ACT>
__device__ __forceinline__ float epi(float v) {
    if (ACT == ACT_RELU) return fmaxf(v, 0.0f);
    if (ACT == ACT_SIG)  return 1.0f / (1.0f + expf(-v));
    if (ACT == ACT_TANH) return tanhf(v);
    return v;
}

// ------------------------- implicit-GEMM conv ------------------------------
// O[b, co, y, x] = act( bias[co] + sum_{ci,ky,kx} W[co,ci,ky,kx] *
//                       I[b, ci, y+ky-PH, x+kx-PW] )
// GEMM view: M = COUT (tile 128), N = NPIX (tile 64), K = CIN*KH*KW (step 16)
// 256 threads, 8x4 register micro-tile per thread.
template <int CIN, int COUT, int KH, int KW, int PH, int PW, int ACT>
__global__ __launch_bounds__(256)
void conv_k(long in_off, int in_bs,
            const float* __restrict__ wgt, const float* __restrict__ bias,
            long out_off, int out_bs)
{
    constexpr int KTOT = CIN * KH * KW;
    static_assert(KTOT % 16 == 0, "K must be a multiple of 16");

    __shared__ __align__(16) float As[16][136];  // [k][m], padded
    __shared__ __align__(16) float Bs[16][72];   // [k][n], padded

    const float* in  = g_scratch + in_off;
    float*       out = g_scratch + out_off;

    const int tid = threadIdx.x;
    const int n0  = blockIdx.x << 6;   // pixel tile base (64)
    const int m0  = blockIdx.y << 7;   // out-channel tile base (128)

    // ---- B (im2col) loader coords: one pixel per thread, 4 k-rows ----
    const int bn   = tid & 63;
    const int krow = tid >> 6;         // 0..3
    const int p    = n0 + bn;          // NPIX % 64 == 0 -> always valid
    const int bb   = p / HW;
    const int hw   = p - bb * HW;
    const int py   = hw / W_;
    const int px   = hw - py * W_;
    const float* inb = in + (long)bb * in_bs;

    // ---- A (weights) loader coords: 2 float4 per thread ----
    const int arow = tid >> 1;                 // 0..127
    const int acol = (tid & 1) << 3;           // 0 or 8
    const bool aok = (m0 + arow) < COUT;
    const float* wrow = wgt + (long)(m0 + arow) * KTOT + acol;

    // ---- micro-tile coords ----
    const int tn = tid & 15;   // 16 col groups of 4 pixels
    const int tm = tid >> 4;   // 16 row groups of 8 channels

    float acc[8][4];
#pragma unroll
    for (int i = 0; i < 8; i++)
#pragma unroll
        for (int j = 0; j < 4; j++) acc[i][j] = 0.0f;

    for (int k0 = 0; k0 < KTOT; k0 += 16) {
        // load A tile (weights) -> transposed into As[k][m]
        float4 a0 = make_float4(0.f, 0.f, 0.f, 0.f), a1 = a0;
        if (aok) {
            a0 = *reinterpret_cast<const float4*>(wrow + k0);
            a1 = *reinterpret_cast<const float4*>(wrow + k0 + 4);
        }
        As[acol + 0][arow] = a0.x; As[acol + 1][arow] = a0.y;
        As[acol + 2][arow] = a0.z; As[acol + 3][arow] = a0.w;
        As[acol + 4][arow] = a1.x; As[acol + 5][arow] = a1.y;
        As[acol + 6][arow] = a1.z; As[acol + 7][arow] = a1.w;

        // load B tile (on-the-fly im2col with zero padding)
#pragma unroll
        for (int i = 0; i < 4; i++) {
            const int kk = krow * 4 + i;
            const int k  = k0 + kk;
            const int ci = k / (KH * KW);
            const int r  = k - ci * (KH * KW);
            const int ky = r / KW;
            const int kx = r - ky * KW;
            const int iy = py + ky - PH;
            const int ix = px + kx - PW;
            float v = 0.0f;
            if ((unsigned)iy < (unsigned)H_ && (unsigned)ix < (unsigned)W_)
                v = __ldg(inb + ci * HW + iy * W_ + ix);
            Bs[kk][bn] = v;
        }
        __syncthreads();

#pragma unroll
        for (int kk = 0; kk < 16; kk++) {
            const float4 av0 = *reinterpret_cast<const float4*>(&As[kk][tm * 8]);
            const float4 av1 = *reinterpret_cast<const float4*>(&As[kk][tm * 8 + 4]);
            const float4 bv  = *reinterpret_cast<const float4*>(&Bs[kk][tn * 4]);
            const float a[8] = {av0.x, av0.y, av0.z, av0.w, av1.x, av1.y, av1.z, av1.w};
            const float bl[4] = {bv.x, bv.y, bv.z, bv.w};
#pragma unroll
            for (int i = 0; i < 8; i++)
#pragma unroll
                for (int j = 0; j < 4; j++)
                    acc[i][j] = fmaf(a[i], bl[j], acc[i][j]);
        }
        __syncthreads();
    }

    // ---- epilogue: bias + activation + float4 store ----
    const int pj  = n0 + (tn << 2);     // 4 consecutive pixels, same batch (HW%4==0)
    const int b2  = pj / HW;
    const int hwj = pj - b2 * HW;
    float* ob = out + (long)b2 * out_bs + hwj;
#pragma unroll
    for (int i = 0; i < 8; i++) {
        const int co = m0 + tm * 8 + i;
        if (co >= COUT) break;
        const float bv = bias[co];
        float4 o;
        o.x = epi<ACT>(acc[i][0] + bv);
        o.y = epi<ACT>(acc[i][1] + bv);
        o.z = epi<ACT>(acc[i][2] + bv);
        o.w = epi<ACT>(acc[i][3] + bv);
        *reinterpret_cast<float4*>(ob + (long)co * HW) = o;
    }
}

// ------------------------- pointwise kernels -------------------------------

// uniform bins: edges j*5 (j=0..16), centers 2.5 + 5*i
__global__ void setup_bins_kernel() {
    const int p = blockIdx.x * blockDim.x + threadIdx.x;
    if (p >= NPIX) return;
    const int b = p / HW, hw = p - b * HW;
    float* ed = g_scratch + OFF_EDGES + (long)b * 17 * HW + hw;
    float* cd = g_scratch + OFF_CD    + (long)b * 16 * HW + hw;
#pragma unroll
    for (int j = 0; j < 17; j++) ed[j * HW] = 5.0f * j;
#pragma unroll
    for (int i = 0; i < 16; i++) cd[i * HW] = 2.5f + 5.0f * i;
}

__global__ void copy_ctx_kernel(const float* __restrict__ ctx) {
    const long i = (long)blockIdx.x * blockDim.x + threadIdx.x;
    const long N = 2L * 192 * HW;
    if (i >= N) return;
    const long b = i / (192L * HW);
    const long rem = i - b * (192L * HW);
    g_scratch[OFF_HX + b * 576L * HW + 384L * HW + rem] = ctx[i];
}

__global__ void copy_h_kernel(const float* __restrict__ h0) {
    const long i = (long)blockIdx.x * blockDim.x + threadIdx.x;
    const long N = 2L * 128 * HW;
    if (i >= N) return;
    const long b = i / (128L * HW);
    const long rem = i - b * (128L * HW);
    const float v = h0[i];
    g_scratch[OFF_H + i] = v;
    g_scratch[OFF_HX + b * 576L * HW + rem] = v;
}

// hx[h-slot] = r * h   (convq then reads [r*h, x])
__global__ void rh_kernel() {
    const long i = (long)blockIdx.x * blockDim.x + threadIdx.x;
    const long b = i / (128L * HW);
    const long rem = i - b * (128L * HW);
    g_scratch[OFF_HX + b * 576L * HW + rem] =
        g_scratch[OFF_R + i] * g_scratch[OFF_H + i];
}

// h = (1-z)*h + z*q ; also refresh hx h-slot
__global__ void gru_update_kernel() {
    const long i = (long)blockIdx.x * blockDim.x + threadIdx.x;
    const long b = i / (128L * HW);
    const long rem = i - b * (128L * HW);
    const float z = g_scratch[OFF_Z + i];
    const float q = g_scratch[OFF_Q + i];
    const float h = g_scratch[OFF_H + i];
    const float hn = (1.0f - z) * h + z * q;
    g_scratch[OFF_H + i] = hn;
    g_scratch[OFF_HX + b * 576L * HW + rem] = hn;
}

// softmax(16) -> depth_r, uncertainty, label/cs, bin update (per pixel)
__global__ void bins_kernel(float* __restrict__ out, int it) {
    const int p = blockIdx.x * blockDim.x + threadIdx.x;
    if (p >= NPIX) return;
    const int b = p / HW, hw = p - b * HW;

    const float* lg = g_scratch + OFF_LOG   + (long)b * 16 * HW + hw;
    float*       cdp = g_scratch + OFF_CD   + (long)b * 16 * HW + hw;
    float*       edp = g_scratch + OFF_EDGES + (long)b * 17 * HW + hw;

    float l[16], cd[16];
    float m = -1e30f;
#pragma unroll
    for (int i = 0; i < 16; i++) { l[i] = lg[i * HW]; m = fmaxf(m, l[i]); }
    float s = 0.0f;
#pragma unroll
    for (int i = 0; i < 16; i++) { l[i] = expf(l[i] - m); s += l[i]; }
    const float inv = 1.0f / s;

    float dr = 0.0f;
#pragma unroll
    for (int i = 0; i < 16; i++) { cd[i] = cdp[i * HW]; dr += l[i] * cd[i]; }
    dr *= inv;

    float var = 0.0f;
#pragma unroll
    for (int i = 0; i < 16; i++) { const float d = cd[i] - dr; var += l[i] * d * d; }
    var *= inv;
    const float unc = sqrtf(var);

    out[(0 * 6 + it) * NPIX + p] = dr;   // pred_depths_r
    out[(2 * 6 + it) * NPIX + p] = unc;  // uncertainty_maps

    // label: count of edges[1..15] <= dr; 0 if dr >= edges[16]
    int cnt = 0;
#pragma unroll
    for (int j = 1; j <= 15; j++) cnt += (dr >= edp[j * HW]) ? 1 : 0;
    const float etop = edp[16 * HW];
    const int label = (dr >= etop) ? 0 : cnt;
    out[(1 * 6 + it) * NPIX + p] = cd[label];  // pred_depths_c

    // update bins: start = max(dr - unc/2, 0), width = unc/16, clip [0,80]
    const float start = fmaxf(dr - 0.5f * unc, 0.0f);
    const float delta = unc * (1.0f / 16.0f);
    float cum = start;
    float eprev = fminf(fmaxf(cum, 0.0f), 80.0f);
    edp[0] = eprev;
#pragma unroll
    for (int i = 1; i <= 16; i++) {
        cum += delta;
        const float e = fminf(fmaxf(cum, 0.0f), 80.0f);
        edp[i * HW] = e;
        cdp[(i - 1) * HW] = 0.5f * (eprev + e);
        eprev = e;
    }
}

// ------------------------- launch ------------------------------------------
extern "C" void kernel_launch(void* const* d_in, const int* in_sizes, int n_in,
                              void* d_out, int out_size)
{
    (void)in_sizes; (void)n_in; (void)out_size;
    const float* context = (const float*)d_in[1];
    const float* gruh    = (const float*)d_in[2];
    const float* e1w = (const float*)d_in[3];  const float* e1b = (const float*)d_in[4];
    const float* e2w = (const float*)d_in[5];  const float* e2b = (const float*)d_in[6];
    const float* e3w = (const float*)d_in[7];  const float* e3b = (const float*)d_in[8];
    const float* e4w = (const float*)d_in[9];  const float* e4b = (const float*)d_in[10];
    const float* z1w = (const float*)d_in[11]; const float* z1b = (const float*)d_in[12];
    const float* r1w = (const float*)d_in[13]; const float* r1b = (const float*)d_in[14];
    const float* q1w = (const float*)d_in[15]; const float* q1b = (const float*)d_in[16];
    const float* z2w = (const float*)d_in[17]; const float* z2b = (const float*)d_in[18];
    const float* r2w = (const float*)d_in[19]; const float* r2b = (const float*)d_in[20];
    const float* q2w = (const float*)d_in[21]; const float* q2b = (const float*)d_in[22];
    const float* p1w = (const float*)d_in[23]; const float* p1b = (const float*)d_in[24];
    const float* p2w = (const float*)d_in[25]; const float* p2b = (const float*)d_in[26];
    float* out = (float*)d_out;

    const dim3 blk(256);
    const int NT = NPIX / 64;  // 600 pixel tiles

    setup_bins_kernel<<<(NPIX + 255) / 256, 256>>>();
    copy_ctx_kernel<<<(2 * 192 * HW) / 256, 256>>>(context);
    copy_h_kernel<<<(2 * 128 * HW) / 256, 256>>>(gruh);

    for (int it = 0; it < 6; ++it) {
        // ProjectionInputDepth encoder (writes d directly into hx x-slot)
        conv_k<16, 128, 7, 7, 3, 3, ACT_RELU><<<dim3(NT, 1), blk>>>(OFF_CD, 16 * HW, e1w, e1b, OFF_E1, 128 * HW);
        conv_k<128, 128, 3, 3, 1, 1, ACT_RELU><<<dim3(NT, 1), blk>>>(OFF_E1, 128 * HW, e2w, e2b, OFF_E2, 128 * HW);
        conv_k<128, 128, 3, 3, 1, 1, ACT_RELU><<<dim3(NT, 1), blk>>>(OFF_E2, 128 * HW, e3w, e3b, OFF_E1, 128 * HW);
        conv_k<128, 256, 3, 3, 1, 1, ACT_RELU><<<dim3(NT, 2), blk>>>(OFF_E1, 128 * HW, e4w, e4b, OFF_HX + 128L * HW, 576 * HW);

        // SepConvGRU horizontal (1,5)
        conv_k<576, 128, 1, 5, 0, 2, ACT_SIG><<<dim3(NT, 1), blk>>>(OFF_HX, 576 * HW, z1w, z1b, OFF_Z, 128 * HW);
        conv_k<576, 128, 1, 5, 0, 2, ACT_SIG><<<dim3(NT, 1), blk>>>(OFF_HX, 576 * HW, r1w, r1b, OFF_R, 128 * HW);
        rh_kernel<<<(2 * 128 * HW) / 256, 256>>>();
        conv_k<576, 128, 1, 5, 0, 2, ACT_TANH><<<dim3(NT, 1), blk>>>(OFF_HX, 576 * HW, q1w, q1b, OFF_Q, 128 * HW);
        gru_update_kernel<<<(2 * 128 * HW) / 256, 256>>>();

        // SepConvGRU vertical (5,1)
        conv_k<576, 128, 5, 1, 2, 0, ACT_SIG><<<dim3(NT, 1), blk>>>(OFF_HX, 576 * HW, z2w, z2b, OFF_Z, 128 * HW);
        conv_k<576, 128, 5, 1, 2, 0, ACT_SIG><<<dim3(NT, 1), blk>>>(OFF_HX, 576 * HW, r2w, r2b, OFF_R, 128 * HW);
        rh_kernel<<<(2 * 128 * HW) / 256, 256>>>();
        conv_k<576, 128, 5, 1, 2, 0, ACT_TANH><<<dim3(NT, 1), blk>>>(OFF_HX, 576 * HW, q2w, q2b, OFF_Q, 128 * HW);
        gru_update_kernel<<<(2 * 128 * HW) / 256, 256>>>();

        // PHead
        conv_k<128, 128, 3, 3, 1, 1, ACT_RELU><<<dim3(NT, 1), blk>>>(OFF_H, 128 * HW, p1w, p1b, OFF_E1, 128 * HW);
        conv_k<128, 16, 3, 3, 1, 1, ACT_NONE><<<dim3(NT, 1), blk>>>(OFF_E1, 128 * HW, p2w, p2b, OFF_LOG, 16 * HW);

        // softmax / depth_r / uncertainty / label / bin update + outputs
        bins_kernel<<<(NPIX + 127) / 128, 128>>>(out, it);
    }
}

// round 8
// speedup vs baseline: 1.6884x; 1.6784x over previous
#include <cuda_runtime.h>
#include <cuda_bf16.h>
#include <math.h>
#include <stdint.h>

// ---------------------------------------------------------------------------
// IEBINS — B=2, H=120, W=160, HD=128, CD=192, BN=16, 6 iters
// mma.sync bf16 (3-term split) implicit-GEMM convs + fused pointwise.
// ---------------------------------------------------------------------------

#define H_   120
#define W_   160
#define HW   19200
#define NPIX 38400

enum { ACT_NONE = 0, ACT_RELU = 1, ACT_SIG = 2, ACT_TANH = 3 };

// ------------------------- float scratch arena -----------------------------
constexpr long OFF_EDGES = 0;
constexpr long OFF_CD    = 652800;
constexpr long OFF_E1    = 1267200;
constexpr long OFF_E2    = 6182400;    // also 128-ch padded logits
constexpr long OFF_HX    = 11097600;   // [b][576][HW]: h | d | ctx
constexpr long OFF_H     = 33216000;
constexpr long OFF_ZR    = 38131200;   // [b][256][HW]: z | r
constexpr long OFF_Q     = 47961600;
constexpr long OFF_PB2   = 52876800;   // padded ph2 bias (128)
constexpr long SCRATCH_TOTAL = OFF_PB2 + 128;

__device__ __align__(1024) float g_scratch[SCRATCH_TOTAL];

// ------------------------- bf16 split-weight arena -------------------------
// layout per conv: [COUT(padded)][KH*KW][CIN] (reordered, bf16 hi / lo)
constexpr long W_E1  = 0;         // 128*784   = 100352
constexpr long W_E2  = 100352;    // 147456
constexpr long W_E3  = 247808;    // 147456
constexpr long W_E4  = 395264;    // 294912
constexpr long W_ZR1 = 690176;    // 737280 (z rows 0..127 | r rows 128..255)
constexpr long W_Q1  = 1427456;   // 368640
constexpr long W_ZR2 = 1796096;   // 737280
constexpr long W_Q2  = 2533376;   // 368640
constexpr long W_P1  = 2902016;   // 147456
constexpr long W_P2  = 3049472;   // 147456 (COUT padded 16->128)
constexpr long W_TOT = 3196928;

__device__ __align__(16) __nv_bfloat16 g_whi[W_TOT];
__device__ __align__(16) __nv_bfloat16 g_wlo[W_TOT];

// ------------------------- helpers -----------------------------------------
template <int ACT>
__device__ __forceinline__ float epi(float v) {
    if (ACT == ACT_RELU) return fmaxf(v, 0.0f);
    if (ACT == ACT_SIG)  return 1.0f / (1.0f + expf(-v));
    if (ACT == ACT_TANH) return tanhf(v);
    return v;
}

__device__ __forceinline__ void mma16816(float* c, const uint32_t* a, const uint32_t* b) {
    asm volatile(
        "mma.sync.aligned.m16n8k16.row.col.f32.bf16.bf16.f32 "
        "{%0,%1,%2,%3}, {%4,%5,%6,%7}, {%8,%9}, {%0,%1,%2,%3};\n"
        : "+f"(c[0]), "+f"(c[1]), "+f"(c[2]), "+f"(c[3])
        : "r"(a[0]), "r"(a[1]), "r"(a[2]), "r"(a[3]), "r"(b[0]), "r"(b[1]));
}

__device__ __forceinline__ void bf16_split(float f, unsigned short& h, unsigned short& l) {
    __nv_bfloat16 hb = __float2bfloat16_rn(f);
    __nv_bfloat16 lb = __float2bfloat16_rn(f - __bfloat162float(hb));
    h = *reinterpret_cast<unsigned short*>(&hb);
    l = *reinterpret_cast<unsigned short*>(&lb);
}

// ===========================================================================
// mma.sync bf16 implicit-GEMM conv.
// GEMM: M = COUT (128 per blockIdx.y), N = 64 pixels, K = KH*KW*CIN in 16-chunks
// (K order: position outer, 16 input channels inner -> cheap im2col).
// 8 warps as 4(m) x 2(n); warp tile 32x32 = 2 x 4 m16n8k16 frags; 3-term split.
// ===========================================================================
template <int CIN, int COUT, int KH, int KW, int PH, int PW, int ACT>
__global__ __launch_bounds__(256)
void conv_mma(long in_off, int in_bs, long w_off,
              const float* __restrict__ bias0, const float* __restrict__ bias1,
              long out_off, int out_bs)
{
    constexpr int KTOT  = CIN * KH * KW;
    constexpr int CPC   = CIN / 16;        // 16-channel chunks per position
    constexpr int NITER = KTOT / 16;
    static_assert(CIN % 16 == 0, "CIN must be multiple of 16");

    // smem: double buffer (2 x 18432B): Ahi[128][24bf16] Alo Bhi[64][24] Blo
    // epilogue overlays as float stage [128][68]
    __shared__ __align__(16) char smem[36864];

    const int tid  = threadIdx.x;
    const int lane = tid & 31;
    const int wid  = tid >> 5;
    const int warp_m = wid & 3;            // 0..3 (32 rows each)
    const int warp_n = wid >> 2;           // 0..1 (32 cols each)
    const int g  = lane >> 2;
    const int tg = lane & 3;

    const int n0 = blockIdx.x << 6;        // 64-pixel tile (64 | HW)
    const int m0 = blockIdx.y << 7;        // 128-channel tile
    const int bb = n0 / HW;
    const int hw0 = n0 - bb * HW;
    const float* inb = g_scratch + in_off + (long)bb * in_bs;

    // B loader: 4 values (one pixel, 4 consecutive ci) per thread
    const int pixl = tid & 63;
    const int kq   = tid >> 6;             // 0..3
    const int hwp  = hw0 + pixl;
    const int py   = hwp / W_;
    const int px   = hwp - py * W_;

    // A loader: one 16-element k-row (hi or lo) per thread
    const int arow = tid & 127;
    const int asel = tid >> 7;             // 0 = hi, 1 = lo
    const __nv_bfloat16* wbase =
        (asel ? g_wlo : g_whi) + w_off + (long)(m0 + arow) * KTOT;

    float acc[2][4][4];
#pragma unroll
    for (int mt = 0; mt < 2; mt++)
#pragma unroll
        for (int nt = 0; nt < 4; nt++)
#pragma unroll
            for (int e = 0; e < 4; e++) acc[mt][nt][e] = 0.0f;

    uint4 pa0, pa1;
    float pbv[4];

    auto ldg = [&](int it) {
        const uint4* ap = reinterpret_cast<const uint4*>(wbase + it * 16);
        pa0 = ap[0];
        pa1 = ap[1];
        const int pos = it / CPC;
        const int cic = it - pos * CPC;
        const int ky  = pos / KW;
        const int kx  = pos - ky * KW;
        const int iy  = py + ky - PH;
        const int ix  = px + kx - PW;
        const bool ok = ((unsigned)iy < (unsigned)H_) && ((unsigned)ix < (unsigned)W_);
        const float* src = inb + (long)(cic * 16 + kq * 4) * HW + iy * W_ + ix;
#pragma unroll
        for (int j = 0; j < 4; j++)
            pbv[j] = ok ? __ldg(src + j * HW) : 0.0f;
    };

    ldg(0);
    int buf = 0;
#pragma unroll 1
    for (int it = 0; it < NITER; ++it) {
        char* sb = smem + buf * 18432;
        // STS A (prefetched bf16 row chunk)
        {
            char* dst = sb + asel * 6144 + arow * 48;
            *reinterpret_cast<uint4*>(dst)      = pa0;
            *reinterpret_cast<uint4*>(dst + 16) = pa1;
        }
        // STS B (split fp32 -> bf16 hi/lo)
        {
            ushort4 hv, lv;
            bf16_split(pbv[0], hv.x, lv.x);
            bf16_split(pbv[1], hv.y, lv.y);
            bf16_split(pbv[2], hv.z, lv.z);
            bf16_split(pbv[3], hv.w, lv.w);
            const int bo = pixl * 48 + kq * 8;
            *reinterpret_cast<ushort4*>(sb + 12288 + bo) = hv;
            *reinterpret_cast<ushort4*>(sb + 15360 + bo) = lv;
        }
        __syncthreads();
        if (it + 1 < NITER) ldg(it + 1);   // overlaps MMA below

        const char* Ah = sb;
        const char* Al = sb + 6144;
        const char* Bh = sb + 12288;
        const char* Bl = sb + 15360;

        uint32_t ah[8], al[8];
#pragma unroll
        for (int mt = 0; mt < 2; mt++) {
            const int r0 = (warp_m * 32 + mt * 16 + g) * 48 + tg * 4;
            ah[mt * 4 + 0] = *reinterpret_cast<const uint32_t*>(Ah + r0);
            ah[mt * 4 + 1] = *reinterpret_cast<const uint32_t*>(Ah + r0 + 8 * 48);
            ah[mt * 4 + 2] = *reinterpret_cast<const uint32_t*>(Ah + r0 + 16);
            ah[mt * 4 + 3] = *reinterpret_cast<const uint32_t*>(Ah + r0 + 8 * 48 + 16);
            al[mt * 4 + 0] = *reinterpret_cast<const uint32_t*>(Al + r0);
            al[mt * 4 + 1] = *reinterpret_cast<const uint32_t*>(Al + r0 + 8 * 48);
            al[mt * 4 + 2] = *reinterpret_cast<const uint32_t*>(Al + r0 + 16);
            al[mt * 4 + 3] = *reinterpret_cast<const uint32_t*>(Al + r0 + 8 * 48 + 16);
        }
#pragma unroll
        for (int nt = 0; nt < 4; nt++) {
            const int c0 = (warp_n * 32 + nt * 8 + g) * 48 + tg * 4;
            uint32_t bh[2], bl[2];
            bh[0] = *reinterpret_cast<const uint32_t*>(Bh + c0);
            bh[1] = *reinterpret_cast<const uint32_t*>(Bh + c0 + 16);
            bl[0] = *reinterpret_cast<const uint32_t*>(Bl + c0);
            bl[1] = *reinterpret_cast<const uint32_t*>(Bl + c0 + 16);
#pragma unroll
            for (int mt = 0; mt < 2; mt++) {
                mma16816(acc[mt][nt], &ah[mt * 4], bh);
                mma16816(acc[mt][nt], &ah[mt * 4], bl);
                mma16816(acc[mt][nt], &al[mt * 4], bh);
            }
        }
        buf ^= 1;
    }

    // ---- epilogue: stage via smem for coalesced stores ----
    __syncthreads();
    float* st = reinterpret_cast<float*>(smem);
#pragma unroll
    for (int mt = 0; mt < 2; mt++)
#pragma unroll
        for (int nt = 0; nt < 4; nt++) {
            const int r = warp_m * 32 + mt * 16 + g;
            const int c = warp_n * 32 + nt * 8 + 2 * tg;
            st[r * 68 + c]           = acc[mt][nt][0];
            st[r * 68 + c + 1]       = acc[mt][nt][1];
            st[(r + 8) * 68 + c]     = acc[mt][nt][2];
            st[(r + 8) * 68 + c + 1] = acc[mt][nt][3];
        }
    __syncthreads();

    const float* bias = (blockIdx.y == 0) ? bias0 : bias1;
    const int row = tid >> 1;
    const int ch  = (tid & 1) * 32;
    const float bv = __ldg(bias + row);
    float* op = g_scratch + out_off + (long)bb * out_bs
              + (long)(m0 + row) * HW + hw0 + ch;
#pragma unroll
    for (int q = 0; q < 8; q++) {
        float4 v = *reinterpret_cast<float4*>(&st[row * 68 + ch + q * 4]);
        float4 o;
        o.x = epi<ACT>(v.x + bv);
        o.y = epi<ACT>(v.y + bv);
        o.z = epi<ACT>(v.z + bv);
        o.w = epi<ACT>(v.w + bv);
        *reinterpret_cast<float4*>(op + q * 4) = o;
    }
}

// ------------------------- setup / pointwise kernels -----------------------
// reorder [co][ci][pos] -> [co][pos][ci], split fp32 -> bf16 hi/lo, pad rows
__global__ void split_w_kernel(const float* __restrict__ w, long off,
                               int rows, int vrows, int cin, int khw) {
    const int ktot = cin * khw;
    const long n = (long)rows * ktot;
    const long i = (long)blockIdx.x * blockDim.x + threadIdx.x;
    if (i >= n) return;
    const int co  = (int)(i / ktot);
    const int rem = (int)(i - (long)co * ktot);
    const int pos = rem / cin;
    const int ci  = rem - pos * cin;
    float x = 0.0f;
    if (co < vrows) x = w[(long)co * ktot + (long)ci * khw + pos];
    __nv_bfloat16 h = __float2bfloat16_rn(x);
    g_whi[off + i] = h;
    g_wlo[off + i] = __float2bfloat16_rn(x - __bfloat162float(h));
}
__global__ void pad_bias_kernel(const float* __restrict__ b) {
    const int i = threadIdx.x;
    g_scratch[OFF_PB2 + i] = (i < 16) ? b[i] : 0.0f;
}
__global__ void setup_bins_kernel() {
    const int p = blockIdx.x * blockDim.x + threadIdx.x;
    if (p >= NPIX) return;
    const int b = p / HW, hw = p - b * HW;
    float* ed = g_scratch + OFF_EDGES + (long)b * 17 * HW + hw;
    float* cd = g_scratch + OFF_CD    + (long)b * 16 * HW + hw;
#pragma unroll
    for (int j = 0; j < 17; j++) ed[j * HW] = 5.0f * j;
#pragma unroll
    for (int i = 0; i < 16; i++) cd[i * HW] = 2.5f + 5.0f * i;
}
__global__ void copy_ctx_kernel(const float* __restrict__ ctx) {
    const long i = (long)blockIdx.x * blockDim.x + threadIdx.x;
    if (i >= 2L * 192 * HW) return;
    const long b = i / (192L * HW);
    const long rem = i - b * (192L * HW);
    g_scratch[OFF_HX + b * 576L * HW + 384L * HW + rem] = ctx[i];
}
__global__ void copy_h_kernel(const float* __restrict__ h0) {
    const long i = (long)blockIdx.x * blockDim.x + threadIdx.x;
    if (i >= 2L * 128 * HW) return;
    const long b = i / (128L * HW);
    const long rem = i - b * (128L * HW);
    const float v = h0[i];
    g_scratch[OFF_H + i] = v;
    g_scratch[OFF_HX + b * 576L * HW + rem] = v;
}
__global__ void rh_kernel() {
    const long i = (long)blockIdx.x * blockDim.x + threadIdx.x;
    const long b = i / (128L * HW);
    const long rem = i - b * (128L * HW);
    const float r = g_scratch[OFF_ZR + b * 256L * HW + 128L * HW + rem];
    g_scratch[OFF_HX + b * 576L * HW + rem] = r * g_scratch[OFF_H + i];
}
__global__ void gru_update_kernel() {
    const long i = (long)blockIdx.x * blockDim.x + threadIdx.x;
    const long b = i / (128L * HW);
    const long rem = i - b * (128L * HW);
    const float z = g_scratch[OFF_ZR + b * 256L * HW + rem];
    const float q = g_scratch[OFF_Q + i];
    const float h = g_scratch[OFF_H + i];
    const float hn = (1.0f - z) * h + z * q;
    g_scratch[OFF_H + i] = hn;
    g_scratch[OFF_HX + b * 576L * HW + rem] = hn;
}
__global__ void bins_kernel(float* __restrict__ out, int it) {
    const int p = blockIdx.x * blockDim.x + threadIdx.x;
    if (p >= NPIX) return;
    const int b = p / HW, hw = p - b * HW;
    const float* lg  = g_scratch + OFF_E2    + (long)b * 128 * HW + hw; // padded logits
    float*       cdp = g_scratch + OFF_CD    + (long)b * 16 * HW + hw;
    float*       edp = g_scratch + OFF_EDGES + (long)b * 17 * HW + hw;

    float l[16], cd[16];
    float m = -1e30f;
#pragma unroll
    for (int i = 0; i < 16; i++) { l[i] = lg[i * HW]; m = fmaxf(m, l[i]); }
    float s = 0.0f;
#pragma unroll
    for (int i = 0; i < 16; i++) { l[i] = expf(l[i] - m); s += l[i]; }
    const float inv = 1.0f / s;
    float dr = 0.0f;
#pragma unroll
    for (int i = 0; i < 16; i++) { cd[i] = cdp[i * HW]; dr += l[i] * cd[i]; }
    dr *= inv;
    float var = 0.0f;
#pragma unroll
    for (int i = 0; i < 16; i++) { const float d = cd[i] - dr; var += l[i] * d * d; }
    var *= inv;
    const float unc = sqrtf(var);

    out[(0 * 6 + it) * NPIX + p] = dr;
    out[(2 * 6 + it) * NPIX + p] = unc;

    int cnt = 0;
#pragma unroll
    for (int j = 1; j <= 15; j++) cnt += (dr >= edp[j * HW]) ? 1 : 0;
    const int label = (dr >= edp[16 * HW]) ? 0 : cnt;
    out[(1 * 6 + it) * NPIX + p] = cd[label];

    const float start = fmaxf(dr - 0.5f * unc, 0.0f);
    const float delta = unc * (1.0f / 16.0f);
    float cum = start;
    float eprev = fminf(fmaxf(cum, 0.0f), 80.0f);
    edp[0] = eprev;
#pragma unroll
    for (int i = 1; i <= 16; i++) {
        cum += delta;
        const float e = fminf(fmaxf(cum, 0.0f), 80.0f);
        edp[i * HW] = e;
        cdp[(i - 1) * HW] = 0.5f * (eprev + e);
        eprev = e;
    }
}

// ------------------------- launch ------------------------------------------
extern "C" void kernel_launch(void* const* d_in, const int* in_sizes, int n_in,
                              void* d_out, int out_size)
{
    (void)in_sizes; (void)n_in; (void)out_size;
    const float* context = (const float*)d_in[1];
    const float* gruh    = (const float*)d_in[2];
    const float* e1w = (const float*)d_in[3];  const float* e1b = (const float*)d_in[4];
    const float* e2w = (const float*)d_in[5];  const float* e2b = (const float*)d_in[6];
    const float* e3w = (const float*)d_in[7];  const float* e3b = (const float*)d_in[8];
    const float* e4w = (const float*)d_in[9];  const float* e4b = (const float*)d_in[10];
    const float* z1w = (const float*)d_in[11]; const float* z1b = (const float*)d_in[12];
    const float* r1w = (const float*)d_in[13]; const float* r1b = (const float*)d_in[14];
    const float* q1w = (const float*)d_in[15]; const float* q1b = (const float*)d_in[16];
    const float* z2w = (const float*)d_in[17]; const float* z2b = (const float*)d_in[18];
    const float* r2w = (const float*)d_in[19]; const float* r2b = (const float*)d_in[20];
    const float* q2w = (const float*)d_in[21]; const float* q2b = (const float*)d_in[22];
    const float* p1w = (const float*)d_in[23]; const float* p1b = (const float*)d_in[24];
    const float* p2w = (const float*)d_in[25]; const float* p2b = (const float*)d_in[26];
    float* out = (float*)d_out;

    float* sbase = nullptr;
    cudaGetSymbolAddress((void**)&sbase, g_scratch);
    const float* pb2 = sbase + OFF_PB2;

    const dim3 blk(256);
    const int NT = NPIX / 64;            // 600 pixel tiles
    const int PW256 = 2 * 128 * HW / 256;

    setup_bins_kernel<<<(NPIX + 255) / 256, 256>>>();
    copy_ctx_kernel<<<(2 * 192 * HW) / 256, 256>>>(context);
    copy_h_kernel<<<PW256, 256>>>(gruh);

    // weight reorder + bf16 split
    auto SW = [&](const float* w, long off, int rows, int vrows, int cin, int khw) {
        const long n = (long)rows * cin * khw;
        split_w_kernel<<<(int)((n + 255) / 256), 256>>>(w, off, rows, vrows, cin, khw);
    };
    SW(e1w, W_E1, 128, 128, 16, 49);
    SW(e2w, W_E2, 128, 128, 128, 9);
    SW(e3w, W_E3, 128, 128, 128, 9);
    SW(e4w, W_E4, 256, 256, 128, 9);
    SW(z1w, W_ZR1,           128, 128, 576, 5);
    SW(r1w, W_ZR1 + 368640,  128, 128, 576, 5);
    SW(q1w, W_Q1, 128, 128, 576, 5);
    SW(z2w, W_ZR2,           128, 128, 576, 5);
    SW(r2w, W_ZR2 + 368640,  128, 128, 576, 5);
    SW(q2w, W_Q2, 128, 128, 576, 5);
    SW(p1w, W_P1, 128, 128, 128, 9);
    SW(p2w, W_P2, 128, 16, 128, 9);     // COUT padded 16 -> 128
    pad_bias_kernel<<<1, 128>>>(p2b);

    for (int it = 0; it < 6; ++it) {
        // encoder (encd4 writes straight into hx x-slot)
        conv_mma<16, 128, 7, 7, 3, 3, ACT_RELU><<<dim3(NT, 1), blk>>>(
            OFF_CD, 16 * HW, W_E1, e1b, e1b, OFF_E1, 128 * HW);
        conv_mma<128, 128, 3, 3, 1, 1, ACT_RELU><<<dim3(NT, 1), blk>>>(
            OFF_E1, 128 * HW, W_E2, e2b, e2b, OFF_E2, 128 * HW);
        conv_mma<128, 128, 3, 3, 1, 1, ACT_RELU><<<dim3(NT, 1), blk>>>(
            OFF_E2, 128 * HW, W_E3, e3b, e3b, OFF_E1, 128 * HW);
        conv_mma<128, 256, 3, 3, 1, 1, ACT_RELU><<<dim3(NT, 2), blk>>>(
            OFF_E1, 128 * HW, W_E4, e4b, e4b + 128, OFF_HX + 128L * HW, 576 * HW);

        // GRU horizontal (1,5): fused z|r, then q
        conv_mma<576, 256, 1, 5, 0, 2, ACT_SIG><<<dim3(NT, 2), blk>>>(
            OFF_HX, 576 * HW, W_ZR1, z1b, r1b, OFF_ZR, 256 * HW);
        rh_kernel<<<PW256, 256>>>();
        conv_mma<576, 128, 1, 5, 0, 2, ACT_TANH><<<dim3(NT, 1), blk>>>(
            OFF_HX, 576 * HW, W_Q1, q1b, q1b, OFF_Q, 128 * HW);
        gru_update_kernel<<<PW256, 256>>>();

        // GRU vertical (5,1)
        conv_mma<576, 256, 5, 1, 2, 0, ACT_SIG><<<dim3(NT, 2), blk>>>(
            OFF_HX, 576 * HW, W_ZR2, z2b, r2b, OFF_ZR, 256 * HW);
        rh_kernel<<<PW256, 256>>>();
        conv_mma<576, 128, 5, 1, 2, 0, ACT_TANH><<<dim3(NT, 1), blk>>>(
            OFF_HX, 576 * HW, W_Q2, q2b, q2b, OFF_Q, 128 * HW);
        gru_update_kernel<<<PW256, 256>>>();

        // PHead (ph2 padded to 128 out-channels, logits into E2)
        conv_mma<128, 128, 3, 3, 1, 1, ACT_RELU><<<dim3(NT, 1), blk>>>(
            OFF_H, 128 * HW, W_P1, p1b, p1b, OFF_E1, 128 * HW);
        conv_mma<128, 128, 3, 3, 1, 1, ACT_NONE><<<dim3(NT, 1), blk>>>(
            OFF_E1, 128 * HW, W_P2, pb2, pb2, OFF_E2, 128 * HW);

        bins_kernel<<<(NPIX + 127) / 128, 128>>>(out, it);
    }
}

// round 9
// speedup vs baseline: 1.8592x; 1.1012x over previous
#include <cuda_runtime.h>
#include <cuda_bf16.h>
#include <math.h>
#include <stdint.h>

// ---------------------------------------------------------------------------
// IEBINS — B=2, H=120, W=160, HD=128, CD=192, BN=16, 6 iters
// mma.sync bf16 (3-term split) implicit-GEMM convs, ldmatrix + BM128xBN128.
// ---------------------------------------------------------------------------

#define H_   120
#define W_   160
#define HW   19200
#define NPIX 38400

enum { ACT_NONE = 0, ACT_RELU = 1, ACT_SIG = 2, ACT_TANH = 3 };

// ------------------------- float scratch arena -----------------------------
constexpr long OFF_EDGES = 0;
constexpr long OFF_CD    = 652800;
constexpr long OFF_E1    = 1267200;
constexpr long OFF_E2    = 6182400;    // also 128-ch padded logits
constexpr long OFF_HX    = 11097600;   // [b][576][HW]: h | d | ctx
constexpr long OFF_H     = 33216000;
constexpr long OFF_ZR    = 38131200;   // [b][256][HW]: z | r
constexpr long OFF_Q     = 47961600;
constexpr long OFF_PB2   = 52876800;   // padded ph2 bias (128)
constexpr long SCRATCH_TOTAL = OFF_PB2 + 128;

__device__ __align__(1024) float g_scratch[SCRATCH_TOTAL];

// ------------------------- bf16 split-weight arena -------------------------
// layout per conv: [COUT(padded)][KH*KW][CIN] (reordered, bf16 hi / lo)
constexpr long W_E1  = 0;         // 128*784
constexpr long W_E2  = 100352;    // 147456
constexpr long W_E3  = 247808;    // 147456
constexpr long W_E4  = 395264;    // 294912
constexpr long W_ZR1 = 690176;    // 737280 (z rows 0..127 | r rows 128..255)
constexpr long W_Q1  = 1427456;   // 368640
constexpr long W_ZR2 = 1796096;   // 737280
constexpr long W_Q2  = 2533376;   // 368640
constexpr long W_P1  = 2902016;   // 147456
constexpr long W_P2  = 3049472;   // 147456 (COUT padded 16->128)
constexpr long W_TOT = 3196928;

__device__ __align__(16) __nv_bfloat16 g_whi[W_TOT];
__device__ __align__(16) __nv_bfloat16 g_wlo[W_TOT];

// ------------------------- helpers -----------------------------------------
template <int ACT>
__device__ __forceinline__ float epi(float v) {
    if (ACT == ACT_RELU) return fmaxf(v, 0.0f);
    if (ACT == ACT_SIG)  return 1.0f / (1.0f + expf(-v));
    if (ACT == ACT_TANH) return tanhf(v);
    return v;
}

__device__ __forceinline__ void mma16816(float* c, const uint32_t* a, const uint32_t* b) {
    asm volatile(
        "mma.sync.aligned.m16n8k16.row.col.f32.bf16.bf16.f32 "
        "{%0,%1,%2,%3}, {%4,%5,%6,%7}, {%8,%9}, {%0,%1,%2,%3};\n"
        : "+f"(c[0]), "+f"(c[1]), "+f"(c[2]), "+f"(c[3])
        : "r"(a[0]), "r"(a[1]), "r"(a[2]), "r"(a[3]), "r"(b[0]), "r"(b[1]));
}
__device__ __forceinline__ void ldsm4(uint32_t& r0, uint32_t& r1, uint32_t& r2,
                                      uint32_t& r3, uint32_t a) {
    asm volatile("ldmatrix.sync.aligned.m8n8.x4.shared.b16 {%0,%1,%2,%3}, [%4];"
                 : "=r"(r0), "=r"(r1), "=r"(r2), "=r"(r3) : "r"(a));
}
__device__ __forceinline__ uint32_t smem_u32(const void* p) {
    uint32_t a;
    asm("{ .reg .u64 t; cvta.to.shared.u64 t, %1; cvt.u32.u64 %0, t; }"
        : "=r"(a) : "l"(p));
    return a;
}
__device__ __forceinline__ uint32_t bf16_pack2(float f0, float f1) {
    __nv_bfloat16 b0 = __float2bfloat16_rn(f0);
    __nv_bfloat16 b1 = __float2bfloat16_rn(f1);
    return (uint32_t)*reinterpret_cast<unsigned short*>(&b0)
         | ((uint32_t)*reinterpret_cast<unsigned short*>(&b1) << 16);
}
__device__ __forceinline__ float bf16_hi(float f) {
    return __bfloat162float(__float2bfloat16_rn(f));
}

// ===========================================================================
// mma.sync bf16 implicit-GEMM conv, ldmatrix fragments.
// GEMM: M = COUT (128/blockIdx.y), N = 128 pixels, K in 16-chunks
// (pos outer x 16 input channels inner). 8 warps = 2(m) x 4(n);
// warp tile 64x32 = 4x4 m16n8k16 frags; 3-term bf16 split (AhBh+AhBl+AlBh).
// smem rows stride 48B -> conflict-free ldmatrix/STS.
// ===========================================================================
template <int CIN, int COUT, int KH, int KW, int PH, int PW, int ACT>
__global__ __launch_bounds__(256, 1)
void conv_mma(long in_off, int in_bs, long w_off,
              const float* __restrict__ bias0, const float* __restrict__ bias1,
              long out_off, int out_bs)
{
    constexpr int KTOT  = CIN * KH * KW;
    constexpr int CPC   = CIN / 16;
    constexpr int NITER = KTOT / 16;
    static_assert(CIN % 16 == 0, "CIN must be multiple of 16");

    // stage = Ahi[128*48] Alo Bhi Blo = 24576B; double buffered = 48KB
    constexpr int STAGE = 24576;
    __shared__ __align__(128) char smem[2 * STAGE];
    const uint32_t sbase = smem_u32(smem);

    const int tid  = threadIdx.x;
    const int lane = tid & 31;
    const int wid  = tid >> 5;
    const int warp_m = wid >> 2;           // 0..1 (64 rows each)
    const int warp_n = wid & 3;            // 0..3 (32 cols each)
    const int g    = lane >> 2;
    const int tg   = lane & 3;
    const int lrow = lane & 15;
    const int lcol = lane >> 4;            // 0,1 -> k-half (16B)

    const int n0 = blockIdx.x << 7;        // 128-pixel tile (128 | HW)
    const int m0 = blockIdx.y << 7;
    const int bb = n0 / HW;
    const int hw0 = n0 - bb * HW;
    const float* inb = g_scratch + in_off + (long)bb * in_bs;

    // ---- A loader: row = tid&127, sel hi/lo = tid>>7; 32B per iter ----
    const int arow = tid & 127;
    const int asel = tid >> 7;
    const __nv_bfloat16* wbase =
        (asel ? g_wlo : g_whi) + w_off + (long)(m0 + arow) * KTOT;
    const uint32_t aStsOff = asel * 6144 + arow * 48;

    // ---- B loader: pixel = tid&127, k-half = tid>>7; 8 ci values ----
    const int pixl  = tid & 127;
    const int khalf = tid >> 7;
    const int hwp = hw0 + pixl;
    const int py  = hwp / W_;
    const int px  = hwp - py * W_;
    const uint32_t bStsOff = 12288 + pixl * 48 + khalf * 16;

    // ---- ldmatrix base offsets (within a stage) ----
    const uint32_t aLdOff = (warp_m * 64 + lrow) * 48 + lcol * 16;
    const uint32_t bLdOff = 12288 + (warp_n * 32 + lrow) * 48 + lcol * 16;

    float acc[4][4][4];
#pragma unroll
    for (int mt = 0; mt < 4; mt++)
#pragma unroll
        for (int nt = 0; nt < 4; nt++)
#pragma unroll
            for (int e = 0; e < 4; e++) acc[mt][nt][e] = 0.0f;

    uint4 pa0, pa1;
    float pbv[8];

    auto ldg = [&](int it) {
        const uint4* ap = reinterpret_cast<const uint4*>(wbase + it * 16);
        pa0 = ap[0];
        pa1 = ap[1];
        const int pos = it / CPC;
        const int cic = it - pos * CPC;
        const int ky  = pos / KW;
        const int kx  = pos - ky * KW;
        const int iy  = py + ky - PH;
        const int ix  = px + kx - PW;
        const bool ok = ((unsigned)iy < (unsigned)H_) && ((unsigned)ix < (unsigned)W_);
        const float* src = inb + (long)(cic * 16 + khalf * 8) * HW + iy * W_ + ix;
#pragma unroll
        for (int j = 0; j < 8; j++)
            pbv[j] = ok ? __ldg(src + j * HW) : 0.0f;
    };

    ldg(0);
    uint32_t bufoff = 0;
#pragma unroll 1
    for (int it = 0; it < NITER; ++it) {
        // ---- STS prefetched A (bf16) + split B fp32 -> hi/lo ----
        {
            char* adst = smem + bufoff + aStsOff;
            *reinterpret_cast<uint4*>(adst)      = pa0;
            *reinterpret_cast<uint4*>(adst + 16) = pa1;

            uint4 hv, lv;
            float h0 = bf16_hi(pbv[0]), h1 = bf16_hi(pbv[1]);
            float h2 = bf16_hi(pbv[2]), h3 = bf16_hi(pbv[3]);
            float h4 = bf16_hi(pbv[4]), h5 = bf16_hi(pbv[5]);
            float h6 = bf16_hi(pbv[6]), h7 = bf16_hi(pbv[7]);
            hv.x = bf16_pack2(h0, h1); hv.y = bf16_pack2(h2, h3);
            hv.z = bf16_pack2(h4, h5); hv.w = bf16_pack2(h6, h7);
            lv.x = bf16_pack2(pbv[0] - h0, pbv[1] - h1);
            lv.y = bf16_pack2(pbv[2] - h2, pbv[3] - h3);
            lv.z = bf16_pack2(pbv[4] - h4, pbv[5] - h5);
            lv.w = bf16_pack2(pbv[6] - h6, pbv[7] - h7);
            char* bdst = smem + bufoff + bStsOff;
            *reinterpret_cast<uint4*>(bdst)        = hv;
            *reinterpret_cast<uint4*>(bdst + 6144) = lv;
        }
        __syncthreads();
        if (it + 1 < NITER) ldg(it + 1);   // overlaps MMA

        const uint32_t base = sbase + bufoff;
        uint32_t ah[4][4], al[4][4];
#pragma unroll
        for (int mt = 0; mt < 4; mt++) {
            const uint32_t aa = base + aLdOff + mt * 768;   // 16 rows * 48B
            ldsm4(ah[mt][0], ah[mt][1], ah[mt][2], ah[mt][3], aa);
            ldsm4(al[mt][0], al[mt][1], al[mt][2], al[mt][3], aa + 6144);
        }
#pragma unroll
        for (int p = 0; p < 2; p++) {
            uint32_t bh[4], bl[4];
            const uint32_t ba = base + bLdOff + p * 768;
            ldsm4(bh[0], bh[1], bh[2], bh[3], ba);
            ldsm4(bl[0], bl[1], bl[2], bl[3], ba + 6144);
#pragma unroll
            for (int f = 0; f < 2; f++) {
                uint32_t bhf[2] = { bh[f], bh[f + 2] };
                uint32_t blf[2] = { bl[f], bl[f + 2] };
                const int nt = p * 2 + f;
#pragma unroll
                for (int mt = 0; mt < 4; mt++) {
                    mma16816(acc[mt][nt], ah[mt], bhf);
                    mma16816(acc[mt][nt], ah[mt], blf);
                    mma16816(acc[mt][nt], al[mt], bhf);
                }
            }
        }
        bufoff ^= STAGE;
    }

    // ---- epilogue: direct float2 stores (bias + activation fused) ----
    const float* bias = (blockIdx.y == 0) ? bias0 : bias1;
#pragma unroll
    for (int mt = 0; mt < 4; mt++) {
        const int r0 = warp_m * 64 + mt * 16 + g;
        const float bv0 = __ldg(bias + r0);
        const float bv1 = __ldg(bias + r0 + 8);
        float* orow0 = g_scratch + out_off + (long)bb * out_bs
                     + (long)(m0 + r0) * HW + hw0;
        float* orow1 = orow0 + 8L * HW;
#pragma unroll
        for (int nt = 0; nt < 4; nt++) {
            const int c = warp_n * 32 + nt * 8 + 2 * tg;
            float2 o0, o1;
            o0.x = epi<ACT>(acc[mt][nt][0] + bv0);
            o0.y = epi<ACT>(acc[mt][nt][1] + bv0);
            o1.x = epi<ACT>(acc[mt][nt][2] + bv1);
            o1.y = epi<ACT>(acc[mt][nt][3] + bv1);
            *reinterpret_cast<float2*>(orow0 + c) = o0;
            *reinterpret_cast<float2*>(orow1 + c) = o1;
        }
    }
}

// ------------------------- setup / pointwise kernels -----------------------
__global__ void split_w_kernel(const float* __restrict__ w, long off,
                               int rows, int vrows, int cin, int khw) {
    const int ktot = cin * khw;
    const long n = (long)rows * ktot;
    const long i = (long)blockIdx.x * blockDim.x + threadIdx.x;
    if (i >= n) return;
    const int co  = (int)(i / ktot);
    const int rem = (int)(i - (long)co * ktot);
    const int pos = rem / cin;
    const int ci  = rem - pos * cin;
    float x = 0.0f;
    if (co < vrows) x = w[(long)co * ktot + (long)ci * khw + pos];
    __nv_bfloat16 h = __float2bfloat16_rn(x);
    g_whi[off + i] = h;
    g_wlo[off + i] = __float2bfloat16_rn(x - __bfloat162float(h));
}
__global__ void pad_bias_kernel(const float* __restrict__ b) {
    const int i = threadIdx.x;
    g_scratch[OFF_PB2 + i] = (i < 16) ? b[i] : 0.0f;
}
__global__ void setup_bins_kernel() {
    const int p = blockIdx.x * blockDim.x + threadIdx.x;
    if (p >= NPIX) return;
    const int b = p / HW, hw = p - b * HW;
    float* ed = g_scratch + OFF_EDGES + (long)b * 17 * HW + hw;
    float* cd = g_scratch + OFF_CD    + (long)b * 16 * HW + hw;
#pragma unroll
    for (int j = 0; j < 17; j++) ed[j * HW] = 5.0f * j;
#pragma unroll
    for (int i = 0; i < 16; i++) cd[i * HW] = 2.5f + 5.0f * i;
}
__global__ void copy_ctx_kernel(const float* __restrict__ ctx) {
    const long i = (long)blockIdx.x * blockDim.x + threadIdx.x;
    if (i >= 2L * 192 * HW) return;
    const long b = i / (192L * HW);
    const long rem = i - b * (192L * HW);
    g_scratch[OFF_HX + b * 576L * HW + 384L * HW + rem] = ctx[i];
}
__global__ void copy_h_kernel(const float* __restrict__ h0) {
    const long i = (long)blockIdx.x * blockDim.x + threadIdx.x;
    if (i >= 2L * 128 * HW) return;
    const long b = i / (128L * HW);
    const long rem = i - b * (128L * HW);
    const float v = h0[i];
    g_scratch[OFF_H + i] = v;
    g_scratch[OFF_HX + b * 576L * HW + rem] = v;
}
__global__ void rh_kernel() {
    const long i = (long)blockIdx.x * blockDim.x + threadIdx.x;
    const long b = i / (128L * HW);
    const long rem = i - b * (128L * HW);
    const float r = g_scratch[OFF_ZR + b * 256L * HW + 128L * HW + rem];
    g_scratch[OFF_HX + b * 576L * HW + rem] = r * g_scratch[OFF_H + i];
}
__global__ void gru_update_kernel() {
    const long i = (long)blockIdx.x * blockDim.x + threadIdx.x;
    const long b = i / (128L * HW);
    const long rem = i - b * (128L * HW);
    const float z = g_scratch[OFF_ZR + b * 256L * HW + rem];
    const float q = g_scratch[OFF_Q + i];
    const float h = g_scratch[OFF_H + i];
    const float hn = (1.0f - z) * h + z * q;
    g_scratch[OFF_H + i] = hn;
    g_scratch[OFF_HX + b * 576L * HW + rem] = hn;
}
__global__ void bins_kernel(float* __restrict__ out, int it) {
    const int p = blockIdx.x * blockDim.x + threadIdx.x;
    if (p >= NPIX) return;
    const int b = p / HW, hw = p - b * HW;
    const float* lg  = g_scratch + OFF_E2    + (long)b * 128 * HW + hw;
    float*       cdp = g_scratch + OFF_CD    + (long)b * 16 * HW + hw;
    float*       edp = g_scratch + OFF_EDGES + (long)b * 17 * HW + hw;

    float l[16], cd[16];
    float m = -1e30f;
#pragma unroll
    for (int i = 0; i < 16; i++) { l[i] = lg[i * HW]; m = fmaxf(m, l[i]); }
    float s = 0.0f;
#pragma unroll
    for (int i = 0; i < 16; i++) { l[i] = expf(l[i] - m); s += l[i]; }
    const float inv = 1.0f / s;
    float dr = 0.0f;
#pragma unroll
    for (int i = 0; i < 16; i++) { cd[i] = cdp[i * HW]; dr += l[i] * cd[i]; }
    dr *= inv;
    float var = 0.0f;
#pragma unroll
    for (int i = 0; i < 16; i++) { const float d = cd[i] - dr; var += l[i] * d * d; }
    var *= inv;
    const float unc = sqrtf(var);

    out[(0 * 6 + it) * NPIX + p] = dr;
    out[(2 * 6 + it) * NPIX + p] = unc;

    int cnt = 0;
#pragma unroll
    for (int j = 1; j <= 15; j++) cnt += (dr >= edp[j * HW]) ? 1 : 0;
    const int label = (dr >= edp[16 * HW]) ? 0 : cnt;
    out[(1 * 6 + it) * NPIX + p] = cd[label];

    const float start = fmaxf(dr - 0.5f * unc, 0.0f);
    const float delta = unc * (1.0f / 16.0f);
    float cum = start;
    float eprev = fminf(fmaxf(cum, 0.0f), 80.0f);
    edp[0] = eprev;
#pragma unroll
    for (int i = 1; i <= 16; i++) {
        cum += delta;
        const float e = fminf(fmaxf(cum, 0.0f), 80.0f);
        edp[i * HW] = e;
        cdp[(i - 1) * HW] = 0.5f * (eprev + e);
        eprev = e;
    }
}

// ------------------------- launch ------------------------------------------
extern "C" void kernel_launch(void* const* d_in, const int* in_sizes, int n_in,
                              void* d_out, int out_size)
{
    (void)in_sizes; (void)n_in; (void)out_size;
    const float* context = (const float*)d_in[1];
    const float* gruh    = (const float*)d_in[2];
    const float* e1w = (const float*)d_in[3];  const float* e1b = (const float*)d_in[4];
    const float* e2w = (const float*)d_in[5];  const float* e2b = (const float*)d_in[6];
    const float* e3w = (const float*)d_in[7];  const float* e3b = (const float*)d_in[8];
    const float* e4w = (const float*)d_in[9];  const float* e4b = (const float*)d_in[10];
    const float* z1w = (const float*)d_in[11]; const float* z1b = (const float*)d_in[12];
    const float* r1w = (const float*)d_in[13]; const float* r1b = (const float*)d_in[14];
    const float* q1w = (const float*)d_in[15]; const float* q1b = (const float*)d_in[16];
    const float* z2w = (const float*)d_in[17]; const float* z2b = (const float*)d_in[18];
    const float* r2w = (const float*)d_in[19]; const float* r2b = (const float*)d_in[20];
    const float* q2w = (const float*)d_in[21]; const float* q2b = (const float*)d_in[22];
    const float* p1w = (const float*)d_in[23]; const float* p1b = (const float*)d_in[24];
    const float* p2w = (const float*)d_in[25]; const float* p2b = (const float*)d_in[26];
    float* out = (float*)d_out;

    float* sbase = nullptr;
    cudaGetSymbolAddress((void**)&sbase, g_scratch);
    const float* pb2 = sbase + OFF_PB2;

    const dim3 blk(256);
    const int NT = NPIX / 128;           // 300 pixel tiles
    const int PW256 = 2 * 128 * HW / 256;

    setup_bins_kernel<<<(NPIX + 255) / 256, 256>>>();
    copy_ctx_kernel<<<(2 * 192 * HW) / 256, 256>>>(context);
    copy_h_kernel<<<PW256, 256>>>(gruh);

    auto SW = [&](const float* w, long off, int rows, int vrows, int cin, int khw) {
        const long n = (long)rows * cin * khw;
        split_w_kernel<<<(int)((n + 255) / 256), 256>>>(w, off, rows, vrows, cin, khw);
    };
    SW(e1w, W_E1, 128, 128, 16, 49);
    SW(e2w, W_E2, 128, 128, 128, 9);
    SW(e3w, W_E3, 128, 128, 128, 9);
    SW(e4w, W_E4, 256, 256, 128, 9);
    SW(z1w, W_ZR1,           128, 128, 576, 5);
    SW(r1w, W_ZR1 + 368640,  128, 128, 576, 5);
    SW(q1w, W_Q1, 128, 128, 576, 5);
    SW(z2w, W_ZR2,           128, 128, 576, 5);
    SW(r2w, W_ZR2 + 368640,  128, 128, 576, 5);
    SW(q2w, W_Q2, 128, 128, 576, 5);
    SW(p1w, W_P1, 128, 128, 128, 9);
    SW(p2w, W_P2, 128, 16, 128, 9);
    pad_bias_kernel<<<1, 128>>>(p2b);

    for (int it = 0; it < 6; ++it) {
        // encoder (encd4 writes straight into hx x-slot)
        conv_mma<16, 128, 7, 7, 3, 3, ACT_RELU><<<dim3(NT, 1), blk>>>(
            OFF_CD, 16 * HW, W_E1, e1b, e1b, OFF_E1, 128 * HW);
        conv_mma<128, 128, 3, 3, 1, 1, ACT_RELU><<<dim3(NT, 1), blk>>>(
            OFF_E1, 128 * HW, W_E2, e2b, e2b, OFF_E2, 128 * HW);
        conv_mma<128, 128, 3, 3, 1, 1, ACT_RELU><<<dim3(NT, 1), blk>>>(
            OFF_E2, 128 * HW, W_E3, e3b, e3b, OFF_E1, 128 * HW);
        conv_mma<128, 256, 3, 3, 1, 1, ACT_RELU><<<dim3(NT, 2), blk>>>(
            OFF_E1, 128 * HW, W_E4, e4b, e4b + 128, OFF_HX + 128L * HW, 576 * HW);

        // GRU horizontal (1,5): fused z|r, then q
        conv_mma<576, 256, 1, 5, 0, 2, ACT_SIG><<<dim3(NT, 2), blk>>>(
            OFF_HX, 576 * HW, W_ZR1, z1b, r1b, OFF_ZR, 256 * HW);
        rh_kernel<<<PW256, 256>>>();
        conv_mma<576, 128, 1, 5, 0, 2, ACT_TANH><<<dim3(NT, 1), blk>>>(
            OFF_HX, 576 * HW, W_Q1, q1b, q1b, OFF_Q, 128 * HW);
        gru_update_kernel<<<PW256, 256>>>();

        // GRU vertical (5,1)
        conv_mma<576, 256, 5, 1, 2, 0, ACT_SIG><<<dim3(NT, 2), blk>>>(
            OFF_HX, 576 * HW, W_ZR2, z2b, r2b, OFF_ZR, 256 * HW);
        rh_kernel<<<PW256, 256>>>();
        conv_mma<576, 128, 5, 1, 2, 0, ACT_TANH><<<dim3(NT, 1), blk>>>(
            OFF_HX, 576 * HW, W_Q2, q2b, q2b, OFF_Q, 128 * HW);
        gru_update_kernel<<<PW256, 256>>>();

        // PHead (ph2 padded to 128 out-channels, logits into E2)
        conv_mma<128, 128, 3, 3, 1, 1, ACT_RELU><<<dim3(NT, 1), blk>>>(
            OFF_H, 128 * HW, W_P1, p1b, p1b, OFF_E1, 128 * HW);
        conv_mma<128, 128, 3, 3, 1, 1, ACT_NONE><<<dim3(NT, 1), blk>>>(
            OFF_E1, 128 * HW, W_P2, pb2, pb2, OFF_E2, 128 * HW);

        bins_kernel<<<(NPIX + 127) / 128, 128>>>(out, it);
    }
}

// round 10
// speedup vs baseline: 1.9357x; 1.0411x over previous
#include <cuda_runtime.h>
#include <cuda_bf16.h>
#include <math.h>
#include <stdint.h>

// ---------------------------------------------------------------------------
// IEBINS — B=2, H=120, W=160, HD=128, CD=192, BN=16, 6 iters
// mma.sync bf16 (3-term split) implicit-GEMM convs.
// Activations stored PRE-SPLIT as packed bf16x2 (lo16=hi, hi16=lo) in
// [pixel][channel] layout -> mainloop B path = 2 LDG.128 + 8 PRMT.
// ---------------------------------------------------------------------------

#define H_   120
#define W_   160
#define HW   19200
#define NPIX 38400

enum { ACT_NONE = 0, ACT_RELU = 1, ACT_SIG = 2, ACT_TANH = 3 };

// ------------------------- scratch arena (4B elements) ---------------------
// packed arenas are [global_pixel][channels]; edges/h are fp32.
constexpr long OFF_EDGES = 0;          // fp32 [2][17][HW]
constexpr long OFF_CD    = 652800;     // u32  [NPIX][16]
constexpr long OFF_E1    = 1267200;    // u32  [NPIX][128]
constexpr long OFF_E2    = 6182400;    // u32  [NPIX][128] (also padded logits)
constexpr long OFF_HX    = 11097600;   // u32  [NPIX][576]: h | d | ctx
constexpr long OFF_H     = 33216000;   // fp32 [NPIX][128] (GRU state)
constexpr long OFF_ZR    = 38131200;   // u32  [NPIX][256]: z | r
constexpr long OFF_Q     = 47961600;   // u32  [NPIX][128]
constexpr long OFF_PB2   = 52876800;   // fp32 padded ph2 bias (128)
constexpr long SCRATCH_TOTAL = OFF_PB2 + 128;

__device__ __align__(1024) float g_scratch[SCRATCH_TOTAL];

// ------------------------- bf16 split-weight arena -------------------------
// layout per conv: [COUT(padded)][KH*KW][CIN] (reordered, bf16 hi / lo)
constexpr long W_E1  = 0;         // 128*784
constexpr long W_E2  = 100352;    // 147456
constexpr long W_E3  = 247808;    // 147456
constexpr long W_E4  = 395264;    // 294912
constexpr long W_ZR1 = 690176;    // 737280 (z rows 0..127 | r rows 128..255)
constexpr long W_Q1  = 1427456;   // 368640
constexpr long W_ZR2 = 1796096;   // 737280
constexpr long W_Q2  = 2533376;   // 368640
constexpr long W_P1  = 2902016;   // 147456
constexpr long W_P2  = 3049472;   // 147456 (COUT padded 16->128)
constexpr long W_TOT = 3196928;

__device__ __align__(16) __nv_bfloat16 g_whi[W_TOT];
__device__ __align__(16) __nv_bfloat16 g_wlo[W_TOT];

// ------------------------- helpers -----------------------------------------
template <int ACT>
__device__ __forceinline__ float epi(float v) {
    if (ACT == ACT_RELU) return fmaxf(v, 0.0f);
    if (ACT == ACT_SIG)  return 1.0f / (1.0f + expf(-v));
    if (ACT == ACT_TANH) return tanhf(v);
    return v;
}
__device__ __forceinline__ void mma16816(float* c, const uint32_t* a, const uint32_t* b) {
    asm volatile(
        "mma.sync.aligned.m16n8k16.row.col.f32.bf16.bf16.f32 "
        "{%0,%1,%2,%3}, {%4,%5,%6,%7}, {%8,%9}, {%0,%1,%2,%3};\n"
        : "+f"(c[0]), "+f"(c[1]), "+f"(c[2]), "+f"(c[3])
        : "r"(a[0]), "r"(a[1]), "r"(a[2]), "r"(a[3]), "r"(b[0]), "r"(b[1]));
}
__device__ __forceinline__ void ldsm4(uint32_t& r0, uint32_t& r1, uint32_t& r2,
                                      uint32_t& r3, uint32_t a) {
    asm volatile("ldmatrix.sync.aligned.m8n8.x4.shared.b16 {%0,%1,%2,%3}, [%4];"
                 : "=r"(r0), "=r"(r1), "=r"(r2), "=r"(r3) : "r"(a));
}
__device__ __forceinline__ uint32_t smem_u32(const void* p) {
    uint32_t a;
    asm("{ .reg .u64 t; cvta.to.shared.u64 t, %1; cvt.u32.u64 %0, t; }"
        : "=r"(a) : "l"(p));
    return a;
}
// pack fp32 -> (hi bf16 in low16, lo bf16 in high16)
__device__ __forceinline__ uint32_t packhl(float v) {
    __nv_bfloat16 h = __float2bfloat16_rn(v);
    float hf = __bfloat162float(h);
    __nv_bfloat16 l = __float2bfloat16_rn(v - hf);
    return (uint32_t)(*reinterpret_cast<unsigned short*>(&h))
         | ((uint32_t)(*reinterpret_cast<unsigned short*>(&l)) << 16);
}
__device__ __forceinline__ float unpk(uint32_t u) {
    unsigned short a = (unsigned short)(u & 0xFFFFu);
    unsigned short b = (unsigned short)(u >> 16);
    return __bfloat162float(*reinterpret_cast<__nv_bfloat16*>(&a))
         + __bfloat162float(*reinterpret_cast<__nv_bfloat16*>(&b));
}

// ===========================================================================
// mma.sync bf16 implicit-GEMM conv.
// GEMM: M = COUT (128/blockIdx.y), N = 128 pixels, K in 16-chunks
// (pos outer x 16 input channels inner). 8 warps = 2(m) x 4(n);
// warp tile 64x32 = 4x4 m16n8k16 frags; 3-term split (AhBh+AhBl+AlBh).
// Input: packed bf16x2 [pixel][in_cs], B loader = 2 LDG.128 + 8 PRMT.
// Output: packed bf16x2 [pixel][out_cs] via smem-staged epilogue.
// ===========================================================================
template <int CIN, int COUT, int KH, int KW, int PH, int PW, int ACT>
__global__ __launch_bounds__(256, 1)
void conv_mma(long in_off, int in_cs, int in_ch0, long w_off,
              const float* __restrict__ bias0, const float* __restrict__ bias1,
              long out_off, int out_cs, int out_ch0)
{
    constexpr int KTOT  = CIN * KH * KW;
    constexpr int CPC   = CIN / 16;
    constexpr int NITER = KTOT / 16;
    static_assert(CIN % 16 == 0, "CIN must be multiple of 16");

    constexpr int STAGE = 24576;       // Ahi[128*48] Alo Bhi Blo
    __shared__ __align__(128) char smem[2 * STAGE];
    const uint32_t sbase = smem_u32(smem);

    const int tid  = threadIdx.x;
    const int lane = tid & 31;
    const int wid  = tid >> 5;
    const int warp_m = wid >> 2;       // 0..1 (64 rows each)
    const int warp_n = wid & 3;        // 0..3 (32 cols each)
    const int g    = lane >> 2;
    const int tg   = lane & 3;
    const int lrow = lane & 15;
    const int lcol = lane >> 4;

    const int n0 = blockIdx.x << 7;    // global pixel tile base (128 | HW)
    const int m0 = blockIdx.y << 7;
    const int bb = n0 / HW;
    const int hw0 = n0 - bb * HW;
    const int pixbase = bb * HW;
    const uint32_t* inu =
        reinterpret_cast<const uint32_t*>(g_scratch) + in_off + in_ch0;

    // ---- A loader ----
    const int arow = tid & 127;
    const int asel = tid >> 7;
    const __nv_bfloat16* wbase =
        (asel ? g_wlo : g_whi) + w_off + (long)(m0 + arow) * KTOT;
    const uint32_t aStsOff = asel * 6144 + arow * 48;

    // ---- B loader: pixel = tid&127, k-half = tid>>7 ----
    const int pixl  = tid & 127;
    const int khalf = tid >> 7;
    const int hwp = hw0 + pixl;
    const int py  = hwp / W_;
    const int px  = hwp - py * W_;
    const uint32_t bStsOff = 12288 + pixl * 48 + khalf * 16;

    // ---- ldmatrix offsets ----
    const uint32_t aLdOff = (warp_m * 64 + lrow) * 48 + lcol * 16;
    const uint32_t bLdOff = 12288 + (warp_n * 32 + lrow) * 48 + lcol * 16;

    float acc[4][4][4];
#pragma unroll
    for (int mt = 0; mt < 4; mt++)
#pragma unroll
        for (int nt = 0; nt < 4; nt++)
#pragma unroll
            for (int e = 0; e < 4; e++) acc[mt][nt][e] = 0.0f;

    uint4 pa0, pa1, pw0, pw1;

    auto ldg = [&](int it) {
        const uint4* ap = reinterpret_cast<const uint4*>(wbase + it * 16);
        pa0 = ap[0];
        pa1 = ap[1];
        const int pos = it / CPC;
        const int cic = it - pos * CPC;
        const int ky  = pos / KW;
        const int kx  = pos - ky * KW;
        const int iy  = py + ky - PH;
        const int ix  = px + kx - PW;
        if (((unsigned)iy < (unsigned)H_) && ((unsigned)ix < (unsigned)W_)) {
            const uint32_t* src =
                inu + (long)(pixbase + iy * W_ + ix) * in_cs + cic * 16 + khalf * 8;
            pw0 = *reinterpret_cast<const uint4*>(src);
            pw1 = *reinterpret_cast<const uint4*>(src + 4);
        } else {
            pw0 = make_uint4(0, 0, 0, 0);
            pw1 = make_uint4(0, 0, 0, 0);
        }
    };

    ldg(0);
    uint32_t bufoff = 0;
#pragma unroll 1
    for (int it = 0; it < NITER; ++it) {
        // ---- STS prefetched A + PRMT-unpacked B hi/lo ----
        {
            char* adst = smem + bufoff + aStsOff;
            *reinterpret_cast<uint4*>(adst)      = pa0;
            *reinterpret_cast<uint4*>(adst + 16) = pa1;

            uint4 hv, lv;
            hv.x = __byte_perm(pw0.x, pw0.y, 0x5410);
            hv.y = __byte_perm(pw0.z, pw0.w, 0x5410);
            hv.z = __byte_perm(pw1.x, pw1.y, 0x5410);
            hv.w = __byte_perm(pw1.z, pw1.w, 0x5410);
            lv.x = __byte_perm(pw0.x, pw0.y, 0x7632);
            lv.y = __byte_perm(pw0.z, pw0.w, 0x7632);
            lv.z = __byte_perm(pw1.x, pw1.y, 0x7632);
            lv.w = __byte_perm(pw1.z, pw1.w, 0x7632);
            char* bdst = smem + bufoff + bStsOff;
            *reinterpret_cast<uint4*>(bdst)        = hv;
            *reinterpret_cast<uint4*>(bdst + 6144) = lv;
        }
        __syncthreads();
        if (it + 1 < NITER) ldg(it + 1);   // overlaps MMA

        const uint32_t base = sbase + bufoff;
        uint32_t ah[4][4], al[4][4];
#pragma unroll
        for (int mt = 0; mt < 4; mt++) {
            const uint32_t aa = base + aLdOff + mt * 768;
            ldsm4(ah[mt][0], ah[mt][1], ah[mt][2], ah[mt][3], aa);
            ldsm4(al[mt][0], al[mt][1], al[mt][2], al[mt][3], aa + 6144);
        }
#pragma unroll
        for (int p = 0; p < 2; p++) {
            uint32_t bh[4], bl[4];
            const uint32_t ba = base + bLdOff + p * 768;
            ldsm4(bh[0], bh[1], bh[2], bh[3], ba);
            ldsm4(bl[0], bl[1], bl[2], bl[3], ba + 6144);
#pragma unroll
            for (int f = 0; f < 2; f++) {
                uint32_t bhf[2] = { bh[f], bh[f + 2] };
                uint32_t blf[2] = { bl[f], bl[f + 2] };
                const int nt = p * 2 + f;
#pragma unroll
                for (int mt = 0; mt < 4; mt++) {
                    mma16816(acc[mt][nt], ah[mt], bhf);
                    mma16816(acc[mt][nt], ah[mt], blf);
                    mma16816(acc[mt][nt], al[mt], bhf);
                }
            }
        }
        bufoff ^= STAGE;
    }

    // ---- epilogue: bias + act + pack, smem-staged [pixel][ch] stores ----
    const float* bias = (blockIdx.y == 0) ? bias0 : bias1;
    uint32_t pk[4][4][4];
#pragma unroll
    for (int mt = 0; mt < 4; mt++) {
        const int r0 = warp_m * 64 + mt * 16 + g;
        const float bv0 = __ldg(bias + r0);
        const float bv1 = __ldg(bias + r0 + 8);
#pragma unroll
        for (int nt = 0; nt < 4; nt++) {
            pk[mt][nt][0] = packhl(epi<ACT>(acc[mt][nt][0] + bv0));
            pk[mt][nt][1] = packhl(epi<ACT>(acc[mt][nt][1] + bv0));
            pk[mt][nt][2] = packhl(epi<ACT>(acc[mt][nt][2] + bv1));
            pk[mt][nt][3] = packhl(epi<ACT>(acc[mt][nt][3] + bv1));
        }
    }
    uint32_t* st = reinterpret_cast<uint32_t*>(smem);
    uint32_t* outu = reinterpret_cast<uint32_t*>(g_scratch) + out_off + out_ch0 + m0;
    const int pix = tid & 63;
    const int q   = tid >> 6;
#pragma unroll 1
    for (int pass = 0; pass < 2; pass++) {
        __syncthreads();
        if ((warp_n >> 1) == pass) {
#pragma unroll
            for (int mt = 0; mt < 4; mt++) {
                const int r = warp_m * 64 + mt * 16 + g;
#pragma unroll
                for (int nt = 0; nt < 4; nt++) {
                    const int cloc = (warp_n & 1) * 32 + nt * 8 + 2 * tg;
                    st[cloc * 132 + r]           = pk[mt][nt][0];
                    st[(cloc + 1) * 132 + r]     = pk[mt][nt][1];
                    st[cloc * 132 + r + 8]       = pk[mt][nt][2];
                    st[(cloc + 1) * 132 + r + 8] = pk[mt][nt][3];
                }
            }
        }
        __syncthreads();
        uint32_t* orow = outu + (long)(n0 + pass * 64 + pix) * out_cs + q * 32;
#pragma unroll
        for (int j = 0; j < 8; j++) {
            uint4 v = *reinterpret_cast<uint4*>(&st[pix * 132 + q * 32 + j * 4]);
            *reinterpret_cast<uint4*>(orow + j * 4) = v;
        }
    }
}

// ------------------------- setup / pointwise kernels -----------------------
__global__ void split_w_kernel(const float* __restrict__ w, long off,
                               int rows, int vrows, int cin, int khw) {
    const int ktot = cin * khw;
    const long n = (long)rows * ktot;
    const long i = (long)blockIdx.x * blockDim.x + threadIdx.x;
    if (i >= n) return;
    const int co  = (int)(i / ktot);
    const int rem = (int)(i - (long)co * ktot);
    const int pos = rem / cin;
    const int ci  = rem - pos * cin;
    float x = 0.0f;
    if (co < vrows) x = w[(long)co * ktot + (long)ci * khw + pos];
    __nv_bfloat16 h = __float2bfloat16_rn(x);
    g_whi[off + i] = h;
    g_wlo[off + i] = __float2bfloat16_rn(x - __bfloat162float(h));
}
__global__ void pad_bias_kernel(const float* __restrict__ b) {
    const int i = threadIdx.x;
    g_scratch[OFF_PB2 + i] = (i < 16) ? b[i] : 0.0f;
}
__global__ void setup_bins_kernel() {
    const int p = blockIdx.x * blockDim.x + threadIdx.x;
    if (p >= NPIX) return;
    const int b = p / HW, hw = p - b * HW;
    float* ed = g_scratch + OFF_EDGES + (long)b * 17 * HW + hw;
#pragma unroll
    for (int j = 0; j < 17; j++) ed[j * HW] = 5.0f * j;
    uint32_t* cdp = reinterpret_cast<uint32_t*>(g_scratch) + OFF_CD + (long)p * 16;
#pragma unroll
    for (int i = 0; i < 16; i++) cdp[i] = packhl(2.5f + 5.0f * i);
}
// ctx [b][192][hw] fp32 -> hx [pixel][384+c] packed (smem transpose)
__global__ void copy_ctx_kernel(const float* __restrict__ ctx) {
    __shared__ float t[192 * 33];
    const int p0 = blockIdx.x * 32;
    const int b = p0 / HW;
    const int hw = p0 - b * HW;
    const float* src = ctx + (long)b * 192 * HW + hw;
    for (int k = threadIdx.x; k < 192 * 32; k += 256) {
        const int c = k >> 5, w = k & 31;
        t[c * 33 + w] = src[(long)c * HW + w];
    }
    __syncthreads();
    uint32_t* ga = reinterpret_cast<uint32_t*>(g_scratch);
    for (int k = threadIdx.x; k < 32 * 192; k += 256) {
        const int w = k / 192, c = k - w * 192;
        ga[OFF_HX + (long)(p0 + w) * 576 + 384 + c] = packhl(t[c * 33 + w]);
    }
}
// h0 [b][128][hw] fp32 -> OFF_H [pixel][128] fp32 + hx [pixel][0..127] packed
__global__ void copy_h_kernel(const float* __restrict__ h0) {
    __shared__ float t[128 * 33];
    const int p0 = blockIdx.x * 32;
    const int b = p0 / HW;
    const int hw = p0 - b * HW;
    const float* src = h0 + (long)b * 128 * HW + hw;
    for (int k = threadIdx.x; k < 128 * 32; k += 256) {
        const int c = k >> 5, w = k & 31;
        t[c * 33 + w] = src[(long)c * HW + w];
    }
    __syncthreads();
    uint32_t* ga = reinterpret_cast<uint32_t*>(g_scratch);
    for (int k = threadIdx.x; k < 32 * 128; k += 256) {
        const int w = k >> 7, c = k & 127;
        const float v = t[c * 33 + w];
        g_scratch[OFF_H + (long)(p0 + w) * 128 + c] = v;
        ga[OFF_HX + (long)(p0 + w) * 576 + c] = packhl(v);
    }
}
__global__ void rh_kernel() {
    const long i = (long)blockIdx.x * blockDim.x + threadIdx.x;
    const long p = i >> 7;
    const int c = (int)(i & 127);
    uint32_t* ga = reinterpret_cast<uint32_t*>(g_scratch);
    const float r = unpk(ga[OFF_ZR + p * 256 + 128 + c]);
    const float h = g_scratch[OFF_H + i];
    ga[OFF_HX + p * 576 + c] = packhl(r * h);
}
__global__ void gru_update_kernel() {
    const long i = (long)blockIdx.x * blockDim.x + threadIdx.x;
    const long p = i >> 7;
    const int c = (int)(i & 127);
    uint32_t* ga = reinterpret_cast<uint32_t*>(g_scratch);
    const float z = unpk(ga[OFF_ZR + p * 256 + c]);
    const float q = unpk(ga[OFF_Q + i]);
    const float h = g_scratch[OFF_H + i];
    const float hn = (1.0f - z) * h + z * q;
    g_scratch[OFF_H + i] = hn;
    ga[OFF_HX + p * 576 + c] = packhl(hn);
}
__global__ void bins_kernel(float* __restrict__ out, int it) {
    const int p = blockIdx.x * blockDim.x + threadIdx.x;
    if (p >= NPIX) return;
    const int b = p / HW, hw = p - b * HW;
    uint32_t* ga = reinterpret_cast<uint32_t*>(g_scratch);
    const uint32_t* lg = ga + OFF_E2 + (long)p * 128;
    uint32_t*      cdp = ga + OFF_CD + (long)p * 16;
    float*         edp = g_scratch + OFF_EDGES + (long)b * 17 * HW + hw;

    float l[16], cd[16];
    float m = -1e30f;
#pragma unroll
    for (int i = 0; i < 16; i++) { l[i] = unpk(lg[i]); m = fmaxf(m, l[i]); }
    float s = 0.0f;
#pragma unroll
    for (int i = 0; i < 16; i++) { l[i] = expf(l[i] - m); s += l[i]; }
    const float inv = 1.0f / s;
    float dr = 0.0f;
#pragma unroll
    for (int i = 0; i < 16; i++) { cd[i] = unpk(cdp[i]); dr += l[i] * cd[i]; }
    dr *= inv;
    float var = 0.0f;
#pragma unroll
    for (int i = 0; i < 16; i++) { const float d = cd[i] - dr; var += l[i] * d * d; }
    var *= inv;
    const float unc = sqrtf(var);

    out[(0 * 6 + it) * NPIX + p] = dr;
    out[(2 * 6 + it) * NPIX + p] = unc;

    int cnt = 0;
#pragma unroll
    for (int j = 1; j <= 15; j++) cnt += (dr >= edp[j * HW]) ? 1 : 0;
    const int label = (dr >= edp[16 * HW]) ? 0 : cnt;
    out[(1 * 6 + it) * NPIX + p] = cd[label];

    const float start = fmaxf(dr - 0.5f * unc, 0.0f);
    const float delta = unc * (1.0f / 16.0f);
    float cum = start;
    float eprev = fminf(fmaxf(cum, 0.0f), 80.0f);
    edp[0] = eprev;
#pragma unroll
    for (int i = 1; i <= 16; i++) {
        cum += delta;
        const float e = fminf(fmaxf(cum, 0.0f), 80.0f);
        edp[i * HW] = e;
        cdp[i - 1] = packhl(0.5f * (eprev + e));
        eprev = e;
    }
}

// ------------------------- launch ------------------------------------------
extern "C" void kernel_launch(void* const* d_in, const int* in_sizes, int n_in,
                              void* d_out, int out_size)
{
    (void)in_sizes; (void)n_in; (void)out_size;
    const float* context = (const float*)d_in[1];
    const float* gruh    = (const float*)d_in[2];
    const float* e1w = (const float*)d_in[3];  const float* e1b = (const float*)d_in[4];
    const float* e2w = (const float*)d_in[5];  const float* e2b = (const float*)d_in[6];
    const float* e3w = (const float*)d_in[7];  const float* e3b = (const float*)d_in[8];
    const float* e4w = (const float*)d_in[9];  const float* e4b = (const float*)d_in[10];
    const float* z1w = (const float*)d_in[11]; const float* z1b = (const float*)d_in[12];
    const float* r1w = (const float*)d_in[13]; const float* r1b = (const float*)d_in[14];
    const float* q1w = (const float*)d_in[15]; const float* q1b = (const float*)d_in[16];
    const float* z2w = (const float*)d_in[17]; const float* z2b = (const float*)d_in[18];
    const float* r2w = (const float*)d_in[19]; const float* r2b = (const float*)d_in[20];
    const float* q2w = (const float*)d_in[21]; const float* q2b = (const float*)d_in[22];
    const float* p1w = (const float*)d_in[23]; const float* p1b = (const float*)d_in[24];
    const float* p2w = (const float*)d_in[25]; const float* p2b = (const float*)d_in[26];
    float* out = (float*)d_out;

    float* sbase = nullptr;
    cudaGetSymbolAddress((void**)&sbase, g_scratch);
    const float* pb2 = sbase + OFF_PB2;

    const dim3 blk(256);
    const int NT = NPIX / 128;           // 300 pixel tiles
    const int PW256 = 2 * 128 * HW / 256;
    const int TB = NPIX / 32;            // 1200 transpose tiles

    setup_bins_kernel<<<(NPIX + 255) / 256, 256>>>();
    copy_ctx_kernel<<<TB, 256>>>(context);
    copy_h_kernel<<<TB, 256>>>(gruh);

    auto SW = [&](const float* w, long off, int rows, int vrows, int cin, int khw) {
        const long n = (long)rows * cin * khw;
        split_w_kernel<<<(int)((n + 255) / 256), 256>>>(w, off, rows, vrows, cin, khw);
    };
    SW(e1w, W_E1, 128, 128, 16, 49);
    SW(e2w, W_E2, 128, 128, 128, 9);
    SW(e3w, W_E3, 128, 128, 128, 9);
    SW(e4w, W_E4, 256, 256, 128, 9);
    SW(z1w, W_ZR1,           128, 128, 576, 5);
    SW(r1w, W_ZR1 + 368640,  128, 128, 576, 5);
    SW(q1w, W_Q1, 128, 128, 576, 5);
    SW(z2w, W_ZR2,           128, 128, 576, 5);
    SW(r2w, W_ZR2 + 368640,  128, 128, 576, 5);
    SW(q2w, W_Q2, 128, 128, 576, 5);
    SW(p1w, W_P1, 128, 128, 128, 9);
    SW(p2w, W_P2, 128, 16, 128, 9);
    pad_bias_kernel<<<1, 128>>>(p2b);

    for (int it = 0; it < 6; ++it) {
        // encoder (encd4 writes straight into hx x-slot)
        conv_mma<16, 128, 7, 7, 3, 3, ACT_RELU><<<dim3(NT, 1), blk>>>(
            OFF_CD, 16, 0, W_E1, e1b, e1b, OFF_E1, 128, 0);
        conv_mma<128, 128, 3, 3, 1, 1, ACT_RELU><<<dim3(NT, 1), blk>>>(
            OFF_E1, 128, 0, W_E2, e2b, e2b, OFF_E2, 128, 0);
        conv_mma<128, 128, 3, 3, 1, 1, ACT_RELU><<<dim3(NT, 1), blk>>>(
            OFF_E2, 128, 0, W_E3, e3b, e3b, OFF_E1, 128, 0);
        conv_mma<128, 256, 3, 3, 1, 1, ACT_RELU><<<dim3(NT, 2), blk>>>(
            OFF_E1, 128, 0, W_E4, e4b, e4b + 128, OFF_HX, 576, 128);

        // GRU horizontal (1,5): fused z|r, then q
        conv_mma<576, 256, 1, 5, 0, 2, ACT_SIG><<<dim3(NT, 2), blk>>>(
            OFF_HX, 576, 0, W_ZR1, z1b, r1b, OFF_ZR, 256, 0);
        rh_kernel<<<PW256, 256>>>();
        conv_mma<576, 128, 1, 5, 0, 2, ACT_TANH><<<dim3(NT, 1), blk>>>(
            OFF_HX, 576, 0, W_Q1, q1b, q1b, OFF_Q, 128, 0);
        gru_update_kernel<<<PW256, 256>>>();

        // GRU vertical (5,1)
        conv_mma<576, 256, 5, 1, 2, 0, ACT_SIG><<<dim3(NT, 2), blk>>>(
            OFF_HX, 576, 0, W_ZR2, z2b, r2b, OFF_ZR, 256, 0);
        rh_kernel<<<PW256, 256>>>();
        conv_mma<576, 128, 5, 1, 2, 0, ACT_TANH><<<dim3(NT, 1), blk>>>(
            OFF_HX, 576, 0, W_Q2, q2b, q2b, OFF_Q, 128, 0);
        gru_update_kernel<<<PW256, 256>>>();

        // PHead: ph1 reads the packed h slot of hx (stride 576, offset 0)
        conv_mma<128, 128, 3, 3, 1, 1, ACT_RELU><<<dim3(NT, 1), blk>>>(
            OFF_HX, 576, 0, W_P1, p1b, p1b, OFF_E1, 128, 0);
        conv_mma<128, 128, 3, 3, 1, 1, ACT_NONE><<<dim3(NT, 1), blk>>>(
            OFF_E1, 128, 0, W_P2, pb2, pb2, OFF_E2, 128, 0);

        bins_kernel<<<(NPIX + 127) / 128, 128>>>(out, it);
    }
}

// round 11
// speedup vs baseline: 2.0829x; 1.0760x over previous
#include <cuda_runtime.h>
#include <cuda_bf16.h>
#include <math.h>
#include <stdint.h>

// ---------------------------------------------------------------------------
// IEBINS — B=2, H=120, W=160, HD=128, CD=192, BN=16, 6 iters
// mma.sync bf16 (3-term split) implicit-GEMM convs.
// Activations in SEPARATE bf16 hi/lo arenas, [pixel][channel] layout.
// Mainloop: cp.async 3-stage pipeline (A + B straight to smem), ldmatrix,
// 48 HMMA/warp/iter. Epilogue emits both planes.
// ---------------------------------------------------------------------------

#define H_   120
#define W_   160
#define HW   19200
#define NPIX 38400

enum { ACT_NONE = 0, ACT_RELU = 1, ACT_SIG = 2, ACT_TANH = 3 };

// ------------------------- fp32 scratch ------------------------------------
constexpr long OFF_EDGES = 0;          // [2][17][HW]
constexpr long OFF_H     = 652800;     // [NPIX][128] GRU state
constexpr long OFF_PB2   = 5568000;    // padded ph2 bias (128)
constexpr long SCRATCH_TOTAL = OFF_PB2 + 128;
__device__ __align__(1024) float g_scratch[SCRATCH_TOTAL];

// ------------------------- bf16 activation arenas (hi / lo planes) ---------
constexpr long A_CD = 0;          // [NPIX][16]
constexpr long A_E1 = 614400;     // [NPIX][128]
constexpr long A_E2 = 5529600;    // [NPIX][128] (also padded logits)
constexpr long A_HX = 10444800;   // [NPIX][576]: h | d | ctx
constexpr long A_ZR = 32563200;   // [NPIX][256]: z | r
constexpr long A_Q  = 42393600;   // [NPIX][128]
constexpr long A_TOT = 47308800;
__device__ __align__(1024) __nv_bfloat16 g_acthi[A_TOT];
__device__ __align__(1024) __nv_bfloat16 g_actlo[A_TOT];

// ------------------------- bf16 split-weight arena -------------------------
// layout per conv: [COUT(padded)][KH*KW][CIN], hi / lo planes
constexpr long W_E1  = 0;         // 128*784
constexpr long W_E2  = 100352;    // 147456
constexpr long W_E3  = 247808;    // 147456
constexpr long W_E4  = 395264;    // 294912
constexpr long W_ZR1 = 690176;    // 737280 (z | r)
constexpr long W_Q1  = 1427456;   // 368640
constexpr long W_ZR2 = 1796096;   // 737280
constexpr long W_Q2  = 2533376;   // 368640
constexpr long W_P1  = 2902016;   // 147456
constexpr long W_P2  = 3049472;   // 147456 (COUT padded 16->128)
constexpr long W_TOT = 3196928;
__device__ __align__(16) __nv_bfloat16 g_whi[W_TOT];
__device__ __align__(16) __nv_bfloat16 g_wlo[W_TOT];

// ------------------------- helpers -----------------------------------------
template <int ACT>
__device__ __forceinline__ float epi(float v) {
    if (ACT == ACT_RELU) return fmaxf(v, 0.0f);
    if (ACT == ACT_SIG)  return 1.0f / (1.0f + expf(-v));
    if (ACT == ACT_TANH) return tanhf(v);
    return v;
}
__device__ __forceinline__ void mma16816(float* c, const uint32_t* a, const uint32_t* b) {
    asm volatile(
        "mma.sync.aligned.m16n8k16.row.col.f32.bf16.bf16.f32 "
        "{%0,%1,%2,%3}, {%4,%5,%6,%7}, {%8,%9}, {%0,%1,%2,%3};\n"
        : "+f"(c[0]), "+f"(c[1]), "+f"(c[2]), "+f"(c[3])
        : "r"(a[0]), "r"(a[1]), "r"(a[2]), "r"(a[3]), "r"(b[0]), "r"(b[1]));
}
__device__ __forceinline__ void ldsm4(uint32_t& r0, uint32_t& r1, uint32_t& r2,
                                      uint32_t& r3, uint32_t a) {
    asm volatile("ldmatrix.sync.aligned.m8n8.x4.shared.b16 {%0,%1,%2,%3}, [%4];"
                 : "=r"(r0), "=r"(r1), "=r"(r2), "=r"(r3) : "r"(a));
}
__device__ __forceinline__ uint32_t smem_u32(const void* p) {
    uint32_t a;
    asm("{ .reg .u64 t; cvta.to.shared.u64 t, %1; cvt.u32.u64 %0, t; }"
        : "=r"(a) : "l"(p));
    return a;
}
__device__ __forceinline__ void cpa16(uint32_t d, const void* s) {
    asm volatile("cp.async.cg.shared.global [%0], [%1], 16;"
                 :: "r"(d), "l"(s) : "memory");
}
__device__ __forceinline__ void cpa16z(uint32_t d, const void* s, int sz) {
    asm volatile("cp.async.cg.shared.global [%0], [%1], 16, %2;"
                 :: "r"(d), "l"(s), "r"(sz) : "memory");
}
#define CP_COMMIT() asm volatile("cp.async.commit_group;" ::: "memory")
#define CP_WAIT1()  asm volatile("cp.async.wait_group 1;" ::: "memory")

__device__ __forceinline__ uint32_t packhl(float v) {   // hi in low16, lo in high16
    __nv_bfloat16 h = __float2bfloat16_rn(v);
    __nv_bfloat16 l = __float2bfloat16_rn(v - __bfloat162float(h));
    return (uint32_t)(*reinterpret_cast<unsigned short*>(&h))
         | ((uint32_t)(*reinterpret_cast<unsigned short*>(&l)) << 16);
}
__device__ __forceinline__ void split2(float v, __nv_bfloat16& h, __nv_bfloat16& l) {
    h = __float2bfloat16_rn(v);
    l = __float2bfloat16_rn(v - __bfloat162float(h));
}
__device__ __forceinline__ float join2(__nv_bfloat16 h, __nv_bfloat16 l) {
    return __bfloat162float(h) + __bfloat162float(l);
}

// ===========================================================================
// mma.sync bf16 implicit-GEMM conv, cp.async 3-stage pipeline.
// GEMM: M = COUT (128/blockIdx.y), N = 128 pixels, K in 16-chunks
// (pos outer x 16 in-channels inner). 8 warps = 2(m) x 4(n);
// warp tile 64x32 = 4x4 m16n8k16; 3-term split (AhBh + AhBl + AlBh).
// Stage (24576B): Ahi[128*48] | Alo | Bhi | Blo; 3 stages dynamic smem.
// ===========================================================================
template <int CIN, int COUT, int KH, int KW, int PH, int PW, int ACT>
__global__ __launch_bounds__(256)
void conv_mma(long in_off, int in_cs, int in_ch0, long w_off,
              const float* __restrict__ bias0, const float* __restrict__ bias1,
              long out_off, int out_cs, int out_ch0)
{
    constexpr int KTOT  = CIN * KH * KW;
    constexpr int CPC   = CIN / 16;
    constexpr int NITER = KTOT / 16;
    constexpr int STAGE = 24576;
    static_assert(CIN % 16 == 0 && NITER >= 3, "bad K config");

    extern __shared__ __align__(128) char smem[];
    const uint32_t sbase = smem_u32(smem);

    const int tid  = threadIdx.x;
    const int lane = tid & 31;
    const int wid  = tid >> 5;
    const int warp_m = wid >> 2;
    const int warp_n = wid & 3;
    const int g    = lane >> 2;
    const int tg   = lane & 3;
    const int lrow = lane & 15;
    const int lcol = lane >> 4;

    const int n0 = blockIdx.x << 7;
    const int m0 = blockIdx.y << 7;
    const int bb = n0 / HW;
    const int pixbase = bb * HW;

    // ---- A loader: row = tid&127, plane = tid>>7 ----
    const int arow = tid & 127;
    const int asel = tid >> 7;
    const __nv_bfloat16* wbase =
        (asel ? g_wlo : g_whi) + w_off + (long)(m0 + arow) * KTOT;
    const uint32_t aStsOff = asel * 6144 + arow * 48;

    // ---- B loader: pixel = tid&127, plane = tid>>7 ----
    const int pixl   = tid & 127;
    const int bplane = tid >> 7;
    const int hwp = (n0 - pixbase) + pixl;
    const int py  = hwp / W_;
    const int px  = hwp - py * W_;
    const __nv_bfloat16* bsrc0 =
        (bplane ? g_actlo : g_acthi) + in_off + in_ch0;
    const uint32_t bStsOff = 12288 + bplane * 6144 + pixl * 48;

    // ---- ldmatrix offsets ----
    const uint32_t aLdOff = (warp_m * 64 + lrow) * 48 + lcol * 16;
    const uint32_t bLdOff = 12288 + (warp_n * 32 + lrow) * 48 + lcol * 16;

    float acc[4][4][4];
#pragma unroll
    for (int mt = 0; mt < 4; mt++)
#pragma unroll
        for (int nt = 0; nt < 4; nt++)
#pragma unroll
            for (int e = 0; e < 4; e++) acc[mt][nt][e] = 0.0f;

    auto issue = [&](int it, uint32_t soff) {
        // A: 32B of weights (always valid)
        const uint32_t ad = sbase + soff + aStsOff;
        const __nv_bfloat16* as = wbase + it * 16;
        cpa16(ad, as);
        cpa16(ad + 16, as + 8);
        // B: 32B of one activation plane, zero-filled OOB
        const int pos = it / CPC;
        const int cic = it - pos * CPC;
        const int ky  = pos / KW;
        const int kx  = pos - ky * KW;
        const int iy  = py + ky - PH;
        const int ix  = px + kx - PW;
        const bool ok = ((unsigned)iy < (unsigned)H_) && ((unsigned)ix < (unsigned)W_);
        const __nv_bfloat16* bs = ok
            ? bsrc0 + (long)(pixbase + iy * W_ + ix) * in_cs + cic * 16
            : bsrc0;
        const int sz = ok ? 16 : 0;
        const uint32_t bd = sbase + soff + bStsOff;
        cpa16z(bd, bs, sz);
        cpa16z(bd + 16, bs + 8, sz);
    };

    // ---- prologue: 2 stages in flight ----
    issue(0, 0);            CP_COMMIT();
    issue(1, STAGE);        CP_COMMIT();

    uint32_t cur = 0, nxt = 2 * STAGE;
#pragma unroll 1
    for (int it = 0; it < NITER; ++it) {
        CP_WAIT1();
        __syncthreads();
        if (it + 2 < NITER) issue(it + 2, nxt);
        CP_COMMIT();

        const uint32_t base = sbase + cur;
        uint32_t ah[4][4], al[4][4];
#pragma unroll
        for (int mt = 0; mt < 4; mt++) {
            const uint32_t aa = base + aLdOff + mt * 768;
            ldsm4(ah[mt][0], ah[mt][1], ah[mt][2], ah[mt][3], aa);
            ldsm4(al[mt][0], al[mt][1], al[mt][2], al[mt][3], aa + 6144);
        }
#pragma unroll
        for (int p = 0; p < 2; p++) {
            uint32_t bh[4], bl[4];
            const uint32_t ba = base + bLdOff + p * 768;
            ldsm4(bh[0], bh[1], bh[2], bh[3], ba);
            ldsm4(bl[0], bl[1], bl[2], bl[3], ba + 6144);
#pragma unroll
            for (int f = 0; f < 2; f++) {
                uint32_t bhf[2] = { bh[f], bh[f + 2] };
                uint32_t blf[2] = { bl[f], bl[f + 2] };
                const int nt = p * 2 + f;
#pragma unroll
                for (int mt = 0; mt < 4; mt++) {
                    mma16816(acc[mt][nt], ah[mt], bhf);
                    mma16816(acc[mt][nt], ah[mt], blf);
                    mma16816(acc[mt][nt], al[mt], bhf);
                }
            }
        }
        cur = (cur == 2 * STAGE) ? 0 : cur + STAGE;
        nxt = (nxt == 2 * STAGE) ? 0 : nxt + STAGE;
    }

    // ---- epilogue: bias + act + pack; smem-staged [pixel][ch] plane stores --
    const float* bias = (blockIdx.y == 0) ? bias0 : bias1;
    uint32_t pk[4][4][4];
#pragma unroll
    for (int mt = 0; mt < 4; mt++) {
        const int r0 = warp_m * 64 + mt * 16 + g;
        const float bv0 = __ldg(bias + r0);
        const float bv1 = __ldg(bias + r0 + 8);
#pragma unroll
        for (int nt = 0; nt < 4; nt++) {
            pk[mt][nt][0] = packhl(epi<ACT>(acc[mt][nt][0] + bv0));
            pk[mt][nt][1] = packhl(epi<ACT>(acc[mt][nt][1] + bv0));
            pk[mt][nt][2] = packhl(epi<ACT>(acc[mt][nt][2] + bv1));
            pk[mt][nt][3] = packhl(epi<ACT>(acc[mt][nt][3] + bv1));
        }
    }
    uint32_t* st = reinterpret_cast<uint32_t*>(smem);
    const int pix = tid & 63;
    const int q   = tid >> 6;
#pragma unroll 1
    for (int pass = 0; pass < 2; pass++) {
        __syncthreads();
        if ((warp_n >> 1) == pass) {
#pragma unroll
            for (int mt = 0; mt < 4; mt++) {
                const int r = warp_m * 64 + mt * 16 + g;
#pragma unroll
                for (int nt = 0; nt < 4; nt++) {
                    const int cloc = (warp_n & 1) * 32 + nt * 8 + 2 * tg;
                    st[cloc * 132 + r]           = pk[mt][nt][0];
                    st[(cloc + 1) * 132 + r]     = pk[mt][nt][1];
                    st[cloc * 132 + r + 8]       = pk[mt][nt][2];
                    st[(cloc + 1) * 132 + r + 8] = pk[mt][nt][3];
                }
            }
        }
        __syncthreads();
        const long prow = (long)(n0 + pass * 64 + pix) * out_cs + out_ch0 + m0 + q * 32;
        __nv_bfloat16* oh = g_acthi + out_off + prow;
        __nv_bfloat16* ol = g_actlo + out_off + prow;
#pragma unroll
        for (int jp = 0; jp < 4; jp++) {
            uint4 vA = *reinterpret_cast<uint4*>(&st[pix * 132 + q * 32 + jp * 8]);
            uint4 vB = *reinterpret_cast<uint4*>(&st[pix * 132 + q * 32 + jp * 8 + 4]);
            uint4 hv, lv;
            hv.x = __byte_perm(vA.x, vA.y, 0x5410);
            hv.y = __byte_perm(vA.z, vA.w, 0x5410);
            hv.z = __byte_perm(vB.x, vB.y, 0x5410);
            hv.w = __byte_perm(vB.z, vB.w, 0x5410);
            lv.x = __byte_perm(vA.x, vA.y, 0x7632);
            lv.y = __byte_perm(vA.z, vA.w, 0x7632);
            lv.z = __byte_perm(vB.x, vB.y, 0x7632);
            lv.w = __byte_perm(vB.z, vB.w, 0x7632);
            *reinterpret_cast<uint4*>(oh + jp * 8) = hv;
            *reinterpret_cast<uint4*>(ol + jp * 8) = lv;
        }
    }
}

// ------------------------- setup / pointwise kernels -----------------------
__global__ void split_w_kernel(const float* __restrict__ w, long off,
                               int rows, int vrows, int cin, int khw) {
    const int ktot = cin * khw;
    const long n = (long)rows * ktot;
    const long i = (long)blockIdx.x * blockDim.x + threadIdx.x;
    if (i >= n) return;
    const int co  = (int)(i / ktot);
    const int rem = (int)(i - (long)co * ktot);
    const int pos = rem / cin;
    const int ci  = rem - pos * cin;
    float x = 0.0f;
    if (co < vrows) x = w[(long)co * ktot + (long)ci * khw + pos];
    split2(x, g_whi[off + i], g_wlo[off + i]);
}
__global__ void pad_bias_kernel(const float* __restrict__ b) {
    const int i = threadIdx.x;
    g_scratch[OFF_PB2 + i] = (i < 16) ? b[i] : 0.0f;
}
__global__ void setup_bins_kernel() {
    const int p = blockIdx.x * blockDim.x + threadIdx.x;
    if (p >= NPIX) return;
    const int b = p / HW, hw = p - b * HW;
    float* ed = g_scratch + OFF_EDGES + (long)b * 17 * HW + hw;
#pragma unroll
    for (int j = 0; j < 17; j++) ed[j * HW] = 5.0f * j;
#pragma unroll
    for (int i = 0; i < 16; i++)
        split2(2.5f + 5.0f * i, g_acthi[A_CD + (long)p * 16 + i],
               g_actlo[A_CD + (long)p * 16 + i]);
}
__global__ void copy_ctx_kernel(const float* __restrict__ ctx) {
    __shared__ float t[192 * 33];
    const int p0 = blockIdx.x * 32;
    const int b = p0 / HW;
    const int hw = p0 - b * HW;
    const float* src = ctx + (long)b * 192 * HW + hw;
    for (int k = threadIdx.x; k < 192 * 32; k += 256) {
        const int c = k >> 5, w = k & 31;
        t[c * 33 + w] = src[(long)c * HW + w];
    }
    __syncthreads();
    for (int k = threadIdx.x; k < 32 * 192; k += 256) {
        const int w = k / 192, c = k - w * 192;
        const long o = A_HX + (long)(p0 + w) * 576 + 384 + c;
        split2(t[c * 33 + w], g_acthi[o], g_actlo[o]);
    }
}
__global__ void copy_h_kernel(const float* __restrict__ h0) {
    __shared__ float t[128 * 33];
    const int p0 = blockIdx.x * 32;
    const int b = p0 / HW;
    const int hw = p0 - b * HW;
    const float* src = h0 + (long)b * 128 * HW + hw;
    for (int k = threadIdx.x; k < 128 * 32; k += 256) {
        const int c = k >> 5, w = k & 31;
        t[c * 33 + w] = src[(long)c * HW + w];
    }
    __syncthreads();
    for (int k = threadIdx.x; k < 32 * 128; k += 256) {
        const int w = k >> 7, c = k & 127;
        const float v = t[c * 33 + w];
        g_scratch[OFF_H + (long)(p0 + w) * 128 + c] = v;
        const long o = A_HX + (long)(p0 + w) * 576 + c;
        split2(v, g_acthi[o], g_actlo[o]);
    }
}
__global__ void rh_kernel() {
    const long i = (long)blockIdx.x * blockDim.x + threadIdx.x;
    const long p = i >> 7;
    const int c = (int)(i & 127);
    const long zo = A_ZR + p * 256 + 128 + c;
    const float r = join2(g_acthi[zo], g_actlo[zo]);
    const float h = g_scratch[OFF_H + i];
    const long o = A_HX + p * 576 + c;
    split2(r * h, g_acthi[o], g_actlo[o]);
}
__global__ void gru_update_kernel() {
    const long i = (long)blockIdx.x * blockDim.x + threadIdx.x;
    const long p = i >> 7;
    const int c = (int)(i & 127);
    const long zo = A_ZR + p * 256 + c;
    const long qo = A_Q + p * 128 + c;
    const float z = join2(g_acthi[zo], g_actlo[zo]);
    const float q = join2(g_acthi[qo], g_actlo[qo]);
    const float h = g_scratch[OFF_H + i];
    const float hn = (1.0f - z) * h + z * q;
    g_scratch[OFF_H + i] = hn;
    const long o = A_HX + p * 576 + c;
    split2(hn, g_acthi[o], g_actlo[o]);
}
__global__ void bins_kernel(float* __restrict__ out, int it) {
    const int p = blockIdx.x * blockDim.x + threadIdx.x;
    if (p >= NPIX) return;
    const int b = p / HW, hw = p - b * HW;
    const long lgo = A_E2 + (long)p * 128;
    const long cdo = A_CD + (long)p * 16;
    float* edp = g_scratch + OFF_EDGES + (long)b * 17 * HW + hw;

    float l[16], cd[16];
    float m = -1e30f;
#pragma unroll
    for (int i = 0; i < 16; i++) {
        l[i] = join2(g_acthi[lgo + i], g_actlo[lgo + i]);
        m = fmaxf(m, l[i]);
    }
    float s = 0.0f;
#pragma unroll
    for (int i = 0; i < 16; i++) { l[i] = expf(l[i] - m); s += l[i]; }
    const float inv = 1.0f / s;
    float dr = 0.0f;
#pragma unroll
    for (int i = 0; i < 16; i++) {
        cd[i] = join2(g_acthi[cdo + i], g_actlo[cdo + i]);
        dr += l[i] * cd[i];
    }
    dr *= inv;
    float var = 0.0f;
#pragma unroll
    for (int i = 0; i < 16; i++) { const float d = cd[i] - dr; var += l[i] * d * d; }
    var *= inv;
    const float unc = sqrtf(var);

    out[(0 * 6 + it) * NPIX + p] = dr;
    out[(2 * 6 + it) * NPIX + p] = unc;

    int cnt = 0;
#pragma unroll
    for (int j = 1; j <= 15; j++) cnt += (dr >= edp[j * HW]) ? 1 : 0;
    const int label = (dr >= edp[16 * HW]) ? 0 : cnt;
    out[(1 * 6 + it) * NPIX + p] = cd[label];

    const float start = fmaxf(dr - 0.5f * unc, 0.0f);
    const float delta = unc * (1.0f / 16.0f);
    float cum = start;
    float eprev = fminf(fmaxf(cum, 0.0f), 80.0f);
    edp[0] = eprev;
#pragma unroll
    for (int i = 1; i <= 16; i++) {
        cum += delta;
        const float e = fminf(fmaxf(cum, 0.0f), 80.0f);
        edp[i * HW] = e;
        split2(0.5f * (eprev + e), g_acthi[cdo + i - 1], g_actlo[cdo + i - 1]);
        eprev = e;
    }
}

// ------------------------- launch ------------------------------------------
extern "C" void kernel_launch(void* const* d_in, const int* in_sizes, int n_in,
                              void* d_out, int out_size)
{
    (void)in_sizes; (void)n_in; (void)out_size;
    const float* context = (const float*)d_in[1];
    const float* gruh    = (const float*)d_in[2];
    const float* e1w = (const float*)d_in[3];  const float* e1b = (const float*)d_in[4];
    const float* e2w = (const float*)d_in[5];  const float* e2b = (const float*)d_in[6];
    const float* e3w = (const float*)d_in[7];  const float* e3b = (const float*)d_in[8];
    const float* e4w = (const float*)d_in[9];  const float* e4b = (const float*)d_in[10];
    const float* z1w = (const float*)d_in[11]; const float* z1b = (const float*)d_in[12];
    const float* r1w = (const float*)d_in[13]; const float* r1b = (const float*)d_in[14];
    const float* q1w = (const float*)d_in[15]; const float* q1b = (const float*)d_in[16];
    const float* z2w = (const float*)d_in[17]; const float* z2b = (const float*)d_in[18];
    const float* r2w = (const float*)d_in[19]; const float* r2b = (const float*)d_in[20];
    const float* q2w = (const float*)d_in[21]; const float* q2b = (const float*)d_in[22];
    const float* p1w = (const float*)d_in[23]; const float* p1b = (const float*)d_in[24];
    const float* p2w = (const float*)d_in[25]; const float* p2b = (const float*)d_in[26];
    float* out = (float*)d_out;

    float* sbase = nullptr;
    cudaGetSymbolAddress((void**)&sbase, g_scratch);
    const float* pb2 = sbase + OFF_PB2;

    constexpr int SMEM_DYN = 73728;   // 3 x 24576B stages
    auto fe1  = conv_mma<16, 128, 7, 7, 3, 3, ACT_RELU>;
    auto fc33 = conv_mma<128, 128, 3, 3, 1, 1, ACT_RELU>;
    auto fe4  = conv_mma<128, 256, 3, 3, 1, 1, ACT_RELU>;
    auto fzr1 = conv_mma<576, 256, 1, 5, 0, 2, ACT_SIG>;
    auto fq1  = conv_mma<576, 128, 1, 5, 0, 2, ACT_TANH>;
    auto fzr2 = conv_mma<576, 256, 5, 1, 2, 0, ACT_SIG>;
    auto fq2  = conv_mma<576, 128, 5, 1, 2, 0, ACT_TANH>;
    auto fp2  = conv_mma<128, 128, 3, 3, 1, 1, ACT_NONE>;
    cudaFuncSetAttribute(fe1,  cudaFuncAttributeMaxDynamicSharedMemorySize, SMEM_DYN);
    cudaFuncSetAttribute(fc33, cudaFuncAttributeMaxDynamicSharedMemorySize, SMEM_DYN);
    cudaFuncSetAttribute(fe4,  cudaFuncAttributeMaxDynamicSharedMemorySize, SMEM_DYN);
    cudaFuncSetAttribute(fzr1, cudaFuncAttributeMaxDynamicSharedMemorySize, SMEM_DYN);
    cudaFuncSetAttribute(fq1,  cudaFuncAttributeMaxDynamicSharedMemorySize, SMEM_DYN);
    cudaFuncSetAttribute(fzr2, cudaFuncAttributeMaxDynamicSharedMemorySize, SMEM_DYN);
    cudaFuncSetAttribute(fq2,  cudaFuncAttributeMaxDynamicSharedMemorySize, SMEM_DYN);
    cudaFuncSetAttribute(fp2,  cudaFuncAttributeMaxDynamicSharedMemorySize, SMEM_DYN);

    const dim3 blk(256);
    const int NT = NPIX / 128;
    const int PW256 = 2 * 128 * HW / 256;
    const int TB = NPIX / 32;

    setup_bins_kernel<<<(NPIX + 255) / 256, 256>>>();
    copy_ctx_kernel<<<TB, 256>>>(context);
    copy_h_kernel<<<TB, 256>>>(gruh);

    auto SW = [&](const float* w, long off, int rows, int vrows, int cin, int khw) {
        const long n = (long)rows * cin * khw;
        split_w_kernel<<<(int)((n + 255) / 256), 256>>>(w, off, rows, vrows, cin, khw);
    };
    SW(e1w, W_E1, 128, 128, 16, 49);
    SW(e2w, W_E2, 128, 128, 128, 9);
    SW(e3w, W_E3, 128, 128, 128, 9);
    SW(e4w, W_E4, 256, 256, 128, 9);
    SW(z1w, W_ZR1,           128, 128, 576, 5);
    SW(r1w, W_ZR1 + 368640,  128, 128, 576, 5);
    SW(q1w, W_Q1, 128, 128, 576, 5);
    SW(z2w, W_ZR2,           128, 128, 576, 5);
    SW(r2w, W_ZR2 + 368640,  128, 128, 576, 5);
    SW(q2w, W_Q2, 128, 128, 576, 5);
    SW(p1w, W_P1, 128, 128, 128, 9);
    SW(p2w, W_P2, 128, 16, 128, 9);
    pad_bias_kernel<<<1, 128>>>(p2b);

    for (int it = 0; it < 6; ++it) {
        fe1 <<<dim3(NT, 1), blk, SMEM_DYN>>>(A_CD, 16, 0, W_E1, e1b, e1b, A_E1, 128, 0);
        fc33<<<dim3(NT, 1), blk, SMEM_DYN>>>(A_E1, 128, 0, W_E2, e2b, e2b, A_E2, 128, 0);
        fc33<<<dim3(NT, 1), blk, SMEM_DYN>>>(A_E2, 128, 0, W_E3, e3b, e3b, A_E1, 128, 0);
        fe4 <<<dim3(NT, 2), blk, SMEM_DYN>>>(A_E1, 128, 0, W_E4, e4b, e4b + 128, A_HX, 576, 128);

        fzr1<<<dim3(NT, 2), blk, SMEM_DYN>>>(A_HX, 576, 0, W_ZR1, z1b, r1b, A_ZR, 256, 0);
        rh_kernel<<<PW256, 256>>>();
        fq1 <<<dim3(NT, 1), blk, SMEM_DYN>>>(A_HX, 576, 0, W_Q1, q1b, q1b, A_Q, 128, 0);
        gru_update_kernel<<<PW256, 256>>>();

        fzr2<<<dim3(NT, 2), blk, SMEM_DYN>>>(A_HX, 576, 0, W_ZR2, z2b, r2b, A_ZR, 256, 0);
        rh_kernel<<<PW256, 256>>>();
        fq2 <<<dim3(NT, 1), blk, SMEM_DYN>>>(A_HX, 576, 0, W_Q2, q2b, q2b, A_Q, 128, 0);
        gru_update_kernel<<<PW256, 256>>>();

        fc33<<<dim3(NT, 1), blk, SMEM_DYN>>>(A_HX, 576, 0, W_P1, p1b, p1b, A_E1, 128, 0);
        fp2 <<<dim3(NT, 1), blk, SMEM_DYN>>>(A_E1, 128, 0, W_P2, pb2, pb2, A_E2, 128, 0);

        bins_kernel<<<(NPIX + 127) / 128, 128>>>(out, it);
    }
}

// round 13
// speedup vs baseline: 2.1901x; 1.0515x over previous
#include <cuda_runtime.h>
#include <cuda_fp16.h>
#include <math.h>
#include <stdint.h>

// ---------------------------------------------------------------------------
// IEBINS — B=2, H=120, W=160, HD=128, CD=192, BN=16, 6 iters
// mma.sync fp16 3-term-split implicit-GEMM convs.
// Activations in separate fp16 hi/lo arenas, [pixel][channel] layout.
// cp.async 3-stage pipeline + ldmatrix. Specialized M=16 tile for ph2.
// ---------------------------------------------------------------------------

#define H_   120
#define W_   160
#define HW   19200
#define NPIX 38400

enum { ACT_NONE = 0, ACT_RELU = 1, ACT_SIG = 2, ACT_TANH = 3 };

// ------------------------- fp32 scratch ------------------------------------
constexpr long OFF_EDGES = 0;          // [2][17][HW]
constexpr long OFF_H     = 652800;     // [NPIX][128] GRU state
constexpr long SCRATCH_TOTAL = OFF_H + (long)NPIX * 128;
__device__ __align__(1024) float g_scratch[SCRATCH_TOTAL];

// ------------------------- fp16 activation arenas (hi / lo planes) ---------
constexpr long A_CD = 0;          // [NPIX][16]
constexpr long A_E1 = 614400;     // [NPIX][128]
constexpr long A_E2 = 5529600;    // [NPIX][128]
constexpr long A_HX = 10444800;   // [NPIX][576]: h | d | ctx
constexpr long A_ZR = 32563200;   // [NPIX][256]: z | r
constexpr long A_Q  = 42393600;   // [NPIX][128]
constexpr long A_LG = 47308800;   // [NPIX][16] logits
constexpr long A_TOT = 47923200;
__device__ __align__(1024) __half g_acthi[A_TOT];
__device__ __align__(1024) __half g_actlo[A_TOT];

// ------------------------- fp16 split-weight arena -------------------------
// layout per conv: [COUT][KH*KW][CIN], hi / lo planes
constexpr long W_E1  = 0;         // 128*784
constexpr long W_E2  = 100352;    // 147456
constexpr long W_E3  = 247808;    // 147456
constexpr long W_E4  = 395264;    // 294912
constexpr long W_ZR1 = 690176;    // 737280 (z | r)
constexpr long W_Q1  = 1427456;   // 368640
constexpr long W_ZR2 = 1796096;   // 737280
constexpr long W_Q2  = 2533376;   // 368640
constexpr long W_P1  = 2902016;   // 147456
constexpr long W_P2  = 3049472;   // 18432 (16 x 1152, unpadded)
constexpr long W_TOT = 3067904;
__device__ __align__(16) __half g_whi[W_TOT];
__device__ __align__(16) __half g_wlo[W_TOT];

// ------------------------- helpers -----------------------------------------
template <int ACT>
__device__ __forceinline__ float epi(float v) {
    if (ACT == ACT_RELU) return fmaxf(v, 0.0f);
    if (ACT == ACT_SIG)  return 1.0f / (1.0f + expf(-v));
    if (ACT == ACT_TANH) return tanhf(v);
    return v;
}
__device__ __forceinline__ void mma16816(float* c, const uint32_t* a, const uint32_t* b) {
    asm volatile(
        "mma.sync.aligned.m16n8k16.row.col.f32.f16.f16.f32 "
        "{%0,%1,%2,%3}, {%4,%5,%6,%7}, {%8,%9}, {%0,%1,%2,%3};\n"
        : "+f"(c[0]), "+f"(c[1]), "+f"(c[2]), "+f"(c[3])
        : "r"(a[0]), "r"(a[1]), "r"(a[2]), "r"(a[3]), "r"(b[0]), "r"(b[1]));
}
__device__ __forceinline__ void ldsm4(uint32_t& r0, uint32_t& r1, uint32_t& r2,
                                      uint32_t& r3, uint32_t a) {
    asm volatile("ldmatrix.sync.aligned.m8n8.x4.shared.b16 {%0,%1,%2,%3}, [%4];"
                 : "=r"(r0), "=r"(r1), "=r"(r2), "=r"(r3) : "r"(a));
}
__device__ __forceinline__ uint32_t smem_u32(const void* p) {
    uint32_t a;
    asm("{ .reg .u64 t; cvta.to.shared.u64 t, %1; cvt.u32.u64 %0, t; }"
        : "=r"(a) : "l"(p));
    return a;
}
__device__ __forceinline__ void cpa16(uint32_t d, const void* s) {
    asm volatile("cp.async.cg.shared.global [%0], [%1], 16;"
                 :: "r"(d), "l"(s) : "memory");
}
__device__ __forceinline__ void cpa16z(uint32_t d, const void* s, int sz) {
    asm volatile("cp.async.cg.shared.global [%0], [%1], 16, %2;"
                 :: "r"(d), "l"(s), "r"(sz) : "memory");
}
#define CP_COMMIT() asm volatile("cp.async.commit_group;" ::: "memory")
#define CP_WAIT1()  asm volatile("cp.async.wait_group 1;" ::: "memory")

__device__ __forceinline__ void split2(float v, __half& h, __half& l) {
    h = __float2half_rn(v);
    l = __float2half_rn(v - __half2float(h));
}
__device__ __forceinline__ uint32_t packhl(float v) {   // hi low16 | lo high16
    __half h, l;
    split2(v, h, l);
    return (uint32_t)(*reinterpret_cast<unsigned short*>(&h))
         | ((uint32_t)(*reinterpret_cast<unsigned short*>(&l)) << 16);
}
__device__ __forceinline__ float join2(__half h, __half l) {
    return __half2float(h) + __half2float(l);
}

// ===========================================================================
// fp16 mma implicit-GEMM conv, cp.async 3-stage pipeline, ldmatrix.
// M = COUT(128/blk.y), N = 128 pixels, K in 16-chunks (pos outer, ci inner).
// 8 warps = 2(m) x 4(n); warp tile 64x32; AhBh + AhBl + AlBh (3-term).
// ===========================================================================
template <int CIN, int COUT, int KH, int KW, int PH, int PW, int ACT>
__global__ __launch_bounds__(256)
void conv_mma(long in_off, int in_cs, int in_ch0, long w_off,
              const float* __restrict__ bias0, const float* __restrict__ bias1,
              long out_off, int out_cs, int out_ch0)
{
    constexpr int KTOT  = CIN * KH * KW;
    constexpr int CPC   = CIN / 16;
    constexpr int NITER = KTOT / 16;
    constexpr int STAGE = 24576;
    static_assert(CIN % 16 == 0 && NITER >= 3, "bad K config");

    extern __shared__ __align__(128) char smem[];
    const uint32_t sbase = smem_u32(smem);

    const int tid  = threadIdx.x;
    const int lane = tid & 31;
    const int wid  = tid >> 5;
    const int warp_m = wid >> 2;
    const int warp_n = wid & 3;
    const int g    = lane >> 2;
    const int tg   = lane & 3;
    const int lrow = lane & 15;
    const int lcol = lane >> 4;

    const int n0 = blockIdx.x << 7;
    const int m0 = blockIdx.y << 7;
    const int bb = n0 / HW;
    const int pixbase = bb * HW;

    const int arow = tid & 127;
    const int asel = tid >> 7;
    const __half* wbase =
        (asel ? g_wlo : g_whi) + w_off + (long)(m0 + arow) * KTOT;
    const uint32_t aStsOff = asel * 6144 + arow * 48;

    const int pixl   = tid & 127;
    const int bplane = tid >> 7;
    const int hwp = (n0 - pixbase) + pixl;
    const int py  = hwp / W_;
    const int px  = hwp - py * W_;
    const __half* bsrc0 = (bplane ? g_actlo : g_acthi) + in_off + in_ch0;
    const uint32_t bStsOff = 12288 + bplane * 6144 + pixl * 48;

    const uint32_t aLdOff = (warp_m * 64 + lrow) * 48 + lcol * 16;
    const uint32_t bLdOff = 12288 + (warp_n * 32 + lrow) * 48 + lcol * 16;

    float acc[4][4][4];
#pragma unroll
    for (int mt = 0; mt < 4; mt++)
#pragma unroll
        for (int nt = 0; nt < 4; nt++)
#pragma unroll
            for (int e = 0; e < 4; e++) acc[mt][nt][e] = 0.0f;

    auto issue = [&](int it, uint32_t soff) {
        const uint32_t ad = sbase + soff + aStsOff;
        const __half* as = wbase + it * 16;
        cpa16(ad, as);
        cpa16(ad + 16, as + 8);
        const int pos = it / CPC;
        const int cic = it - pos * CPC;
        const int ky  = pos / KW;
        const int kx  = pos - ky * KW;
        const int iy  = py + ky - PH;
        const int ix  = px + kx - PW;
        const bool ok = ((unsigned)iy < (unsigned)H_) && ((unsigned)ix < (unsigned)W_);
        const __half* bs = ok
            ? bsrc0 + (long)(pixbase + iy * W_ + ix) * in_cs + cic * 16
            : bsrc0;
        const int sz = ok ? 16 : 0;
        const uint32_t bd = sbase + soff + bStsOff;
        cpa16z(bd, bs, sz);
        cpa16z(bd + 16, bs + 8, sz);
    };

    issue(0, 0);            CP_COMMIT();
    issue(1, STAGE);        CP_COMMIT();

    uint32_t cur = 0, nxt = 2 * STAGE;
#pragma unroll 1
    for (int it = 0; it < NITER; ++it) {
        CP_WAIT1();
        __syncthreads();
        if (it + 2 < NITER) issue(it + 2, nxt);
        CP_COMMIT();

        const uint32_t base = sbase + cur;
        uint32_t ah[4][4], al[4][4];
#pragma unroll
        for (int mt = 0; mt < 4; mt++) {
            const uint32_t aa = base + aLdOff + mt * 768;
            ldsm4(ah[mt][0], ah[mt][1], ah[mt][2], ah[mt][3], aa);
            ldsm4(al[mt][0], al[mt][1], al[mt][2], al[mt][3], aa + 6144);
        }
#pragma unroll
        for (int p = 0; p < 2; p++) {
            uint32_t bh[4], bl[4];
            const uint32_t ba = base + bLdOff + p * 768;
            ldsm4(bh[0], bh[1], bh[2], bh[3], ba);
            ldsm4(bl[0], bl[1], bl[2], bl[3], ba + 6144);
#pragma unroll
            for (int f = 0; f < 2; f++) {
                uint32_t bhf[2] = { bh[f], bh[f + 2] };
                uint32_t blf[2] = { bl[f], bl[f + 2] };
                const int nt = p * 2 + f;
#pragma unroll
                for (int mt = 0; mt < 4; mt++) {
                    mma16816(acc[mt][nt], ah[mt], bhf);
                    mma16816(acc[mt][nt], ah[mt], blf);
                    mma16816(acc[mt][nt], al[mt], bhf);
                }
            }
        }
        cur = (cur == 2 * STAGE) ? 0 : cur + STAGE;
        nxt = (nxt == 2 * STAGE) ? 0 : nxt + STAGE;
    }

    // ---- epilogue: bias + act + pack; smem-staged plane stores ----
    const float* bias = (blockIdx.y == 0) ? bias0 : bias1;
    uint32_t pk[4][4][4];
#pragma unroll
    for (int mt = 0; mt < 4; mt++) {
        const int r0 = warp_m * 64 + mt * 16 + g;
        const float bv0 = __ldg(bias + r0);
        const float bv1 = __ldg(bias + r0 + 8);
#pragma unroll
        for (int nt = 0; nt < 4; nt++) {
            pk[mt][nt][0] = packhl(epi<ACT>(acc[mt][nt][0] + bv0));
            pk[mt][nt][1] = packhl(epi<ACT>(acc[mt][nt][1] + bv0));
            pk[mt][nt][2] = packhl(epi<ACT>(acc[mt][nt][2] + bv1));
            pk[mt][nt][3] = packhl(epi<ACT>(acc[mt][nt][3] + bv1));
        }
    }
    uint32_t* st = reinterpret_cast<uint32_t*>(smem);
    const int pix = tid & 63;
    const int q   = tid >> 6;
#pragma unroll 1
    for (int pass = 0; pass < 2; pass++) {
        __syncthreads();
        if ((warp_n >> 1) == pass) {
#pragma unroll
            for (int mt = 0; mt < 4; mt++) {
                const int r = warp_m * 64 + mt * 16 + g;
#pragma unroll
                for (int nt = 0; nt < 4; nt++) {
                    const int cloc = (warp_n & 1) * 32 + nt * 8 + 2 * tg;
                    st[cloc * 132 + r]           = pk[mt][nt][0];
                    st[(cloc + 1) * 132 + r]     = pk[mt][nt][1];
                    st[cloc * 132 + r + 8]       = pk[mt][nt][2];
                    st[(cloc + 1) * 132 + r + 8] = pk[mt][nt][3];
                }
            }
        }
        __syncthreads();
        const long prow = (long)(n0 + pass * 64 + pix) * out_cs + out_ch0 + m0 + q * 32;
        __half* oh = g_acthi + out_off + prow;
        __half* ol = g_actlo + out_off + prow;
#pragma unroll
        for (int jp = 0; jp < 4; jp++) {
            uint4 vA = *reinterpret_cast<uint4*>(&st[pix * 132 + q * 32 + jp * 8]);
            uint4 vB = *reinterpret_cast<uint4*>(&st[pix * 132 + q * 32 + jp * 8 + 4]);
            uint4 hv, lv;
            hv.x = __byte_perm(vA.x, vA.y, 0x5410);
            hv.y = __byte_perm(vA.z, vA.w, 0x5410);
            hv.z = __byte_perm(vB.x, vB.y, 0x5410);
            hv.w = __byte_perm(vB.z, vB.w, 0x5410);
            lv.x = __byte_perm(vA.x, vA.y, 0x7632);
            lv.y = __byte_perm(vA.z, vA.w, 0x7632);
            lv.z = __byte_perm(vB.x, vB.y, 0x7632);
            lv.w = __byte_perm(vB.z, vB.w, 0x7632);
            *reinterpret_cast<uint4*>(oh + jp * 8) = hv;
            *reinterpret_cast<uint4*>(ol + jp * 8) = lv;
        }
    }
}

// ===========================================================================
// Specialized ph2 conv: COUT=16, CIN=128, 3x3. M=16 x N=128 tile.
// 8 warps, each: all 16 M-rows x 16 pixels; 6 HMMA/warp/iter (3-term).
// ===========================================================================
__global__ __launch_bounds__(256)
void conv_mma16(long in_off, long w_off, const float* __restrict__ bias,
                long out_off)
{
    constexpr int KTOT = 1152, CPC = 8, NITER = 72;
    constexpr int STAGE = 13824;   // Ahi768 | Alo768 | Bhi6144 | Blo6144
    __shared__ __align__(128) char smem[3 * STAGE];
    const uint32_t sbase = smem_u32(smem);

    const int tid  = threadIdx.x;
    const int lane = tid & 31;
    const int wid  = tid >> 5;
    const int g  = lane >> 2;
    const int tg = lane & 3;

    const int n0 = blockIdx.x << 7;
    const int bb = n0 / HW;
    const int pixbase = bb * HW;

    const int arow  = tid & 15;
    const int ahalf = (tid >> 4) & 1;
    const int asel  = tid >> 5;    // valid when tid<64
    const __half* wb =
        ((asel & 1) ? g_wlo : g_whi) + w_off + (long)arow * KTOT + ahalf * 8;

    const int pixl   = tid & 127;
    const int bplane = tid >> 7;
    const int hwp = (n0 - pixbase) + pixl;
    const int py  = hwp / W_;
    const int px  = hwp - py * W_;
    const __half* bsrc0 = (bplane ? g_actlo : g_acthi) + in_off;
    const uint32_t bStsOff = 1536 + bplane * 6144 + pixl * 48;

    const uint32_t aLdOff = (lane & 15) * 48 + (lane >> 4) * 16;
    const uint32_t bLdOff = 1536 + (wid * 16 + (lane & 15)) * 48 + (lane >> 4) * 16;

    float acc[2][4];
#pragma unroll
    for (int nf = 0; nf < 2; nf++)
#pragma unroll
        for (int e = 0; e < 4; e++) acc[nf][e] = 0.0f;

    auto issue = [&](int it, uint32_t soff) {
        if (tid < 64)
            cpa16(sbase + soff + (asel & 1) * 768 + arow * 48 + ahalf * 16,
                  wb + it * 16);
        const int pos = it / CPC;
        const int cic = it - pos * CPC;
        const int ky  = pos / 3;
        const int kx  = pos - ky * 3;
        const int iy  = py + ky - 1;
        const int ix  = px + kx - 1;
        const bool ok = ((unsigned)iy < (unsigned)H_) && ((unsigned)ix < (unsigned)W_);
        const __half* bs = ok
            ? bsrc0 + (long)(pixbase + iy * W_ + ix) * 128 + cic * 16
            : bsrc0;
        const int sz = ok ? 16 : 0;
        const uint32_t bd = sbase + soff + bStsOff;
        cpa16z(bd, bs, sz);
        cpa16z(bd + 16, bs + 8, sz);
    };

    issue(0, 0);       CP_COMMIT();
    issue(1, STAGE);   CP_COMMIT();

    uint32_t cur = 0, nxt = 2 * STAGE;
#pragma unroll 1
    for (int it = 0; it < NITER; ++it) {
        CP_WAIT1();
        __syncthreads();
        if (it + 2 < NITER) issue(it + 2, nxt);
        CP_COMMIT();

        const uint32_t base = sbase + cur;
        uint32_t ah[4], al[4], bh[4], bl[4];
        ldsm4(ah[0], ah[1], ah[2], ah[3], base + aLdOff);
        ldsm4(al[0], al[1], al[2], al[3], base + aLdOff + 768);
        ldsm4(bh[0], bh[1], bh[2], bh[3], base + bLdOff);
        ldsm4(bl[0], bl[1], bl[2], bl[3], base + bLdOff + 6144);
#pragma unroll
        for (int nf = 0; nf < 2; nf++) {
            uint32_t bhf[2] = { bh[nf], bh[nf + 2] };
            uint32_t blf[2] = { bl[nf], bl[nf + 2] };
            mma16816(acc[nf], ah, bhf);
            mma16816(acc[nf], ah, blf);
            mma16816(acc[nf], al, bhf);
        }
        cur = (cur == 2 * STAGE) ? 0 : cur + STAGE;
        nxt = (nxt == 2 * STAGE) ? 0 : nxt + STAGE;
    }

    const float bv0 = __ldg(bias + g);
    const float bv1 = __ldg(bias + g + 8);
#pragma unroll
    for (int nf = 0; nf < 2; nf++) {
        const long p0 = (long)(n0 + wid * 16 + nf * 8 + 2 * tg);
        __half h, l;
        split2(acc[nf][0] + bv0, h, l);
        g_acthi[out_off + p0 * 16 + g] = h;       g_actlo[out_off + p0 * 16 + g] = l;
        split2(acc[nf][1] + bv0, h, l);
        g_acthi[out_off + (p0 + 1) * 16 + g] = h; g_actlo[out_off + (p0 + 1) * 16 + g] = l;
        split2(acc[nf][2] + bv1, h, l);
        g_acthi[out_off + p0 * 16 + g + 8] = h;   g_actlo[out_off + p0 * 16 + g + 8] = l;
        split2(acc[nf][3] + bv1, h, l);
        g_acthi[out_off + (p0 + 1) * 16 + g + 8] = h;
        g_actlo[out_off + (p0 + 1) * 16 + g + 8] = l;
    }
}

// ------------------------- setup / pointwise kernels -----------------------
__global__ void split_w_kernel(const float* __restrict__ w, long off,
                               int rows, int cin, int khw) {
    const int ktot = cin * khw;
    const long n = (long)rows * ktot;
    const long i = (long)blockIdx.x * blockDim.x + threadIdx.x;
    if (i >= n) return;
    const int co  = (int)(i / ktot);
    const int rem = (int)(i - (long)co * ktot);
    const int pos = rem / cin;
    const int ci  = rem - pos * cin;
    const float x = w[(long)co * ktot + (long)ci * khw + pos];
    split2(x, g_whi[off + i], g_wlo[off + i]);
}
__global__ void setup_bins_kernel() {
    const int p = blockIdx.x * blockDim.x + threadIdx.x;
    if (p >= NPIX) return;
    const int b = p / HW, hw = p - b * HW;
    float* ed = g_scratch + OFF_EDGES + (long)b * 17 * HW + hw;
#pragma unroll
    for (int j = 0; j < 17; j++) ed[j * HW] = 5.0f * j;
#pragma unroll
    for (int i = 0; i < 16; i++)
        split2(2.5f + 5.0f * i, g_acthi[A_CD + (long)p * 16 + i],
               g_actlo[A_CD + (long)p * 16 + i]);
}
__global__ void copy_ctx_kernel(const float* __restrict__ ctx) {
    __shared__ float t[192 * 33];
    const int p0 = blockIdx.x * 32;
    const int b = p0 / HW;
    const int hw = p0 - b * HW;
    const float* src = ctx + (long)b * 192 * HW + hw;
    for (int k = threadIdx.x; k < 192 * 32; k += 256) {
        const int c = k >> 5, w = k & 31;
        t[c * 33 + w] = src[(long)c * HW + w];
    }
    __syncthreads();
    for (int k = threadIdx.x; k < 32 * 192; k += 256) {
        const int w = k / 192, c = k - w * 192;
        const long o = A_HX + (long)(p0 + w) * 576 + 384 + c;
        split2(t[c * 33 + w], g_acthi[o], g_actlo[o]);
    }
}
__global__ void copy_h_kernel(const float* __restrict__ h0) {
    __shared__ float t[128 * 33];
    const int p0 = blockIdx.x * 32;
    const int b = p0 / HW;
    const int hw = p0 - b * HW;
    const float* src = h0 + (long)b * 128 * HW + hw;
    for (int k = threadIdx.x; k < 128 * 32; k += 256) {
        const int c = k >> 5, w = k & 31;
        t[c * 33 + w] = src[(long)c * HW + w];
    }
    __syncthreads();
    for (int k = threadIdx.x; k < 32 * 128; k += 256) {
        const int w = k >> 7, c = k & 127;
        const float v = t[c * 33 + w];
        g_scratch[OFF_H + (long)(p0 + w) * 128 + c] = v;
        const long o = A_HX + (long)(p0 + w) * 576 + c;
        split2(v, g_acthi[o], g_actlo[o]);
    }
}
__global__ void rh_kernel() {
    const long i = (long)blockIdx.x * blockDim.x + threadIdx.x;
    const long p = i >> 7;
    const int c = (int)(i & 127);
    const long zo = A_ZR + p * 256 + 128 + c;
    const float r = join2(g_acthi[zo], g_actlo[zo]);
    const float h = g_scratch[OFF_H + i];
    const long o = A_HX + p * 576 + c;
    split2(r * h, g_acthi[o], g_actlo[o]);
}
__global__ void gru_update_kernel() {
    const long i = (long)blockIdx.x * blockDim.x + threadIdx.x;
    const long p = i >> 7;
    const int c = (int)(i & 127);
    const long zo = A_ZR + p * 256 + c;
    const long qo = A_Q + p * 128 + c;
    const float z = join2(g_acthi[zo], g_actlo[zo]);
    const float q = join2(g_acthi[qo], g_actlo[qo]);
    const float h = g_scratch[OFF_H + i];
    const float hn = (1.0f - z) * h + z * q;
    g_scratch[OFF_H + i] = hn;
    const long o = A_HX + p * 576 + c;
    split2(hn, g_acthi[o], g_actlo[o]);
}
__global__ void bins_kernel(float* __restrict__ out, int it) {
    const int p = blockIdx.x * blockDim.x + threadIdx.x;
    if (p >= NPIX) return;
    const int b = p / HW, hw = p - b * HW;
    const long lgo = A_LG + (long)p * 16;
    const long cdo = A_CD + (long)p * 16;
    float* edp = g_scratch + OFF_EDGES + (long)b * 17 * HW + hw;

    float l[16], cd[16];
    float m = -1e30f;
#pragma unroll
    for (int i = 0; i < 16; i++) {
        l[i] = join2(g_acthi[lgo + i], g_actlo[lgo + i]);
        m = fmaxf(m, l[i]);
    }
    float s = 0.0f;
#pragma unroll
    for (int i = 0; i < 16; i++) { l[i] = expf(l[i] - m); s += l[i]; }
    const float inv = 1.0f / s;
    float dr = 0.0f;
#pragma unroll
    for (int i = 0; i < 16; i++) {
        cd[i] = join2(g_acthi[cdo + i], g_actlo[cdo + i]);
        dr += l[i] * cd[i];
    }
    dr *= inv;
    float var = 0.0f;
#pragma unroll
    for (int i = 0; i < 16; i++) { const float d = cd[i] - dr; var += l[i] * d * d; }
    var *= inv;
    const float unc = sqrtf(var);

    out[(0 * 6 + it) * NPIX + p] = dr;
    out[(2 * 6 + it) * NPIX + p] = unc;

    int cnt = 0;
#pragma unroll
    for (int j = 1; j <= 15; j++) cnt += (dr >= edp[j * HW]) ? 1 : 0;
    const int label = (dr >= edp[16 * HW]) ? 0 : cnt;
    out[(1 * 6 + it) * NPIX + p] = cd[label];

    const float start = fmaxf(dr - 0.5f * unc, 0.0f);
    const float delta = unc * (1.0f / 16.0f);
    float cum = start;
    float eprev = fminf(fmaxf(cum, 0.0f), 80.0f);
    edp[0] = eprev;
#pragma unroll
    for (int i = 1; i <= 16; i++) {
        cum += delta;
        const float e = fminf(fmaxf(cum, 0.0f), 80.0f);
        edp[i * HW] = e;
        split2(0.5f * (eprev + e), g_acthi[cdo + i - 1], g_actlo[cdo + i - 1]);
        eprev = e;
    }
}

// ------------------------- launch ------------------------------------------
extern "C" void kernel_launch(void* const* d_in, const int* in_sizes, int n_in,
                              void* d_out, int out_size)
{
    (void)in_sizes; (void)n_in; (void)out_size;
    const float* context = (const float*)d_in[1];
    const float* gruh    = (const float*)d_in[2];
    const float* e1w = (const float*)d_in[3];  const float* e1b = (const float*)d_in[4];
    const float* e2w = (const float*)d_in[5];  const float* e2b = (const float*)d_in[6];
    const float* e3w = (const float*)d_in[7];  const float* e3b = (const float*)d_in[8];
    const float* e4w = (const float*)d_in[9];  const float* e4b = (const float*)d_in[10];
    const float* z1w = (const float*)d_in[11]; const float* z1b = (const float*)d_in[12];
    const float* r1w = (const float*)d_in[13]; const float* r1b = (const float*)d_in[14];
    const float* q1w = (const float*)d_in[15]; const float* q1b = (const float*)d_in[16];
    const float* z2w = (const float*)d_in[17]; const float* z2b = (const float*)d_in[18];
    const float* r2w = (const float*)d_in[19]; const float* r2b = (const float*)d_in[20];
    const float* q2w = (const float*)d_in[21]; const float* q2b = (const float*)d_in[22];
    const float* p1w = (const float*)d_in[23]; const float* p1b = (const float*)d_in[24];
    const float* p2w = (const float*)d_in[25]; const float* p2b = (const float*)d_in[26];
    float* out = (float*)d_out;

    constexpr int SMEM_DYN = 73728;   // 3 x 24576B stages
    auto fe1  = conv_mma<16, 128, 7, 7, 3, 3, ACT_RELU>;
    auto fc33 = conv_mma<128, 128, 3, 3, 1, 1, ACT_RELU>;
    auto fe4  = conv_mma<128, 256, 3, 3, 1, 1, ACT_RELU>;
    auto fzr1 = conv_mma<576, 256, 1, 5, 0, 2, ACT_SIG>;
    auto fq1  = conv_mma<576, 128, 1, 5, 0, 2, ACT_TANH>;
    auto fzr2 = conv_mma<576, 256, 5, 1, 2, 0, ACT_SIG>;
    auto fq2  = conv_mma<576, 128, 5, 1, 2, 0, ACT_TANH>;
    cudaFuncSetAttribute(fe1,  cudaFuncAttributeMaxDynamicSharedMemorySize, SMEM_DYN);
    cudaFuncSetAttribute(fc33, cudaFuncAttributeMaxDynamicSharedMemorySize, SMEM_DYN);
    cudaFuncSetAttribute(fe4,  cudaFuncAttributeMaxDynamicSharedMemorySize, SMEM_DYN);
    cudaFuncSetAttribute(fzr1, cudaFuncAttributeMaxDynamicSharedMemorySize, SMEM_DYN);
    cudaFuncSetAttribute(fq1,  cudaFuncAttributeMaxDynamicSharedMemorySize, SMEM_DYN);
    cudaFuncSetAttribute(fzr2, cudaFuncAttributeMaxDynamicSharedMemorySize, SMEM_DYN);
    cudaFuncSetAttribute(fq2,  cudaFuncAttributeMaxDynamicSharedMemorySize, SMEM_DYN);

    const dim3 blk(256);
    const int NT = NPIX / 128;
    const int PW256 = 2 * 128 * HW / 256;
    const int TB = NPIX / 32;

    setup_bins_kernel<<<(NPIX + 255) / 256, 256>>>();
    copy_ctx_kernel<<<TB, 256>>>(context);
    copy_h_kernel<<<TB, 256>>>(gruh);

    auto SW = [&](const float* w, long off, int rows, int cin, int khw) {
        const long n = (long)rows * cin * khw;
        split_w_kernel<<<(int)((n + 255) / 256), 256>>>(w, off, rows, cin, khw);
    };
    SW(e1w, W_E1, 128, 16, 49);
    SW(e2w, W_E2, 128, 128, 9);
    SW(e3w, W_E3, 128, 128, 9);
    SW(e4w, W_E4, 256, 128, 9);
    SW(z1w, W_ZR1,           128, 576, 5);
    SW(r1w, W_ZR1 + 368640,  128, 576, 5);
    SW(q1w, W_Q1, 128, 576, 5);
    SW(z2w, W_ZR2,           128, 576, 5);
    SW(r2w, W_ZR2 + 368640,  128, 576, 5);
    SW(q2w, W_Q2, 128, 576, 5);
    SW(p1w, W_P1, 128, 128, 9);
    SW(p2w, W_P2, 16, 128, 9);          // unpadded 16 rows

    for (int it = 0; it < 6; ++it) {
        fe1 <<<dim3(NT, 1), blk, SMEM_DYN>>>(A_CD, 16, 0, W_E1, e1b, e1b, A_E1, 128, 0);
        fc33<<<dim3(NT, 1), blk, SMEM_DYN>>>(A_E1, 128, 0, W_E2, e2b, e2b, A_E2, 128, 0);
        fc33<<<dim3(NT, 1), blk, SMEM_DYN>>>(A_E2, 128, 0, W_E3, e3b, e3b, A_E1, 128, 0);
        fe4 <<<dim3(NT, 2), blk, SMEM_DYN>>>(A_E1, 128, 0, W_E4, e4b, e4b + 128, A_HX, 576, 128);

        fzr1<<<dim3(NT, 2), blk, SMEM_DYN>>>(A_HX, 576, 0, W_ZR1, z1b, r1b, A_ZR, 256, 0);
        rh_kernel<<<PW256, 256>>>();
        fq1 <<<dim3(NT, 1), blk, SMEM_DYN>>>(A_HX, 576, 0, W_Q1, q1b, q1b, A_Q, 128, 0);
        gru_update_kernel<<<PW256, 256>>>();

        fzr2<<<dim3(NT, 2), blk, SMEM_DYN>>>(A_HX, 576, 0, W_ZR2, z2b, r2b, A_ZR, 256, 0);
        rh_kernel<<<PW256, 256>>>();
        fq2 <<<dim3(NT, 1), blk, SMEM_DYN>>>(A_HX, 576, 0, W_Q2, q2b, q2b, A_Q, 128, 0);
        gru_update_kernel<<<PW256, 256>>>();

        fc33<<<dim3(NT, 1), blk, SMEM_DYN>>>(A_HX, 576, 0, W_P1, p1b, p1b, A_E1, 128, 0);
        conv_mma16<<<NT, blk>>>(A_E1, W_P2, p2b, A_LG);

        bins_kernel<<<(NPIX + 127) / 128, 128>>>(out, it);
    }
}

// round 14
// speedup vs baseline: 2.4041x; 1.0977x over previous
#include <cuda_runtime.h>
#include <cuda_fp16.h>
#include <math.h>
#include <stdint.h>

// ---------------------------------------------------------------------------
// IEBINS — B=2, H=120, W=160, HD=128, CD=192, BN=16, 6 iters
// mma.sync fp16 3-term-split implicit-GEMM convs; cp.async 3-stage pipeline.
// GRU pointwise ops FUSED into conv epilogues (rh / gru-update), dual-source
// B loader (h-like tensor [pixel][128] + x tensor [pixel][448]).
// ---------------------------------------------------------------------------

#define H_   120
#define W_   160
#define HW   19200
#define NPIX 38400

enum { ACT_NONE = 0, ACT_RELU = 1, ACT_SIG = 2, ACT_TANH = 3 };
enum { EPI_STD = 0, EPI_Z_RH = 1, EPI_GRU = 2 };

// ------------------------- fp32 scratch ------------------------------------
constexpr long OFF_EDGES = 0;          // [2][17][HW]
constexpr long OFF_H     = 652800;     // [NPIX][128] GRU state
constexpr long SCRATCH_TOTAL = OFF_H + (long)NPIX * 128;
__device__ __align__(1024) float g_scratch[SCRATCH_TOTAL];

// ------------------------- fp16 activation arenas (hi / lo planes) ---------
constexpr long A_CD = 0;          // [NPIX][16]
constexpr long A_E1 = 614400;     // [NPIX][128]
constexpr long A_E2 = 5529600;    // [NPIX][128]
constexpr long A_X  = 10444800;   // [NPIX][448]: d(0:256) | ctx(256:448)
constexpr long A_HT = 27648000;   // [NPIX][128] packed h
constexpr long A_RH = 32563200;   // [NPIX][128] packed r*h
constexpr long A_Z  = 37478400;   // [NPIX][128] packed z
constexpr long A_LG = 42393600;   // [NPIX][16] logits
constexpr long A_TOT = 43008000;
__device__ __align__(1024) __half g_acthi[A_TOT];
__device__ __align__(1024) __half g_actlo[A_TOT];

// ------------------------- fp16 split-weight arena -------------------------
// layout per conv: [COUT][KH*KW][CIN], hi / lo planes
constexpr long W_E1  = 0;         // 128*784
constexpr long W_E2  = 100352;    // 147456
constexpr long W_E3  = 247808;    // 147456
constexpr long W_E4  = 395264;    // 294912
constexpr long W_ZR1 = 690176;    // 737280 (z | r)
constexpr long W_Q1  = 1427456;   // 368640
constexpr long W_ZR2 = 1796096;   // 737280
constexpr long W_Q2  = 2533376;   // 368640
constexpr long W_P1  = 2902016;   // 147456
constexpr long W_P2  = 3049472;   // 18432 (16 x 1152, unpadded)
constexpr long W_TOT = 3067904;
__device__ __align__(16) __half g_whi[W_TOT];
__device__ __align__(16) __half g_wlo[W_TOT];

// ------------------------- helpers -----------------------------------------
template <int ACT>
__device__ __forceinline__ float epi(float v) {
    if (ACT == ACT_RELU) return fmaxf(v, 0.0f);
    if (ACT == ACT_SIG)  return 1.0f / (1.0f + expf(-v));
    if (ACT == ACT_TANH) return tanhf(v);
    return v;
}
__device__ __forceinline__ void mma16816(float* c, const uint32_t* a, const uint32_t* b) {
    asm volatile(
        "mma.sync.aligned.m16n8k16.row.col.f32.f16.f16.f32 "
        "{%0,%1,%2,%3}, {%4,%5,%6,%7}, {%8,%9}, {%0,%1,%2,%3};\n"
        : "+f"(c[0]), "+f"(c[1]), "+f"(c[2]), "+f"(c[3])
        : "r"(a[0]), "r"(a[1]), "r"(a[2]), "r"(a[3]), "r"(b[0]), "r"(b[1]));
}
__device__ __forceinline__ void ldsm4(uint32_t& r0, uint32_t& r1, uint32_t& r2,
                                      uint32_t& r3, uint32_t a) {
    asm volatile("ldmatrix.sync.aligned.m8n8.x4.shared.b16 {%0,%1,%2,%3}, [%4];"
                 : "=r"(r0), "=r"(r1), "=r"(r2), "=r"(r3) : "r"(a));
}
__device__ __forceinline__ uint32_t smem_u32(const void* p) {
    uint32_t a;
    asm("{ .reg .u64 t; cvta.to.shared.u64 t, %1; cvt.u32.u64 %0, t; }"
        : "=r"(a) : "l"(p));
    return a;
}
__device__ __forceinline__ void cpa16(uint32_t d, const void* s) {
    asm volatile("cp.async.cg.shared.global [%0], [%1], 16;"
                 :: "r"(d), "l"(s) : "memory");
}
__device__ __forceinline__ void cpa16z(uint32_t d, const void* s, int sz) {
    asm volatile("cp.async.cg.shared.global [%0], [%1], 16, %2;"
                 :: "r"(d), "l"(s), "r"(sz) : "memory");
}
#define CP_COMMIT() asm volatile("cp.async.commit_group;" ::: "memory")
#define CP_WAIT1()  asm volatile("cp.async.wait_group 1;" ::: "memory")

__device__ __forceinline__ void split2(float v, __half& h, __half& l) {
    h = __float2half_rn(v);
    l = __float2half_rn(v - __half2float(h));
}
__device__ __forceinline__ uint32_t packhl(float v) {   // hi low16 | lo high16
    __half h, l;
    split2(v, h, l);
    return (uint32_t)(*reinterpret_cast<unsigned short*>(&h))
         | ((uint32_t)(*reinterpret_cast<unsigned short*>(&l)) << 16);
}
__device__ __forceinline__ float join2(__half h, __half l) {
    return __half2float(h) + __half2float(l);
}
__device__ __forceinline__ float joinu(uint32_t u) {
    unsigned short hb = (unsigned short)(u & 0xFFFFu);
    unsigned short lb = (unsigned short)(u >> 16);
    return __half2float(*reinterpret_cast<__half*>(&hb))
         + __half2float(*reinterpret_cast<__half*>(&lb));
}

// ===========================================================================
// fp16 mma implicit-GEMM conv, cp.async 3-stage pipeline, ldmatrix.
// M = COUT(128/blk.y), N = 128 pixels, K in 16-chunks (pos outer, ci inner).
// Dual-source B: channels [0,CSPLIT) from tensor0, rest from tensor1.
// EPI_STD: packed hi/lo store. EPI_Z_RH: y0=z store, y1=r*h fuse.
// EPI_GRU: hn=(1-z)h+zq fuse (writes OFF_H + A_HT).
// ===========================================================================
template <int CSPLIT, int CIN, int COUT, int KH, int KW, int PH, int PW,
          int ACT, int EPI>
__global__ __launch_bounds__(256)
void conv_mma(long in0_off, int in0_cs, long in1_off, int in1_cs,
              long w_off, const float* __restrict__ bias0,
              const float* __restrict__ bias1,
              long out_off, int out_cs, int out_ch0)
{
    constexpr int KTOT  = CIN * KH * KW;
    constexpr int CPC   = CIN / 16;
    constexpr int NITER = KTOT / 16;
    constexpr int STAGE = 24576;
    static_assert(CIN % 16 == 0 && NITER >= 3 && CSPLIT % 16 == 0, "bad cfg");

    extern __shared__ __align__(128) char smem[];
    const uint32_t sbase = smem_u32(smem);

    const int tid  = threadIdx.x;
    const int lane = tid & 31;
    const int wid  = tid >> 5;
    const int warp_m = wid >> 2;
    const int warp_n = wid & 3;
    const int g    = lane >> 2;
    const int tg   = lane & 3;
    const int lrow = lane & 15;
    const int lcol = lane >> 4;

    const int n0 = blockIdx.x << 7;
    const int m0 = blockIdx.y << 7;
    const int bb = n0 / HW;
    const int pixbase = bb * HW;

    const int arow = tid & 127;
    const int asel = tid >> 7;
    const __half* wbase =
        (asel ? g_wlo : g_whi) + w_off + (long)(m0 + arow) * KTOT;
    const uint32_t aStsOff = asel * 6144 + arow * 48;

    const int pixl   = tid & 127;
    const int bplane = tid >> 7;
    const int hwp = (n0 - pixbase) + pixl;
    const int py  = hwp / W_;
    const int px  = hwp - py * W_;
    const __half* plane = bplane ? g_actlo : g_acthi;
    const __half* b0 = plane + in0_off;
    const __half* b1 = plane + in1_off;
    const uint32_t bStsOff = 12288 + bplane * 6144 + pixl * 48;

    const uint32_t aLdOff = (warp_m * 64 + lrow) * 48 + lcol * 16;
    const uint32_t bLdOff = 12288 + (warp_n * 32 + lrow) * 48 + lcol * 16;

    float acc[4][4][4];
#pragma unroll
    for (int mt = 0; mt < 4; mt++)
#pragma unroll
        for (int nt = 0; nt < 4; nt++)
#pragma unroll
            for (int e = 0; e < 4; e++) acc[mt][nt][e] = 0.0f;

    auto issue = [&](int it, uint32_t soff) {
        const uint32_t ad = sbase + soff + aStsOff;
        const __half* as = wbase + it * 16;
        cpa16(ad, as);
        cpa16(ad + 16, as + 8);
        const int pos = it / CPC;
        const int cic = it - pos * CPC;
        const int ky  = pos / KW;
        const int kx  = pos - ky * KW;
        const int iy  = py + ky - PH;
        const int ix  = px + kx - PW;
        const bool ok = ((unsigned)iy < (unsigned)H_) && ((unsigned)ix < (unsigned)W_);
        const __half* bs;
        if (ok) {
            const long poff = (long)(pixbase + iy * W_ + ix);
            const int c16 = cic * 16;
            if (CSPLIT > 0 && c16 < CSPLIT)
                bs = b0 + poff * in0_cs + c16;
            else
                bs = b1 + poff * in1_cs + (c16 - CSPLIT);
        } else {
            bs = b1;
        }
        const int sz = ok ? 16 : 0;
        const uint32_t bd = sbase + soff + bStsOff;
        cpa16z(bd, bs, sz);
        cpa16z(bd + 16, bs + 8, sz);
    };

    issue(0, 0);            CP_COMMIT();
    issue(1, STAGE);        CP_COMMIT();

    uint32_t cur = 0, nxt = 2 * STAGE;
#pragma unroll 1
    for (int it = 0; it < NITER; ++it) {
        CP_WAIT1();
        __syncthreads();
        if (it + 2 < NITER) issue(it + 2, nxt);
        CP_COMMIT();

        const uint32_t base = sbase + cur;
        uint32_t ah[4][4], al[4][4];
#pragma unroll
        for (int mt = 0; mt < 4; mt++) {
            const uint32_t aa = base + aLdOff + mt * 768;
            ldsm4(ah[mt][0], ah[mt][1], ah[mt][2], ah[mt][3], aa);
            ldsm4(al[mt][0], al[mt][1], al[mt][2], al[mt][3], aa + 6144);
        }
#pragma unroll
        for (int p = 0; p < 2; p++) {
            uint32_t bh[4], bl[4];
            const uint32_t ba = base + bLdOff + p * 768;
            ldsm4(bh[0], bh[1], bh[2], bh[3], ba);
            ldsm4(bl[0], bl[1], bl[2], bl[3], ba + 6144);
#pragma unroll
            for (int f = 0; f < 2; f++) {
                uint32_t bhf[2] = { bh[f], bh[f + 2] };
                uint32_t blf[2] = { bl[f], bl[f + 2] };
                const int nt = p * 2 + f;
#pragma unroll
                for (int mt = 0; mt < 4; mt++) {
                    mma16816(acc[mt][nt], ah[mt], bhf);
                    mma16816(acc[mt][nt], ah[mt], blf);
                    mma16816(acc[mt][nt], al[mt], bhf);
                }
            }
        }
        cur = (cur == 2 * STAGE) ? 0 : cur + STAGE;
        nxt = (nxt == 2 * STAGE) ? 0 : nxt + STAGE;
    }

    // ---- epilogue: bias + act + pack; smem-staged [pixel][ch] ----
    const float* bias = (blockIdx.y == 0) ? bias0 : bias1;
    uint32_t pk[4][4][4];
#pragma unroll
    for (int mt = 0; mt < 4; mt++) {
        const int r0 = warp_m * 64 + mt * 16 + g;
        const float bv0 = __ldg(bias + r0);
        const float bv1 = __ldg(bias + r0 + 8);
#pragma unroll
        for (int nt = 0; nt < 4; nt++) {
            pk[mt][nt][0] = packhl(epi<ACT>(acc[mt][nt][0] + bv0));
            pk[mt][nt][1] = packhl(epi<ACT>(acc[mt][nt][1] + bv0));
            pk[mt][nt][2] = packhl(epi<ACT>(acc[mt][nt][2] + bv1));
            pk[mt][nt][3] = packhl(epi<ACT>(acc[mt][nt][3] + bv1));
        }
    }
    uint32_t* st = reinterpret_cast<uint32_t*>(smem);
    const int pix = tid & 63;
    const int q   = tid >> 6;
#pragma unroll 1
    for (int pass = 0; pass < 2; pass++) {
        __syncthreads();
        if ((warp_n >> 1) == pass) {
#pragma unroll
            for (int mt = 0; mt < 4; mt++) {
                const int r = warp_m * 64 + mt * 16 + g;
#pragma unroll
                for (int nt = 0; nt < 4; nt++) {
                    const int cloc = (warp_n & 1) * 32 + nt * 8 + 2 * tg;
                    st[cloc * 132 + r]           = pk[mt][nt][0];
                    st[(cloc + 1) * 132 + r]     = pk[mt][nt][1];
                    st[cloc * 132 + r + 8]       = pk[mt][nt][2];
                    st[(cloc + 1) * 132 + r + 8] = pk[mt][nt][3];
                }
            }
        }
        __syncthreads();
        const long P = n0 + pass * 64 + pix;
        if (EPI == EPI_STD || (EPI == EPI_Z_RH && blockIdx.y == 0)) {
            const long prow = P * out_cs + out_ch0 + m0 + q * 32;
            __half* oh = g_acthi + out_off + prow;
            __half* ol = g_actlo + out_off + prow;
#pragma unroll
            for (int jp = 0; jp < 4; jp++) {
                uint4 vA = *reinterpret_cast<uint4*>(&st[pix * 132 + q * 32 + jp * 8]);
                uint4 vB = *reinterpret_cast<uint4*>(&st[pix * 132 + q * 32 + jp * 8 + 4]);
                uint4 hv, lv;
                hv.x = __byte_perm(vA.x, vA.y, 0x5410);
                hv.y = __byte_perm(vA.z, vA.w, 0x5410);
                hv.z = __byte_perm(vB.x, vB.y, 0x5410);
                hv.w = __byte_perm(vB.z, vB.w, 0x5410);
                lv.x = __byte_perm(vA.x, vA.y, 0x7632);
                lv.y = __byte_perm(vA.z, vA.w, 0x7632);
                lv.z = __byte_perm(vB.x, vB.y, 0x7632);
                lv.w = __byte_perm(vB.z, vB.w, 0x7632);
                *reinterpret_cast<uint4*>(oh + jp * 8) = hv;
                *reinterpret_cast<uint4*>(ol + jp * 8) = lv;
            }
        } else if (EPI == EPI_Z_RH) {
            // y==1: rh = r * h  -> A_RH (reads h fp32; no race with mainloop)
            const long cbase = P * 128 + q * 32;
#pragma unroll
            for (int jp = 0; jp < 4; jp++) {
                float4 h0 = *reinterpret_cast<float4*>(&g_scratch[OFF_H + cbase + jp * 8]);
                float4 h1 = *reinterpret_cast<float4*>(&g_scratch[OFF_H + cbase + jp * 8 + 4]);
                const float hv[8] = {h0.x, h0.y, h0.z, h0.w, h1.x, h1.y, h1.z, h1.w};
                union { uint4 v; __half h[8]; } oh, ol;
#pragma unroll
                for (int k = 0; k < 8; k++) {
                    const float r = joinu(st[pix * 132 + q * 32 + jp * 8 + k]);
                    split2(r * hv[k], oh.h[k], ol.h[k]);
                }
                *reinterpret_cast<uint4*>(&g_acthi[A_RH + cbase + jp * 8]) = oh.v;
                *reinterpret_cast<uint4*>(&g_actlo[A_RH + cbase + jp * 8]) = ol.v;
            }
        } else if (EPI == EPI_GRU) {
            // hn = (1-z)*h + z*q -> OFF_H (fp32) + A_HT (packed)
            const long cbase = P * 128 + q * 32;
#pragma unroll
            for (int jp = 0; jp < 4; jp++) {
                float4 h0 = *reinterpret_cast<float4*>(&g_scratch[OFF_H + cbase + jp * 8]);
                float4 h1 = *reinterpret_cast<float4*>(&g_scratch[OFF_H + cbase + jp * 8 + 4]);
                const float hv[8] = {h0.x, h0.y, h0.z, h0.w, h1.x, h1.y, h1.z, h1.w};
                union { uint4 v; __half h[8]; } zh, zl, oh, ol;
                zh.v = *reinterpret_cast<const uint4*>(&g_acthi[A_Z + cbase + jp * 8]);
                zl.v = *reinterpret_cast<const uint4*>(&g_actlo[A_Z + cbase + jp * 8]);
                float hn[8];
#pragma unroll
                for (int k = 0; k < 8; k++) {
                    const float qv = joinu(st[pix * 132 + q * 32 + jp * 8 + k]);
                    const float z  = join2(zh.h[k], zl.h[k]);
                    hn[k] = (1.0f - z) * hv[k] + z * qv;
                    split2(hn[k], oh.h[k], ol.h[k]);
                }
                *reinterpret_cast<float4*>(&g_scratch[OFF_H + cbase + jp * 8]) =
                    make_float4(hn[0], hn[1], hn[2], hn[3]);
                *reinterpret_cast<float4*>(&g_scratch[OFF_H + cbase + jp * 8 + 4]) =
                    make_float4(hn[4], hn[5], hn[6], hn[7]);
                *reinterpret_cast<uint4*>(&g_acthi[A_HT + cbase + jp * 8]) = oh.v;
                *reinterpret_cast<uint4*>(&g_actlo[A_HT + cbase + jp * 8]) = ol.v;
            }
        }
    }
}

// ===========================================================================
// Specialized ph2 conv: COUT=16, CIN=128, 3x3. M=16 x N=128 tile.
// ===========================================================================
__global__ __launch_bounds__(256)
void conv_mma16(long in_off, long w_off, const float* __restrict__ bias,
                long out_off)
{
    constexpr int KTOT = 1152, CPC = 8, NITER = 72;
    constexpr int STAGE = 13824;   // Ahi768 | Alo768 | Bhi6144 | Blo6144
    __shared__ __align__(128) char smem[3 * STAGE];
    const uint32_t sbase = smem_u32(smem);

    const int tid  = threadIdx.x;
    const int lane = tid & 31;
    const int wid  = tid >> 5;
    const int g  = lane >> 2;
    const int tg = lane & 3;

    const int n0 = blockIdx.x << 7;
    const int bb = n0 / HW;
    const int pixbase = bb * HW;

    const int arow  = tid & 15;
    const int ahalf = (tid >> 4) & 1;
    const int asel  = tid >> 5;    // valid when tid<64
    const __half* wb =
        ((asel & 1) ? g_wlo : g_whi) + w_off + (long)arow * KTOT + ahalf * 8;

    const int pixl   = tid & 127;
    const int bplane = tid >> 7;
    const int hwp = (n0 - pixbase) + pixl;
    const int py  = hwp / W_;
    const int px  = hwp - py * W_;
    const __half* bsrc0 = (bplane ? g_actlo : g_acthi) + in_off;
    const uint32_t bStsOff = 1536 + bplane * 6144 + pixl * 48;

    const uint32_t aLdOff = (lane & 15) * 48 + (lane >> 4) * 16;
    const uint32_t bLdOff = 1536 + (wid * 16 + (lane & 15)) * 48 + (lane >> 4) * 16;

    float acc[2][4];
#pragma unroll
    for (int nf = 0; nf < 2; nf++)
#pragma unroll
        for (int e = 0; e < 4; e++) acc[nf][e] = 0.0f;

    auto issue = [&](int it, uint32_t soff) {
        if (tid < 64)
            cpa16(sbase + soff + (asel & 1) * 768 + arow * 48 + ahalf * 16,
                  wb + it * 16);
        const int pos = it / CPC;
        const int cic = it - pos * CPC;
        const int ky  = pos / 3;
        const int kx  = pos - ky * 3;
        const int iy  = py + ky - 1;
        const int ix  = px + kx - 1;
        const bool ok = ((unsigned)iy < (unsigned)H_) && ((unsigned)ix < (unsigned)W_);
        const __half* bs = ok
            ? bsrc0 + (long)(pixbase + iy * W_ + ix) * 128 + cic * 16
            : bsrc0;
        const int sz = ok ? 16 : 0;
        const uint32_t bd = sbase + soff + bStsOff;
        cpa16z(bd, bs, sz);
        cpa16z(bd + 16, bs + 8, sz);
    };

    issue(0, 0);       CP_COMMIT();
    issue(1, STAGE);   CP_COMMIT();

    uint32_t cur = 0, nxt = 2 * STAGE;
#pragma unroll 1
    for (int it = 0; it < NITER; ++it) {
        CP_WAIT1();
        __syncthreads();
        if (it + 2 < NITER) issue(it + 2, nxt);
        CP_COMMIT();

        const uint32_t base = sbase + cur;
        uint32_t ah[4], al[4], bh[4], bl[4];
        ldsm4(ah[0], ah[1], ah[2], ah[3], base + aLdOff);
        ldsm4(al[0], al[1], al[2], al[3], base + aLdOff + 768);
        ldsm4(bh[0], bh[1], bh[2], bh[3], base + bLdOff);
        ldsm4(bl[0], bl[1], bl[2], bl[3], base + bLdOff + 6144);
#pragma unroll
        for (int nf = 0; nf < 2; nf++) {
            uint32_t bhf[2] = { bh[nf], bh[nf + 2] };
            uint32_t blf[2] = { bl[nf], bl[nf + 2] };
            mma16816(acc[nf], ah, bhf);
            mma16816(acc[nf], ah, blf);
            mma16816(acc[nf], al, bhf);
        }
        cur = (cur == 2 * STAGE) ? 0 : cur + STAGE;
        nxt = (nxt == 2 * STAGE) ? 0 : nxt + STAGE;
    }

    const float bv0 = __ldg(bias + g);
    const float bv1 = __ldg(bias + g + 8);
#pragma unroll
    for (int nf = 0; nf < 2; nf++) {
        const long p0 = (long)(n0 + wid * 16 + nf * 8 + 2 * tg);
        __half h, l;
        split2(acc[nf][0] + bv0, h, l);
        g_acthi[out_off + p0 * 16 + g] = h;       g_actlo[out_off + p0 * 16 + g] = l;
        split2(acc[nf][1] + bv0, h, l);
        g_acthi[out_off + (p0 + 1) * 16 + g] = h; g_actlo[out_off + (p0 + 1) * 16 + g] = l;
        split2(acc[nf][2] + bv1, h, l);
        g_acthi[out_off + p0 * 16 + g + 8] = h;   g_actlo[out_off + p0 * 16 + g + 8] = l;
        split2(acc[nf][3] + bv1, h, l);
        g_acthi[out_off + (p0 + 1) * 16 + g + 8] = h;
        g_actlo[out_off + (p0 + 1) * 16 + g + 8] = l;
    }
}

// ------------------------- setup / pointwise kernels -----------------------
__global__ void split_w_kernel(const float* __restrict__ w, long off,
                               int rows, int cin, int khw) {
    const int ktot = cin * khw;
    const long n = (long)rows * ktot;
    const long i = (long)blockIdx.x * blockDim.x + threadIdx.x;
    if (i >= n) return;
    const int co  = (int)(i / ktot);
    const int rem = (int)(i - (long)co * ktot);
    const int pos = rem / cin;
    const int ci  = rem - pos * cin;
    const float x = w[(long)co * ktot + (long)ci * khw + pos];
    split2(x, g_whi[off + i], g_wlo[off + i]);
}
__global__ void setup_bins_kernel() {
    const int p = blockIdx.x * blockDim.x + threadIdx.x;
    if (p >= NPIX) return;
    const int b = p / HW, hw = p - b * HW;
    float* ed = g_scratch + OFF_EDGES + (long)b * 17 * HW + hw;
#pragma unroll
    for (int j = 0; j < 17; j++) ed[j * HW] = 5.0f * j;
#pragma unroll
    for (int i = 0; i < 16; i++)
        split2(2.5f + 5.0f * i, g_acthi[A_CD + (long)p * 16 + i],
               g_actlo[A_CD + (long)p * 16 + i]);
}
__global__ void copy_ctx_kernel(const float* __restrict__ ctx) {
    __shared__ float t[192 * 33];
    const int p0 = blockIdx.x * 32;
    const int b = p0 / HW;
    const int hw = p0 - b * HW;
    const float* src = ctx + (long)b * 192 * HW + hw;
    for (int k = threadIdx.x; k < 192 * 32; k += 256) {
        const int c = k >> 5, w = k & 31;
        t[c * 33 + w] = src[(long)c * HW + w];
    }
    __syncthreads();
    for (int k = threadIdx.x; k < 32 * 192; k += 256) {
        const int w = k / 192, c = k - w * 192;
        const long o = A_X + (long)(p0 + w) * 448 + 256 + c;
        split2(t[c * 33 + w], g_acthi[o], g_actlo[o]);
    }
}
__global__ void copy_h_kernel(const float* __restrict__ h0) {
    __shared__ float t[128 * 33];
    const int p0 = blockIdx.x * 32;
    const int b = p0 / HW;
    const int hw = p0 - b * HW;
    const float* src = h0 + (long)b * 128 * HW + hw;
    for (int k = threadIdx.x; k < 128 * 32; k += 256) {
        const int c = k >> 5, w = k & 31;
        t[c * 33 + w] = src[(long)c * HW + w];
    }
    __syncthreads();
    for (int k = threadIdx.x; k < 32 * 128; k += 256) {
        const int w = k >> 7, c = k & 127;
        const float v = t[c * 33 + w];
        g_scratch[OFF_H + (long)(p0 + w) * 128 + c] = v;
        const long o = A_HT + (long)(p0 + w) * 128 + c;
        split2(v, g_acthi[o], g_actlo[o]);
    }
}
__global__ void bins_kernel(float* __restrict__ out, int it) {
    const int p = blockIdx.x * blockDim.x + threadIdx.x;
    if (p >= NPIX) return;
    const int b = p / HW, hw = p - b * HW;
    const long lgo = A_LG + (long)p * 16;
    const long cdo = A_CD + (long)p * 16;
    float* edp = g_scratch + OFF_EDGES + (long)b * 17 * HW + hw;

    float l[16], cd[16];
    float m = -1e30f;
#pragma unroll
    for (int i = 0; i < 16; i++) {
        l[i] = join2(g_acthi[lgo + i], g_actlo[lgo + i]);
        m = fmaxf(m, l[i]);
    }
    float s = 0.0f;
#pragma unroll
    for (int i = 0; i < 16; i++) { l[i] = expf(l[i] - m); s += l[i]; }
    const float inv = 1.0f / s;
    float dr = 0.0f;
#pragma unroll
    for (int i = 0; i < 16; i++) {
        cd[i] = join2(g_acthi[cdo + i], g_actlo[cdo + i]);
        dr += l[i] * cd[i];
    }
    dr *= inv;
    float var = 0.0f;
#pragma unroll
    for (int i = 0; i < 16; i++) { const float d = cd[i] - dr; var += l[i] * d * d; }
    var *= inv;
    const float unc = sqrtf(var);

    out[(0 * 6 + it) * NPIX + p] = dr;
    out[(2 * 6 + it) * NPIX + p] = unc;

    int cnt = 0;
#pragma unroll
    for (int j = 1; j <= 15; j++) cnt += (dr >= edp[j * HW]) ? 1 : 0;
    const int label = (dr >= edp[16 * HW]) ? 0 : cnt;
    out[(1 * 6 + it) * NPIX + p] = cd[label];

    const float start = fmaxf(dr - 0.5f * unc, 0.0f);
    const float delta = unc * (1.0f / 16.0f);
    float cum = start;
    float eprev = fminf(fmaxf(cum, 0.0f), 80.0f);
    edp[0] = eprev;
#pragma unroll
    for (int i = 1; i <= 16; i++) {
        cum += delta;
        const float e = fminf(fmaxf(cum, 0.0f), 80.0f);
        edp[i * HW] = e;
        split2(0.5f * (eprev + e), g_acthi[cdo + i - 1], g_actlo[cdo + i - 1]);
        eprev = e;
    }
}

// ------------------------- launch ------------------------------------------
extern "C" void kernel_launch(void* const* d_in, const int* in_sizes, int n_in,
                              void* d_out, int out_size)
{
    (void)in_sizes; (void)n_in; (void)out_size;
    const float* context = (const float*)d_in[1];
    const float* gruh    = (const float*)d_in[2];
    const float* e1w = (const float*)d_in[3];  const float* e1b = (const float*)d_in[4];
    const float* e2w = (const float*)d_in[5];  const float* e2b = (const float*)d_in[6];
    const float* e3w = (const float*)d_in[7];  const float* e3b = (const float*)d_in[8];
    const float* e4w = (const float*)d_in[9];  const float* e4b = (const float*)d_in[10];
    const float* z1w = (const float*)d_in[11]; const float* z1b = (const float*)d_in[12];
    const float* r1w = (const float*)d_in[13]; const float* r1b = (const float*)d_in[14];
    const float* q1w = (const float*)d_in[15]; const float* q1b = (const float*)d_in[16];
    const float* z2w = (const float*)d_in[17]; const float* z2b = (const float*)d_in[18];
    const float* r2w = (const float*)d_in[19]; const float* r2b = (const float*)d_in[20];
    const float* q2w = (const float*)d_in[21]; const float* q2b = (const float*)d_in[22];
    const float* p1w = (const float*)d_in[23]; const float* p1b = (const float*)d_in[24];
    const float* p2w = (const float*)d_in[25]; const float* p2b = (const float*)d_in[26];
    float* out = (float*)d_out;

    constexpr int SMEM_DYN = 73728;   // 3 x 24576B stages
    auto fe1  = conv_mma<0, 16, 128, 7, 7, 3, 3, ACT_RELU, EPI_STD>;
    auto fc33 = conv_mma<0, 128, 128, 3, 3, 1, 1, ACT_RELU, EPI_STD>;
    auto fe4  = conv_mma<0, 128, 256, 3, 3, 1, 1, ACT_RELU, EPI_STD>;
    auto fzr1 = conv_mma<128, 576, 256, 1, 5, 0, 2, ACT_SIG, EPI_Z_RH>;
    auto fq1  = conv_mma<128, 576, 128, 1, 5, 0, 2, ACT_TANH, EPI_GRU>;
    auto fzr2 = conv_mma<128, 576, 256, 5, 1, 2, 0, ACT_SIG, EPI_Z_RH>;
    auto fq2  = conv_mma<128, 576, 128, 5, 1, 2, 0, ACT_TANH, EPI_GRU>;
    cudaFuncSetAttribute(fe1,  cudaFuncAttributeMaxDynamicSharedMemorySize, SMEM_DYN);
    cudaFuncSetAttribute(fc33, cudaFuncAttributeMaxDynamicSharedMemorySize, SMEM_DYN);
    cudaFuncSetAttribute(fe4,  cudaFuncAttributeMaxDynamicSharedMemorySize, SMEM_DYN);
    cudaFuncSetAttribute(fzr1, cudaFuncAttributeMaxDynamicSharedMemorySize, SMEM_DYN);
    cudaFuncSetAttribute(fq1,  cudaFuncAttributeMaxDynamicSharedMemorySize, SMEM_DYN);
    cudaFuncSetAttribute(fzr2, cudaFuncAttributeMaxDynamicSharedMemorySize, SMEM_DYN);
    cudaFuncSetAttribute(fq2,  cudaFuncAttributeMaxDynamicSharedMemorySize, SMEM_DYN);

    const dim3 blk(256);
    const int NT = NPIX / 128;
    const int TB = NPIX / 32;

    setup_bins_kernel<<<(NPIX + 255) / 256, 256>>>();
    copy_ctx_kernel<<<TB, 256>>>(context);
    copy_h_kernel<<<TB, 256>>>(gruh);

    auto SW = [&](const float* w, long off, int rows, int cin, int khw) {
        const long n = (long)rows * cin * khw;
        split_w_kernel<<<(int)((n + 255) / 256), 256>>>(w, off, rows, cin, khw);
    };
    SW(e1w, W_E1, 128, 16, 49);
    SW(e2w, W_E2, 128, 128, 9);
    SW(e3w, W_E3, 128, 128, 9);
    SW(e4w, W_E4, 256, 128, 9);
    SW(z1w, W_ZR1,           128, 576, 5);
    SW(r1w, W_ZR1 + 368640,  128, 576, 5);
    SW(q1w, W_Q1, 128, 576, 5);
    SW(z2w, W_ZR2,           128, 576, 5);
    SW(r2w, W_ZR2 + 368640,  128, 576, 5);
    SW(q2w, W_Q2, 128, 576, 5);
    SW(p1w, W_P1, 128, 128, 9);
    SW(p2w, W_P2, 16, 128, 9);          // unpadded 16 rows

    for (int it = 0; it < 6; ++it) {
        // encoder (encd4 writes d into A_X channels 0..255)
        fe1 <<<dim3(NT, 1), blk, SMEM_DYN>>>(A_CD, 16, A_CD, 16, W_E1, e1b, e1b, A_E1, 128, 0);
        fc33<<<dim3(NT, 1), blk, SMEM_DYN>>>(A_E1, 128, A_E1, 128, W_E2, e2b, e2b, A_E2, 128, 0);
        fc33<<<dim3(NT, 1), blk, SMEM_DYN>>>(A_E2, 128, A_E2, 128, W_E3, e3b, e3b, A_E1, 128, 0);
        fe4 <<<dim3(NT, 2), blk, SMEM_DYN>>>(A_E1, 128, A_E1, 128, W_E4, e4b, e4b + 128, A_X, 448, 0);

        // GRU horizontal: z|r conv (y1 fuses rh), then q conv (fuses update)
        fzr1<<<dim3(NT, 2), blk, SMEM_DYN>>>(A_HT, 128, A_X, 448, W_ZR1, z1b, r1b, A_Z, 128, 0);
        fq1 <<<dim3(NT, 1), blk, SMEM_DYN>>>(A_RH, 128, A_X, 448, W_Q1, q1b, q1b, A_HT, 128, 0);

        // GRU vertical
        fzr2<<<dim3(NT, 2), blk, SMEM_DYN>>>(A_HT, 128, A_X, 448, W_ZR2, z2b, r2b, A_Z, 128, 0);
        fq2 <<<dim3(NT, 1), blk, SMEM_DYN>>>(A_RH, 128, A_X, 448, W_Q2, q2b, q2b, A_HT, 128, 0);

        // PHead
        fc33<<<dim3(NT, 1), blk, SMEM_DYN>>>(A_HT, 128, A_HT, 128, W_P1, p1b, p1b, A_E1, 128, 0);
        conv_mma16<<<NT, blk>>>(A_E1, W_P2, p2b, A_LG);

        bins_kernel<<<(NPIX + 127) / 128, 128>>>(out, it);
    }
}